// round 1
// baseline (speedup 1.0000x reference)
#include <cuda_runtime.h>
#include <cfloat>
#include <math.h>

#define BB 4
#define NN 8192
#define CC 64
#define KK 16
#define HH 64
#define NPTS (BB*NN)

// ---------------- device scratch (allocation-free rule: static globals) ----------
__device__ float4 g_P4[NPTS];                    // (x,y,z,|p|^2)
__device__ float  g_PT[(size_t)NPTS*192];        // per point: [hc+b1 (64) | hn (64) | vn+bv (64)]
__device__ int    g_NB[NPTS*KK];                 // knn indices
__device__ float  g_stats[256];                  // [sum_h(64) | sumsq_h(64) | sum_v(64) | sumsq_v(64)]
__device__ float  g_coef1[256];                  // [a1 | d1 | av | dv]
__device__ float  g_ostats[128];                 // [sum_o | sumsq_o]
__device__ float  g_ocoef[128];                  // [ao | do]
__device__ float  g_Opre[(size_t)NPTS*64];       // pre-BN output conv

// ---------------- k_zero: reset stat accumulators every launch -------------------
__global__ void k_zero() {
    int t = threadIdx.x;
    g_stats[t] = 0.f;
    if (t < 128) g_ostats[t] = 0.f;
}

// ---------------- k0: pack xyz into float4 with |p|^2 ---------------------------
__global__ void k0(const float* __restrict__ xyz) {
    int p = blockIdx.x * blockDim.x + threadIdx.x;
    if (p >= NPTS) return;
    int b = p >> 13, n = p & (NN - 1);
    const float* base = xyz + (size_t)b * 3 * NN + n;
    float x = base[0], y = base[NN], z = base[2 * NN];
    g_P4[p] = make_float4(x, y, z, x * x + y * y + z * z);
}

// ---------------- k1: brute-force KNN (top-16 smallest dist) --------------------
#define TS 1024
__global__ void k1() {
    __shared__ float4 sP[TS];
    int b  = blockIdx.x >> 5;                 // 32 blocks per batch
    int n  = ((blockIdx.x & 31) << 8) + threadIdx.x;
    int p  = b * NN + n;
    float4 q = g_P4[p];
    float m2x = -2.f * q.x, m2y = -2.f * q.y, m2z = -2.f * q.z;

    float bd[KK]; int bi[KK];
#pragma unroll
    for (int s = 0; s < KK; s++) { bd[s] = FLT_MAX; bi[s] = 0; }
    float worst = FLT_MAX; int wslot = 0;

    for (int t0 = 0; t0 < NN; t0 += TS) {
        __syncthreads();
        const float4* src = g_P4 + b * NN + t0;
#pragma unroll
        for (int i = 0; i < TS / 256; i++)
            sP[threadIdx.x + i * 256] = src[threadIdx.x + i * 256];
        __syncthreads();
#pragma unroll 8
        for (int j = 0; j < TS; j++) {
            float4 pc = sP[j];
            float t = fmaf(pc.x, m2x, pc.w);
            t = fmaf(pc.y, m2y, t);
            t = fmaf(pc.z, m2z, t);
            if (t < worst) {
                int cand = t0 + j;
#pragma unroll
                for (int s = 0; s < KK; s++) if (s == wslot) { bd[s] = t; bi[s] = cand; }
                worst = -FLT_MAX;
#pragma unroll
                for (int s = 0; s < KK; s++) if (bd[s] > worst) { worst = bd[s]; wslot = s; }
            }
        }
    }
#pragma unroll
    for (int s = 0; s < KK; s++) g_NB[p * KK + s] = bi[s];
}

// ---------------- k2: per-point transforms  PT = [W1c|W1n|Wvn] @ feats ----------
// block: 256 threads, 32 points, 192 outputs in 2 halves of 96
__global__ void k2(const float* __restrict__ feats,
                   const float* __restrict__ W1, const float* __restrict__ b1,
                   const float* __restrict__ Wv, const float* __restrict__ bv) {
    __shared__ float sW[64][96];   // sW[c][o_local]
    __shared__ float sF[64][32];   // sF[c][n_local]
    int tid = threadIdx.x;
    int blk = blockIdx.x;
    int b   = blk >> 8;            // 256 blocks per batch
    int n0  = (blk & 255) << 5;

    for (int e = tid; e < 64 * 32; e += 256) {
        int c = e >> 5, nn = e & 31;
        sF[c][nn] = feats[(size_t)b * CC * NN + (size_t)c * NN + n0 + nn];
    }

    int ox = tid & 31, nx = tid >> 5;   // nx in 0..7

    for (int half = 0; half < 2; half++) {
        __syncthreads();
        for (int e = tid; e < 96 * 64; e += 256) {
            int ol = e % 96, c = e / 96;
            int o = ol + half * 96;
            float w;
            if (o < 64)       w = W1[o * 131 + c];
            else if (o < 128) w = W1[(o - 64) * 131 + 64 + c];
            else              w = Wv[(o - 128) * 67 + c];
            sW[c][ol] = w;
        }
        __syncthreads();

        float acc[3][4];
#pragma unroll
        for (int i = 0; i < 3; i++)
#pragma unroll
            for (int j = 0; j < 4; j++) acc[i][j] = 0.f;

        for (int c = 0; c < 64; c++) {
            float a[3], f[4];
#pragma unroll
            for (int i = 0; i < 3; i++) a[i] = sW[c][ox + 32 * i];
#pragma unroll
            for (int j = 0; j < 4; j++) f[j] = sF[c][nx + 8 * j];
#pragma unroll
            for (int i = 0; i < 3; i++)
#pragma unroll
                for (int j = 0; j < 4; j++) acc[i][j] = fmaf(a[i], f[j], acc[i][j]);
        }

#pragma unroll
        for (int i = 0; i < 3; i++) {
            int o = half * 96 + ox + 32 * i;
            float bias = (o < 64) ? b1[o] : ((o >= 128) ? bv[o - 128] : 0.f);
#pragma unroll
            for (int j = 0; j < 4; j++) {
                int nn = nx + 8 * j;
                g_PT[(size_t)(b * NN + n0 + nn) * 192 + o] = acc[i][j] + bias;
            }
        }
    }
}

// ---------------- k3: BN stats for h and v (recompute path, no activations stored)
__global__ void k3(const float* __restrict__ W1, const float* __restrict__ Wv) {
    __shared__ float sstat[256];
    int tid = threadIdx.x, lane = tid & 31, wid = tid >> 5;
    for (int e = tid; e < 256; e += 256) sstat[e] = 0.f;
    __syncthreads();

    int c1 = lane, c2 = lane + 32;
    float w1x0a = W1[c1 * 131 + 128], w1x1a = W1[c1 * 131 + 129], w1x2a = W1[c1 * 131 + 130];
    float w1x0b = W1[c2 * 131 + 128], w1x1b = W1[c2 * 131 + 129], w1x2b = W1[c2 * 131 + 130];
    float wvx0a = Wv[c1 * 67 + 64],  wvx1a = Wv[c1 * 67 + 65],  wvx2a = Wv[c1 * 67 + 66];
    float wvx0b = Wv[c2 * 67 + 64],  wvx1b = Wv[c2 * 67 + 65],  wvx2b = Wv[c2 * 67 + 66];

    float s0=0,s1=0,s2=0,s3=0,s4=0,s5=0,s6=0,s7=0;
    int gw = blockIdx.x * 8 + wid, nw = gridDim.x * 8;
    for (int p = gw; p < NPTS; p += nw) {
        int b = p >> 13;
        float4 q = g_P4[p];
        const float* ptp = g_PT + (size_t)p * 192;
        float hc1 = ptp[c1], hc2 = ptp[c2];
#pragma unroll 4
        for (int k = 0; k < KK; k++) {
            int m = g_NB[p * KK + k];
            float4 pm = g_P4[b * NN + m];
            float rx = pm.x - q.x, ry = pm.y - q.y, rz = pm.z - q.z;
            const float* ptm = g_PT + (size_t)(b * NN + m) * 192;
            float h1 = hc1 + ptm[64 + c1] + rx * w1x0a + ry * w1x1a + rz * w1x2a;
            float h2 = hc2 + ptm[64 + c2] + rx * w1x0b + ry * w1x1b + rz * w1x2b;
            float v1 = ptm[128 + c1] + rx * wvx0a + ry * wvx1a + rz * wvx2a;
            float v2 = ptm[128 + c2] + rx * wvx0b + ry * wvx1b + rz * wvx2b;
            s0 += h1; s1 += h1 * h1; s2 += h2; s3 += h2 * h2;
            s4 += v1; s5 += v1 * v1; s6 += v2; s7 += v2 * v2;
        }
    }
    atomicAdd(&sstat[c1], s0);        atomicAdd(&sstat[64 + c1], s1);
    atomicAdd(&sstat[c2], s2);        atomicAdd(&sstat[64 + c2], s3);
    atomicAdd(&sstat[128 + c1], s4);  atomicAdd(&sstat[192 + c1], s5);
    atomicAdd(&sstat[128 + c2], s6);  atomicAdd(&sstat[192 + c2], s7);
    __syncthreads();
    for (int e = tid; e < 256; e += 256) atomicAdd(&g_stats[e], sstat[e]);
}

// ---------------- k4: stats -> BN coefficients for h, v -------------------------
__global__ void k4(const float* __restrict__ g1, const float* __restrict__ be1,
                   const float* __restrict__ gv, const float* __restrict__ bev) {
    int c = threadIdx.x;
    float cnt = (float)((size_t)NPTS * KK);
    float mh = g_stats[c] / cnt;
    float vh = g_stats[64 + c] / cnt - mh * mh;
    float a1 = g1[c] * rsqrtf(vh + 1e-5f);
    g_coef1[c] = a1; g_coef1[64 + c] = be1[c] - a1 * mh;
    float mv = g_stats[128 + c] / cnt;
    float vv = g_stats[192 + c] / cnt - mv * mv;
    float av = gv[c] * rsqrtf(vv + 1e-5f);
    g_coef1[128 + c] = av; g_coef1[192 + c] = bev[c] - av * mv;
}

// ---------------- k5: attention + value + weighted sum + out-conv (pre-BN) ------
__global__ void k5(const float* __restrict__ W1, const float* __restrict__ Wv,
                   const float* __restrict__ W2, const float* __restrict__ b2,
                   const float* __restrict__ Wo, const float* __restrict__ bo) {
    __shared__ float sWo[64][65];   // sWo[j][c] = Wo[c][j]
    __shared__ float sOut[8][64];
    __shared__ float sstat[128];
    int tid = threadIdx.x, lane = tid & 31, wid = tid >> 5;

    for (int e = tid; e < 64 * 64; e += 256) {
        int j = e >> 6, c = e & 63;
        sWo[j][c] = Wo[c * 64 + j];
    }
    for (int e = tid; e < 128; e += 256) sstat[e] = 0.f;

    int c1 = lane, c2 = lane + 32;
    float w1x0a = W1[c1 * 131 + 128], w1x1a = W1[c1 * 131 + 129], w1x2a = W1[c1 * 131 + 130];
    float w1x0b = W1[c2 * 131 + 128], w1x1b = W1[c2 * 131 + 129], w1x2b = W1[c2 * 131 + 130];
    float wvx0a = Wv[c1 * 67 + 64],  wvx1a = Wv[c1 * 67 + 65],  wvx2a = Wv[c1 * 67 + 66];
    float wvx0b = Wv[c2 * 67 + 64],  wvx1b = Wv[c2 * 67 + 65],  wvx2b = Wv[c2 * 67 + 66];
    float a1a = g_coef1[c1],      a1b = g_coef1[c2];
    float d1a = g_coef1[64 + c1], d1b = g_coef1[64 + c2];
    float ava = g_coef1[128 + c1], avb = g_coef1[128 + c2];
    float dva = g_coef1[192 + c1], dvb = g_coef1[192 + c2];
    float w2a = W2[c1], w2b = W2[c2];
    float b2v = b2[0];
    float boa = bo[c1], bob = bo[c2];
    __syncthreads();

    float so1 = 0.f, so1q = 0.f, so2 = 0.f, so2q = 0.f;
    int gw = blockIdx.x * 8 + wid, nw = gridDim.x * 8;

    for (int p = gw; p < NPTS; p += nw) {
        int b = p >> 13;
        float4 q = g_P4[p];
        const float* ptp = g_PT + (size_t)p * 192;
        float hc1 = ptp[c1], hc2 = ptp[c2];

        float logits[KK], vv1[KK], vv2[KK];
#pragma unroll
        for (int k = 0; k < KK; k++) {
            int m = g_NB[p * KK + k];
            float4 pm = g_P4[b * NN + m];
            float rx = pm.x - q.x, ry = pm.y - q.y, rz = pm.z - q.z;
            const float* ptm = g_PT + (size_t)(b * NN + m) * 192;
            float h1 = hc1 + ptm[64 + c1] + rx * w1x0a + ry * w1x1a + rz * w1x2a;
            float h2 = hc2 + ptm[64 + c2] + rx * w1x0b + ry * w1x1b + rz * w1x2b;
            float v1 = ptm[128 + c1] + rx * wvx0a + ry * wvx1a + rz * wvx2a;
            float v2 = ptm[128 + c2] + rx * wvx0b + ry * wvx1b + rz * wvx2b;
            float hb1 = fmaxf(a1a * h1 + d1a, 0.f);
            float hb2 = fmaxf(a1b * h2 + d1b, 0.f);
            vv1[k] = fmaxf(ava * v1 + dva, 0.f);
            vv2[k] = fmaxf(avb * v2 + dvb, 0.f);
            float t = hb1 * w2a + hb2 * w2b;
#pragma unroll
            for (int off = 16; off > 0; off >>= 1) t += __shfl_xor_sync(0xffffffffu, t, off);
            logits[k] = t + b2v;
        }
        // softmax over K
        float mx = logits[0];
#pragma unroll
        for (int k = 1; k < KK; k++) mx = fmaxf(mx, logits[k]);
        float ex[KK], se = 0.f;
#pragma unroll
        for (int k = 0; k < KK; k++) { ex[k] = expf(logits[k] - mx); se += ex[k]; }
        float out1 = 0.f, out2 = 0.f;
#pragma unroll
        for (int k = 0; k < KK; k++) {
            float w = ex[k] / se;
            out1 += w * vv1[k];
            out2 += w * vv2[k];
        }
        __syncwarp();
        sOut[wid][c1] = out1; sOut[wid][c2] = out2;
        __syncwarp();
        float oo1 = boa, oo2 = bob;
#pragma unroll 8
        for (int j = 0; j < 64; j++) {
            float oj = sOut[wid][j];
            oo1 = fmaf(sWo[j][c1], oj, oo1);
            oo2 = fmaf(sWo[j][c2], oj, oo2);
        }
        g_Opre[(size_t)p * 64 + c1] = oo1;
        g_Opre[(size_t)p * 64 + c2] = oo2;
        so1 += oo1; so1q += oo1 * oo1;
        so2 += oo2; so2q += oo2 * oo2;
    }
    atomicAdd(&sstat[c1], so1); atomicAdd(&sstat[64 + c1], so1q);
    atomicAdd(&sstat[c2], so2); atomicAdd(&sstat[64 + c2], so2q);
    __syncthreads();
    for (int e = tid; e < 128; e += 256) atomicAdd(&g_ostats[e], sstat[e]);
}

// ---------------- k6: stats -> BN coefficients for o ----------------------------
__global__ void k6(const float* __restrict__ go, const float* __restrict__ beo) {
    int c = threadIdx.x;
    float cnt = (float)NPTS;
    float m = g_ostats[c] / cnt;
    float v = g_ostats[64 + c] / cnt - m * m;
    float a = go[c] * rsqrtf(v + 1e-5f);
    g_ocoef[c] = a; g_ocoef[64 + c] = beo[c] - a * m;
}

// ---------------- k7: BN + relu + residual + transpose to [B,C,N] ---------------
__global__ void k7(const float* __restrict__ feats, float* __restrict__ out) {
    __shared__ float tile[32][65];
    int blk = blockIdx.x;
    int b = blk >> 8;
    int n0 = (blk & 255) << 5;
    int tid = threadIdx.x;
    for (int e = tid; e < 32 * 64; e += 256) {
        int pp = e >> 6, c = e & 63;
        tile[pp][c] = g_Opre[(size_t)(b * NN + n0 + pp) * 64 + c];
    }
    __syncthreads();
    for (int e = tid; e < 64 * 32; e += 256) {
        int c = e >> 5, j = e & 31;
        float val = g_ocoef[c] * tile[j][c] + g_ocoef[64 + c];
        val = fmaxf(val, 0.f) + feats[(size_t)b * CC * NN + (size_t)c * NN + n0 + j];
        out[(size_t)b * CC * NN + (size_t)c * NN + n0 + j] = val;
    }
}

// ---------------- launch ---------------------------------------------------------
extern "C" void kernel_launch(void* const* d_in, const int* in_sizes, int n_in,
                              void* d_out, int out_size) {
    const float* xyz   = (const float*)d_in[0];
    const float* feats = (const float*)d_in[1];
    const float* W1    = (const float*)d_in[2];
    const float* b1    = (const float*)d_in[3];
    const float* g1    = (const float*)d_in[4];
    const float* be1   = (const float*)d_in[5];
    const float* W2    = (const float*)d_in[6];
    const float* b2    = (const float*)d_in[7];
    const float* Wv    = (const float*)d_in[8];
    const float* bv    = (const float*)d_in[9];
    const float* gv    = (const float*)d_in[10];
    const float* bev   = (const float*)d_in[11];
    const float* Wo    = (const float*)d_in[12];
    const float* bo    = (const float*)d_in[13];
    const float* go    = (const float*)d_in[14];
    const float* beo   = (const float*)d_in[15];
    float* out = (float*)d_out;

    k_zero<<<1, 256>>>();
    k0<<<NPTS / 256, 256>>>(xyz);
    k1<<<NPTS / 256, 256>>>();
    k2<<<NPTS / 32, 256>>>(feats, W1, b1, Wv, bv);
    k3<<<1184, 256>>>(W1, Wv);
    k4<<<1, 64>>>(g1, be1, gv, bev);
    k5<<<1184, 256>>>(W1, Wv, W2, b2, Wo, bo);
    k6<<<1, 64>>>(go, beo);
    k7<<<NPTS / 32, 256>>>(feats, out);
}

// round 2
// speedup vs baseline: 1.6346x; 1.6346x over previous
#include <cuda_runtime.h>
#include <cfloat>
#include <math.h>

#define BB 4
#define NN 8192
#define CC 64
#define KK 16
#define HH 64
#define NPTS (BB*NN)

// ---------------- device scratch (allocation-free rule: static globals) ----------
__device__ float4 g_P4[NPTS];                    // (x,y,z,|p|^2)
__device__ float  g_PT[(size_t)NPTS*192];        // per point: [hc+b1 (64) | hn (64) | vn+bv (64)]
__device__ int    g_NB[NPTS*KK];                 // knn indices
__device__ float  g_stats[256];                  // [sum_h(64) | sumsq_h(64) | sum_v(64) | sumsq_v(64)]
__device__ float  g_coef1[256];                  // [a1 | d1 | av | dv]
__device__ float  g_ostats[128];                 // [sum_o | sumsq_o]
__device__ float  g_ocoef[128];                  // [ao | do]
__device__ float  g_Opre[(size_t)NPTS*64];       // pre-BN output conv

// ---------------- k_zero: reset stat accumulators every launch -------------------
__global__ void k_zero() {
    int t = threadIdx.x;
    g_stats[t] = 0.f;
    if (t < 128) g_ostats[t] = 0.f;
}

// ---------------- k0: pack xyz into float4 with |p|^2 ---------------------------
__global__ void k0(const float* __restrict__ xyz) {
    int p = blockIdx.x * blockDim.x + threadIdx.x;
    if (p >= NPTS) return;
    int b = p >> 13, n = p & (NN - 1);
    const float* base = xyz + (size_t)b * 3 * NN + n;
    float x = base[0], y = base[NN], z = base[2 * NN];
    g_P4[p] = make_float4(x, y, z, x * x + y * y + z * z);
}

// ---------------- k1: brute-force KNN (top-16 smallest dist) --------------------
#define TS 1024
__global__ void k1() {
    __shared__ float4 sP[TS];
    int b  = blockIdx.x >> 5;                 // 32 blocks per batch
    int n  = ((blockIdx.x & 31) << 8) + threadIdx.x;
    int p  = b * NN + n;
    float4 q = g_P4[p];
    float m2x = -2.f * q.x, m2y = -2.f * q.y, m2z = -2.f * q.z;

    float bd[KK]; int bi[KK];
#pragma unroll
    for (int s = 0; s < KK; s++) { bd[s] = FLT_MAX; bi[s] = 0; }
    float worst = FLT_MAX; int wslot = 0;

    for (int t0 = 0; t0 < NN; t0 += TS) {
        __syncthreads();
        const float4* src = g_P4 + b * NN + t0;
#pragma unroll
        for (int i = 0; i < TS / 256; i++)
            sP[threadIdx.x + i * 256] = src[threadIdx.x + i * 256];
        __syncthreads();
#pragma unroll 8
        for (int j = 0; j < TS; j++) {
            float4 pc = sP[j];
            float t = fmaf(pc.x, m2x, pc.w);
            t = fmaf(pc.y, m2y, t);
            t = fmaf(pc.z, m2z, t);
            if (t < worst) {
                int cand = t0 + j;
#pragma unroll
                for (int s = 0; s < KK; s++) if (s == wslot) { bd[s] = t; bi[s] = cand; }
                worst = -FLT_MAX;
#pragma unroll
                for (int s = 0; s < KK; s++) if (bd[s] > worst) { worst = bd[s]; wslot = s; }
            }
        }
    }
#pragma unroll
    for (int s = 0; s < KK; s++) g_NB[p * KK + s] = bi[s];
}

// ---------------- k2: per-point transforms  PT = [W1c|W1n|Wvn] @ feats ----------
// block: 256 threads, 32 points, 192 outputs in 2 halves of 96
__global__ void k2(const float* __restrict__ feats,
                   const float* __restrict__ W1, const float* __restrict__ b1,
                   const float* __restrict__ Wv, const float* __restrict__ bv) {
    __shared__ float sW[64][96];   // sW[c][o_local]
    __shared__ float sF[64][32];   // sF[c][n_local]
    int tid = threadIdx.x;
    int blk = blockIdx.x;
    int b   = blk >> 8;            // 256 blocks per batch
    int n0  = (blk & 255) << 5;

    for (int e = tid; e < 64 * 32; e += 256) {
        int c = e >> 5, nn = e & 31;
        sF[c][nn] = feats[(size_t)b * CC * NN + (size_t)c * NN + n0 + nn];
    }

    int ox = tid & 31, nx = tid >> 5;   // nx in 0..7

    for (int half = 0; half < 2; half++) {
        __syncthreads();
        for (int e = tid; e < 96 * 64; e += 256) {
            int ol = e % 96, c = e / 96;
            int o = ol + half * 96;
            float w;
            if (o < 64)       w = W1[o * 131 + c];
            else if (o < 128) w = W1[(o - 64) * 131 + 64 + c];
            else              w = Wv[(o - 128) * 67 + c];
            sW[c][ol] = w;
        }
        __syncthreads();

        float acc[3][4];
#pragma unroll
        for (int i = 0; i < 3; i++)
#pragma unroll
            for (int j = 0; j < 4; j++) acc[i][j] = 0.f;

        for (int c = 0; c < 64; c++) {
            float a[3], f[4];
#pragma unroll
            for (int i = 0; i < 3; i++) a[i] = sW[c][ox + 32 * i];
#pragma unroll
            for (int j = 0; j < 4; j++) f[j] = sF[c][nx + 8 * j];
#pragma unroll
            for (int i = 0; i < 3; i++)
#pragma unroll
                for (int j = 0; j < 4; j++) acc[i][j] = fmaf(a[i], f[j], acc[i][j]);
        }

#pragma unroll
        for (int i = 0; i < 3; i++) {
            int o = half * 96 + ox + 32 * i;
            float bias = (o < 64) ? b1[o] : ((o >= 128) ? bv[o - 128] : 0.f);
#pragma unroll
            for (int j = 0; j < 4; j++) {
                int nn = nx + 8 * j;
                g_PT[(size_t)(b * NN + n0 + nn) * 192 + o] = acc[i][j] + bias;
            }
        }
    }
}

// ---------------- k3: BN stats for h and v (recompute path, no activations stored)
__global__ void k3(const float* __restrict__ W1, const float* __restrict__ Wv) {
    __shared__ float sstat[256];
    int tid = threadIdx.x, lane = tid & 31, wid = tid >> 5;
    for (int e = tid; e < 256; e += 256) sstat[e] = 0.f;
    __syncthreads();

    int c1 = lane, c2 = lane + 32;
    float w1x0a = W1[c1 * 131 + 128], w1x1a = W1[c1 * 131 + 129], w1x2a = W1[c1 * 131 + 130];
    float w1x0b = W1[c2 * 131 + 128], w1x1b = W1[c2 * 131 + 129], w1x2b = W1[c2 * 131 + 130];
    float wvx0a = Wv[c1 * 67 + 64],  wvx1a = Wv[c1 * 67 + 65],  wvx2a = Wv[c1 * 67 + 66];
    float wvx0b = Wv[c2 * 67 + 64],  wvx1b = Wv[c2 * 67 + 65],  wvx2b = Wv[c2 * 67 + 66];

    float s0=0,s1=0,s2=0,s3=0,s4=0,s5=0,s6=0,s7=0;
    int gw = blockIdx.x * 8 + wid, nw = gridDim.x * 8;
    for (int p = gw; p < NPTS; p += nw) {
        int b = p >> 13;
        float4 q = g_P4[p];
        const float* ptp = g_PT + (size_t)p * 192;
        float hc1 = ptp[c1], hc2 = ptp[c2];
#pragma unroll 4
        for (int k = 0; k < KK; k++) {
            int m = g_NB[p * KK + k];
            float4 pm = g_P4[b * NN + m];
            float rx = pm.x - q.x, ry = pm.y - q.y, rz = pm.z - q.z;
            const float* ptm = g_PT + (size_t)(b * NN + m) * 192;
            float h1 = hc1 + ptm[64 + c1] + rx * w1x0a + ry * w1x1a + rz * w1x2a;
            float h2 = hc2 + ptm[64 + c2] + rx * w1x0b + ry * w1x1b + rz * w1x2b;
            float v1 = ptm[128 + c1] + rx * wvx0a + ry * wvx1a + rz * wvx2a;
            float v2 = ptm[128 + c2] + rx * wvx0b + ry * wvx1b + rz * wvx2b;
            s0 += h1; s1 += h1 * h1; s2 += h2; s3 += h2 * h2;
            s4 += v1; s5 += v1 * v1; s6 += v2; s7 += v2 * v2;
        }
    }
    atomicAdd(&sstat[c1], s0);        atomicAdd(&sstat[64 + c1], s1);
    atomicAdd(&sstat[c2], s2);        atomicAdd(&sstat[64 + c2], s3);
    atomicAdd(&sstat[128 + c1], s4);  atomicAdd(&sstat[192 + c1], s5);
    atomicAdd(&sstat[128 + c2], s6);  atomicAdd(&sstat[192 + c2], s7);
    __syncthreads();
    for (int e = tid; e < 256; e += 256) atomicAdd(&g_stats[e], sstat[e]);
}

// ---------------- k4: stats -> BN coefficients for h, v -------------------------
__global__ void k4(const float* __restrict__ g1, const float* __restrict__ be1,
                   const float* __restrict__ gv, const float* __restrict__ bev) {
    int c = threadIdx.x;
    float cnt = (float)((size_t)NPTS * KK);
    float mh = g_stats[c] / cnt;
    float vh = g_stats[64 + c] / cnt - mh * mh;
    float a1 = g1[c] * rsqrtf(vh + 1e-5f);
    g_coef1[c] = a1; g_coef1[64 + c] = be1[c] - a1 * mh;
    float mv = g_stats[128 + c] / cnt;
    float vv = g_stats[192 + c] / cnt - mv * mv;
    float av = gv[c] * rsqrtf(vv + 1e-5f);
    g_coef1[128 + c] = av; g_coef1[192 + c] = bev[c] - av * mv;
}

// ---------------- k5: attention + value + weighted sum + out-conv (pre-BN) ------
__global__ void k5(const float* __restrict__ W1, const float* __restrict__ Wv,
                   const float* __restrict__ W2, const float* __restrict__ b2,
                   const float* __restrict__ Wo, const float* __restrict__ bo) {
    __shared__ float sWo[64][65];   // sWo[j][c] = Wo[c][j]
    __shared__ float sOut[8][64];
    __shared__ float sstat[128];
    int tid = threadIdx.x, lane = tid & 31, wid = tid >> 5;

    for (int e = tid; e < 64 * 64; e += 256) {
        int j = e >> 6, c = e & 63;
        sWo[j][c] = Wo[c * 64 + j];
    }
    for (int e = tid; e < 128; e += 256) sstat[e] = 0.f;

    int c1 = lane, c2 = lane + 32;
    float w1x0a = W1[c1 * 131 + 128], w1x1a = W1[c1 * 131 + 129], w1x2a = W1[c1 * 131 + 130];
    float w1x0b = W1[c2 * 131 + 128], w1x1b = W1[c2 * 131 + 129], w1x2b = W1[c2 * 131 + 130];
    float wvx0a = Wv[c1 * 67 + 64],  wvx1a = Wv[c1 * 67 + 65],  wvx2a = Wv[c1 * 67 + 66];
    float wvx0b = Wv[c2 * 67 + 64],  wvx1b = Wv[c2 * 67 + 65],  wvx2b = Wv[c2 * 67 + 66];
    float a1a = g_coef1[c1],      a1b = g_coef1[c2];
    float d1a = g_coef1[64 + c1], d1b = g_coef1[64 + c2];
    float ava = g_coef1[128 + c1], avb = g_coef1[128 + c2];
    float dva = g_coef1[192 + c1], dvb = g_coef1[192 + c2];
    float w2a = W2[c1], w2b = W2[c2];
    float b2v = b2[0];
    float boa = bo[c1], bob = bo[c2];
    __syncthreads();

    float so1 = 0.f, so1q = 0.f, so2 = 0.f, so2q = 0.f;
    int gw = blockIdx.x * 8 + wid, nw = gridDim.x * 8;

    for (int p = gw; p < NPTS; p += nw) {
        int b = p >> 13;
        float4 q = g_P4[p];
        const float* ptp = g_PT + (size_t)p * 192;
        float hc1 = ptp[c1], hc2 = ptp[c2];

        float logits[KK], vv1[KK], vv2[KK];
#pragma unroll
        for (int k = 0; k < KK; k++) {
            int m = g_NB[p * KK + k];
            float4 pm = g_P4[b * NN + m];
            float rx = pm.x - q.x, ry = pm.y - q.y, rz = pm.z - q.z;
            const float* ptm = g_PT + (size_t)(b * NN + m) * 192;
            float h1 = hc1 + ptm[64 + c1] + rx * w1x0a + ry * w1x1a + rz * w1x2a;
            float h2 = hc2 + ptm[64 + c2] + rx * w1x0b + ry * w1x1b + rz * w1x2b;
            float v1 = ptm[128 + c1] + rx * wvx0a + ry * wvx1a + rz * wvx2a;
            float v2 = ptm[128 + c2] + rx * wvx0b + ry * wvx1b + rz * wvx2b;
            float hb1 = fmaxf(a1a * h1 + d1a, 0.f);
            float hb2 = fmaxf(a1b * h2 + d1b, 0.f);
            vv1[k] = fmaxf(ava * v1 + dva, 0.f);
            vv2[k] = fmaxf(avb * v2 + dvb, 0.f);
            float t = hb1 * w2a + hb2 * w2b;
#pragma unroll
            for (int off = 16; off > 0; off >>= 1) t += __shfl_xor_sync(0xffffffffu, t, off);
            logits[k] = t + b2v;
        }
        // softmax over K
        float mx = logits[0];
#pragma unroll
        for (int k = 1; k < KK; k++) mx = fmaxf(mx, logits[k]);
        float ex[KK], se = 0.f;
#pragma unroll
        for (int k = 0; k < KK; k++) { ex[k] = expf(logits[k] - mx); se += ex[k]; }
        float out1 = 0.f, out2 = 0.f;
#pragma unroll
        for (int k = 0; k < KK; k++) {
            float w = ex[k] / se;
            out1 += w * vv1[k];
            out2 += w * vv2[k];
        }
        __syncwarp();
        sOut[wid][c1] = out1; sOut[wid][c2] = out2;
        __syncwarp();
        float oo1 = boa, oo2 = bob;
#pragma unroll 8
        for (int j = 0; j < 64; j++) {
            float oj = sOut[wid][j];
            oo1 = fmaf(sWo[j][c1], oj, oo1);
            oo2 = fmaf(sWo[j][c2], oj, oo2);
        }
        g_Opre[(size_t)p * 64 + c1] = oo1;
        g_Opre[(size_t)p * 64 + c2] = oo2;
        so1 += oo1; so1q += oo1 * oo1;
        so2 += oo2; so2q += oo2 * oo2;
    }
    atomicAdd(&sstat[c1], so1); atomicAdd(&sstat[64 + c1], so1q);
    atomicAdd(&sstat[c2], so2); atomicAdd(&sstat[64 + c2], so2q);
    __syncthreads();
    for (int e = tid; e < 128; e += 256) atomicAdd(&g_ostats[e], sstat[e]);
}

// ---------------- k6: stats -> BN coefficients for o ----------------------------
__global__ void k6(const float* __restrict__ go, const float* __restrict__ beo) {
    int c = threadIdx.x;
    float cnt = (float)NPTS;
    float m = g_ostats[c] / cnt;
    float v = g_ostats[64 + c] / cnt - m * m;
    float a = go[c] * rsqrtf(v + 1e-5f);
    g_ocoef[c] = a; g_ocoef[64 + c] = beo[c] - a * m;
}

// ---------------- k7: BN + relu + residual + transpose to [B,C,N] ---------------
__global__ void k7(const float* __restrict__ feats, float* __restrict__ out) {
    __shared__ float tile[32][65];
    int blk = blockIdx.x;
    int b = blk >> 8;
    int n0 = (blk & 255) << 5;
    int tid = threadIdx.x;
    for (int e = tid; e < 32 * 64; e += 256) {
        int pp = e >> 6, c = e & 63;
        tile[pp][c] = g_Opre[(size_t)(b * NN + n0 + pp) * 64 + c];
    }
    __syncthreads();
    for (int e = tid; e < 64 * 32; e += 256) {
        int c = e >> 5, j = e & 31;
        float val = g_ocoef[c] * tile[j][c] + g_ocoef[64 + c];
        val = fmaxf(val, 0.f) + feats[(size_t)b * CC * NN + (size_t)c * NN + n0 + j];
        out[(size_t)b * CC * NN + (size_t)c * NN + n0 + j] = val;
    }
}

// ---------------- launch ---------------------------------------------------------
extern "C" void kernel_launch(void* const* d_in, const int* in_sizes, int n_in,
                              void* d_out, int out_size) {
    const float* xyz   = (const float*)d_in[0];
    const float* feats = (const float*)d_in[1];
    const float* W1    = (const float*)d_in[2];
    const float* b1    = (const float*)d_in[3];
    const float* g1    = (const float*)d_in[4];
    const float* be1   = (const float*)d_in[5];
    const float* W2    = (const float*)d_in[6];
    const float* b2    = (const float*)d_in[7];
    const float* Wv    = (const float*)d_in[8];
    const float* bv    = (const float*)d_in[9];
    const float* gv    = (const float*)d_in[10];
    const float* bev   = (const float*)d_in[11];
    const float* Wo    = (const float*)d_in[12];
    const float* bo    = (const float*)d_in[13];
    const float* go    = (const float*)d_in[14];
    const float* beo   = (const float*)d_in[15];
    float* out = (float*)d_out;

    k_zero<<<1, 256>>>();
    k0<<<NPTS / 256, 256>>>(xyz);
    k1<<<NPTS / 256, 256>>>();
    k2<<<NPTS / 32, 256>>>(feats, W1, b1, Wv, bv);
    k3<<<1184, 256>>>(W1, Wv);
    k4<<<1, 64>>>(g1, be1, gv, bev);
    k5<<<1184, 256>>>(W1, Wv, W2, b2, Wo, bo);
    k6<<<1, 64>>>(go, beo);
    k7<<<NPTS / 32, 256>>>(feats, out);
}

// round 3
// speedup vs baseline: 2.7720x; 1.6959x over previous
#include <cuda_runtime.h>
#include <cfloat>
#include <math.h>

#define BB 4
#define NN 8192
#define CC 64
#define KK 16
#define HH 64
#define NPTS (BB*NN)

// ---------------- device scratch ------------------------------------------------
__device__ float4 g_P4[NPTS];                    // (x,y,z,|p|^2)
__device__ float  g_PT[(size_t)NPTS*192];        // [hc+b1 (64) | hn (64) | vn+bv (64)]
__device__ int    g_NB[NPTS*KK];                 // knn indices
__device__ float  g_stats[256];
__device__ float  g_coef1[256];
__device__ float  g_ostats[128];
__device__ float  g_ocoef[128];
__device__ float  g_Opre[(size_t)NPTS*64];

// ---------------- k_zero --------------------------------------------------------
__global__ void k_zero() {
    int t = threadIdx.x;
    g_stats[t] = 0.f;
    if (t < 128) g_ostats[t] = 0.f;
}

// ---------------- k0: pack xyz --------------------------------------------------
__global__ void k0(const float* __restrict__ xyz) {
    int p = blockIdx.x * blockDim.x + threadIdx.x;
    if (p >= NPTS) return;
    int b = p >> 13, n = p & (NN - 1);
    const float* base = xyz + (size_t)b * 3 * NN + n;
    float x = base[0], y = base[NN], z = base[2 * NN];
    g_P4[p] = make_float4(x, y, z, x * x + y * y + z * z);
}

// ---------------- k1: KNN, 1 warp/block, smem top-k lists -----------------------
#define TS 1024
__global__ void __launch_bounds__(32) k1() {
    __shared__ float4   sP[TS];           // candidate tile
    __shared__ unsigned sVal[32 * 16];    // [lane][slot] packed dist|slot
    __shared__ int      sIdx[32 * 16];    // [lane][slot] candidate index

    int lane = threadIdx.x;
    int blk  = blockIdx.x;                // 1024 blocks
    int b    = blk >> 8;                  // 256 blocks per batch
    int n    = ((blk & 255) << 5) + lane;
    int p    = b * NN + n;

    float4 q = g_P4[p];
    float m2x = -2.f * q.x, m2y = -2.f * q.y, m2z = -2.f * q.z, qw = q.w;

    int vbase = lane * 16;
#pragma unroll
    for (int s = 0; s < 16; s++) {
        sVal[vbase + s] = 0x7F7FFFF0u | (unsigned)s;
        sIdx[vbase + s] = 0;
    }
    unsigned worstP = 0x7F7FFFFFu;
    float thr = __uint_as_float(0x7F7FFFF0u) - qw;   // huge

    for (int t0 = 0; t0 < NN; t0 += TS) {
        __syncwarp();
        const float4* src = g_P4 + b * NN + t0;
#pragma unroll
        for (int i = 0; i < TS / 32; i++)
            sP[lane + i * 32] = src[lane + i * 32];
        __syncwarp();

#pragma unroll 2
        for (int j = 0; j < TS; j += 4) {
            float4 ca = sP[j], cb = sP[j + 1], cc = sP[j + 2], cd = sP[j + 3];
            float ta = fmaf(ca.z, m2z, fmaf(ca.y, m2y, fmaf(ca.x, m2x, ca.w)));
            float tb = fmaf(cb.z, m2z, fmaf(cb.y, m2y, fmaf(cb.x, m2x, cb.w)));
            float tc = fmaf(cc.z, m2z, fmaf(cc.y, m2y, fmaf(cc.x, m2x, cc.w)));
            float td = fmaf(cd.z, m2z, fmaf(cd.y, m2y, fmaf(cd.x, m2x, cd.w)));
            float mm = fminf(fminf(ta, tb), fminf(tc, td));
            if (mm < thr) {
                float t4[4] = {ta, tb, tc, td};
                int cbase = t0 + j;
#pragma unroll
                for (int uu = 0; uu < 4; uu++) {
                    float ti = t4[uu];
                    if (ti < thr) {
                        float ts = fmaxf(ti + qw, 0.f);
                        unsigned slot = worstP & 0xFu;
                        sVal[vbase + slot] = (__float_as_uint(ts) & 0xFFFFFFF0u) | slot;
                        sIdx[vbase + slot] = cbase + uu;
                        unsigned mmax = 0u;
                        const uint4* vp = (const uint4*)(sVal + vbase);
#pragma unroll
                        for (int s4 = 0; s4 < 4; s4++) {
                            uint4 v = vp[s4];
                            mmax = max(mmax, max(max(v.x, v.y), max(v.z, v.w)));
                        }
                        worstP = mmax;
                        thr = __uint_as_float(mmax & 0xFFFFFFF0u) - qw;
                    }
                }
            }
        }
    }

#pragma unroll
    for (int s = 0; s < 16; s++) g_NB[p * KK + s] = sIdx[vbase + s];
}

// ---------------- k2: per-point transforms (4 outs x 8 pts per thread) ----------
// 192 threads, 64 points/block, 192 outputs in 2 halves of 96
__global__ void __launch_bounds__(192) k2(const float* __restrict__ feats,
                   const float* __restrict__ W1, const float* __restrict__ b1,
                   const float* __restrict__ Wv, const float* __restrict__ bv) {
    __shared__ float sW[64][96];   // sW[c][o_local]
    __shared__ float sF[64][64];   // sF[c][n_local]
    int tid = threadIdx.x;
    int blk = blockIdx.x;
    int b   = blk >> 7;            // 128 blocks per batch
    int n0  = (blk & 127) << 6;

    // load feats tile (vectorized)
    for (int e = tid; e < 64 * 16; e += 192) {
        int c = e >> 4, v4 = e & 15;
        ((float4*)sF[c])[v4] =
            ((const float4*)(feats + (size_t)b * CC * NN + (size_t)c * NN + n0))[v4];
    }

    int og = tid >> 3;     // 0..23 -> 4 outputs each
    int ng = tid & 7;      // 0..7  -> 8 points each

    for (int half = 0; half < 2; half++) {
        __syncthreads();
        for (int e = tid; e < 96 * 64; e += 192) {
            int ol = e % 96, c = e / 96;
            int o = ol + half * 96;
            float w;
            if (o < 64)       w = W1[o * 131 + c];
            else if (o < 128) w = W1[(o - 64) * 131 + 64 + c];
            else              w = Wv[(o - 128) * 67 + c];
            sW[c][ol] = w;
        }
        __syncthreads();

        float4 acc[8];
#pragma unroll
        for (int j = 0; j < 8; j++) acc[j] = make_float4(0.f, 0.f, 0.f, 0.f);

        for (int c = 0; c < 64; c++) {
            float4 a  = *(const float4*)&sW[c][og * 4];
            float4 f0 = *(const float4*)&sF[c][ng * 8];
            float4 f1 = *(const float4*)&sF[c][ng * 8 + 4];
            float f[8] = {f0.x, f0.y, f0.z, f0.w, f1.x, f1.y, f1.z, f1.w};
#pragma unroll
            for (int j = 0; j < 8; j++) {
                acc[j].x = fmaf(a.x, f[j], acc[j].x);
                acc[j].y = fmaf(a.y, f[j], acc[j].y);
                acc[j].z = fmaf(a.z, f[j], acc[j].z);
                acc[j].w = fmaf(a.w, f[j], acc[j].w);
            }
        }

        int o_base = half * 96 + og * 4;
        float4 bb;
        if (o_base < 64)        bb = *(const float4*)(b1 + o_base);
        else if (o_base < 128)  bb = make_float4(0.f, 0.f, 0.f, 0.f);
        else                    bb = *(const float4*)(bv + (o_base - 128));
#pragma unroll
        for (int j = 0; j < 8; j++) {
            float4 r = make_float4(acc[j].x + bb.x, acc[j].y + bb.y,
                                   acc[j].z + bb.z, acc[j].w + bb.w);
            *(float4*)(g_PT + (size_t)(b * NN + n0 + ng * 8 + j) * 192 + o_base) = r;
        }
    }
}

// ---------------- k3: BN stats for h and v --------------------------------------
__global__ void k3(const float* __restrict__ W1, const float* __restrict__ Wv) {
    __shared__ float sstat[256];
    int tid = threadIdx.x, lane = tid & 31, wid = tid >> 5;
    for (int e = tid; e < 256; e += 256) sstat[e] = 0.f;
    __syncthreads();

    int c1 = lane, c2 = lane + 32;
    float w1x0a = W1[c1 * 131 + 128], w1x1a = W1[c1 * 131 + 129], w1x2a = W1[c1 * 131 + 130];
    float w1x0b = W1[c2 * 131 + 128], w1x1b = W1[c2 * 131 + 129], w1x2b = W1[c2 * 131 + 130];
    float wvx0a = Wv[c1 * 67 + 64],  wvx1a = Wv[c1 * 67 + 65],  wvx2a = Wv[c1 * 67 + 66];
    float wvx0b = Wv[c2 * 67 + 64],  wvx1b = Wv[c2 * 67 + 65],  wvx2b = Wv[c2 * 67 + 66];

    float s0=0,s1=0,s2=0,s3=0,s4=0,s5=0,s6=0,s7=0;
    int gw = blockIdx.x * 8 + wid, nw = gridDim.x * 8;
    for (int p = gw; p < NPTS; p += nw) {
        int b = p >> 13;
        float4 q = g_P4[p];
        const float* ptp = g_PT + (size_t)p * 192;
        float hc1 = ptp[c1], hc2 = ptp[c2];
#pragma unroll 4
        for (int k = 0; k < KK; k++) {
            int m = g_NB[p * KK + k];
            float4 pm = g_P4[b * NN + m];
            float rx = pm.x - q.x, ry = pm.y - q.y, rz = pm.z - q.z;
            const float* ptm = g_PT + (size_t)(b * NN + m) * 192;
            float h1 = hc1 + ptm[64 + c1] + rx * w1x0a + ry * w1x1a + rz * w1x2a;
            float h2 = hc2 + ptm[64 + c2] + rx * w1x0b + ry * w1x1b + rz * w1x2b;
            float v1 = ptm[128 + c1] + rx * wvx0a + ry * wvx1a + rz * wvx2a;
            float v2 = ptm[128 + c2] + rx * wvx0b + ry * wvx1b + rz * wvx2b;
            s0 += h1; s1 += h1 * h1; s2 += h2; s3 += h2 * h2;
            s4 += v1; s5 += v1 * v1; s6 += v2; s7 += v2 * v2;
        }
    }
    atomicAdd(&sstat[c1], s0);        atomicAdd(&sstat[64 + c1], s1);
    atomicAdd(&sstat[c2], s2);        atomicAdd(&sstat[64 + c2], s3);
    atomicAdd(&sstat[128 + c1], s4);  atomicAdd(&sstat[192 + c1], s5);
    atomicAdd(&sstat[128 + c2], s6);  atomicAdd(&sstat[192 + c2], s7);
    __syncthreads();
    for (int e = tid; e < 256; e += 256) atomicAdd(&g_stats[e], sstat[e]);
}

// ---------------- k4: stats -> BN coefficients ----------------------------------
__global__ void k4(const float* __restrict__ g1, const float* __restrict__ be1,
                   const float* __restrict__ gv, const float* __restrict__ bev) {
    int c = threadIdx.x;
    float cnt = (float)((size_t)NPTS * KK);
    float mh = g_stats[c] / cnt;
    float vh = g_stats[64 + c] / cnt - mh * mh;
    float a1 = g1[c] * rsqrtf(vh + 1e-5f);
    g_coef1[c] = a1; g_coef1[64 + c] = be1[c] - a1 * mh;
    float mv = g_stats[128 + c] / cnt;
    float vv = g_stats[192 + c] / cnt - mv * mv;
    float av = gv[c] * rsqrtf(vv + 1e-5f);
    g_coef1[128 + c] = av; g_coef1[192 + c] = bev[c] - av * mv;
}

// ---------------- k5: attention + value + weighted sum + out-conv ---------------
__global__ void k5(const float* __restrict__ W1, const float* __restrict__ Wv,
                   const float* __restrict__ W2, const float* __restrict__ b2,
                   const float* __restrict__ Wo, const float* __restrict__ bo) {
    __shared__ float sWo[64][65];
    __shared__ float sOut[8][64];
    __shared__ float sstat[128];
    int tid = threadIdx.x, lane = tid & 31, wid = tid >> 5;

    for (int e = tid; e < 64 * 64; e += 256) {
        int j = e >> 6, c = e & 63;
        sWo[j][c] = Wo[c * 64 + j];
    }
    for (int e = tid; e < 128; e += 256) sstat[e] = 0.f;

    int c1 = lane, c2 = lane + 32;
    float w1x0a = W1[c1 * 131 + 128], w1x1a = W1[c1 * 131 + 129], w1x2a = W1[c1 * 131 + 130];
    float w1x0b = W1[c2 * 131 + 128], w1x1b = W1[c2 * 131 + 129], w1x2b = W1[c2 * 131 + 130];
    float wvx0a = Wv[c1 * 67 + 64],  wvx1a = Wv[c1 * 67 + 65],  wvx2a = Wv[c1 * 67 + 66];
    float wvx0b = Wv[c2 * 67 + 64],  wvx1b = Wv[c2 * 67 + 65],  wvx2b = Wv[c2 * 67 + 66];
    float a1a = g_coef1[c1],      a1b = g_coef1[c2];
    float d1a = g_coef1[64 + c1], d1b = g_coef1[64 + c2];
    float ava = g_coef1[128 + c1], avb = g_coef1[128 + c2];
    float dva = g_coef1[192 + c1], dvb = g_coef1[192 + c2];
    float w2a = W2[c1], w2b = W2[c2];
    float b2v = b2[0];
    float boa = bo[c1], bob = bo[c2];
    __syncthreads();

    float so1 = 0.f, so1q = 0.f, so2 = 0.f, so2q = 0.f;
    int gw = blockIdx.x * 8 + wid, nw = gridDim.x * 8;

    for (int p = gw; p < NPTS; p += nw) {
        int b = p >> 13;
        float4 q = g_P4[p];
        const float* ptp = g_PT + (size_t)p * 192;
        float hc1 = ptp[c1], hc2 = ptp[c2];

        float logits[KK], vv1[KK], vv2[KK];
#pragma unroll
        for (int k = 0; k < KK; k++) {
            int m = g_NB[p * KK + k];
            float4 pm = g_P4[b * NN + m];
            float rx = pm.x - q.x, ry = pm.y - q.y, rz = pm.z - q.z;
            const float* ptm = g_PT + (size_t)(b * NN + m) * 192;
            float h1 = hc1 + ptm[64 + c1] + rx * w1x0a + ry * w1x1a + rz * w1x2a;
            float h2 = hc2 + ptm[64 + c2] + rx * w1x0b + ry * w1x1b + rz * w1x2b;
            float v1 = ptm[128 + c1] + rx * wvx0a + ry * wvx1a + rz * wvx2a;
            float v2 = ptm[128 + c2] + rx * wvx0b + ry * wvx1b + rz * wvx2b;
            float hb1 = fmaxf(a1a * h1 + d1a, 0.f);
            float hb2 = fmaxf(a1b * h2 + d1b, 0.f);
            vv1[k] = fmaxf(ava * v1 + dva, 0.f);
            vv2[k] = fmaxf(avb * v2 + dvb, 0.f);
            float t = hb1 * w2a + hb2 * w2b;
#pragma unroll
            for (int off = 16; off > 0; off >>= 1) t += __shfl_xor_sync(0xffffffffu, t, off);
            logits[k] = t + b2v;
        }
        float mx = logits[0];
#pragma unroll
        for (int k = 1; k < KK; k++) mx = fmaxf(mx, logits[k]);
        float ex[KK], se = 0.f;
#pragma unroll
        for (int k = 0; k < KK; k++) { ex[k] = expf(logits[k] - mx); se += ex[k]; }
        float out1 = 0.f, out2 = 0.f;
#pragma unroll
        for (int k = 0; k < KK; k++) {
            float w = ex[k] / se;
            out1 += w * vv1[k];
            out2 += w * vv2[k];
        }
        __syncwarp();
        sOut[wid][c1] = out1; sOut[wid][c2] = out2;
        __syncwarp();
        float oo1 = boa, oo2 = bob;
#pragma unroll 8
        for (int j = 0; j < 64; j++) {
            float oj = sOut[wid][j];
            oo1 = fmaf(sWo[j][c1], oj, oo1);
            oo2 = fmaf(sWo[j][c2], oj, oo2);
        }
        g_Opre[(size_t)p * 64 + c1] = oo1;
        g_Opre[(size_t)p * 64 + c2] = oo2;
        so1 += oo1; so1q += oo1 * oo1;
        so2 += oo2; so2q += oo2 * oo2;
    }
    atomicAdd(&sstat[c1], so1); atomicAdd(&sstat[64 + c1], so1q);
    atomicAdd(&sstat[c2], so2); atomicAdd(&sstat[64 + c2], so2q);
    __syncthreads();
    for (int e = tid; e < 128; e += 256) atomicAdd(&g_ostats[e], sstat[e]);
}

// ---------------- k6 ------------------------------------------------------------
__global__ void k6(const float* __restrict__ go, const float* __restrict__ beo) {
    int c = threadIdx.x;
    float cnt = (float)NPTS;
    float m = g_ostats[c] / cnt;
    float v = g_ostats[64 + c] / cnt - m * m;
    float a = go[c] * rsqrtf(v + 1e-5f);
    g_ocoef[c] = a; g_ocoef[64 + c] = beo[c] - a * m;
}

// ---------------- k7: BN + relu + residual + transpose --------------------------
__global__ void k7(const float* __restrict__ feats, float* __restrict__ out) {
    __shared__ float tile[32][65];
    int blk = blockIdx.x;
    int b = blk >> 8;
    int n0 = (blk & 255) << 5;
    int tid = threadIdx.x;
    for (int e = tid; e < 32 * 64; e += 256) {
        int pp = e >> 6, c = e & 63;
        tile[pp][c] = g_Opre[(size_t)(b * NN + n0 + pp) * 64 + c];
    }
    __syncthreads();
    for (int e = tid; e < 64 * 32; e += 256) {
        int c = e >> 5, j = e & 31;
        float val = g_ocoef[c] * tile[j][c] + g_ocoef[64 + c];
        val = fmaxf(val, 0.f) + feats[(size_t)b * CC * NN + (size_t)c * NN + n0 + j];
        out[(size_t)b * CC * NN + (size_t)c * NN + n0 + j] = val;
    }
}

// ---------------- launch --------------------------------------------------------
extern "C" void kernel_launch(void* const* d_in, const int* in_sizes, int n_in,
                              void* d_out, int out_size) {
    const float* xyz   = (const float*)d_in[0];
    const float* feats = (const float*)d_in[1];
    const float* W1    = (const float*)d_in[2];
    const float* b1    = (const float*)d_in[3];
    const float* g1    = (const float*)d_in[4];
    const float* be1   = (const float*)d_in[5];
    const float* W2    = (const float*)d_in[6];
    const float* b2    = (const float*)d_in[7];
    const float* Wv    = (const float*)d_in[8];
    const float* bv    = (const float*)d_in[9];
    const float* gv    = (const float*)d_in[10];
    const float* bev   = (const float*)d_in[11];
    const float* Wo    = (const float*)d_in[12];
    const float* bo    = (const float*)d_in[13];
    const float* go    = (const float*)d_in[14];
    const float* beo   = (const float*)d_in[15];
    float* out = (float*)d_out;

    k_zero<<<1, 256>>>();
    k0<<<NPTS / 256, 256>>>(xyz);
    k1<<<NPTS / 32, 32>>>();
    k2<<<NPTS / 64, 192>>>(feats, W1, b1, Wv, bv);
    k3<<<1184, 256>>>(W1, Wv);
    k4<<<1, 64>>>(g1, be1, gv, bev);
    k5<<<1184, 256>>>(W1, Wv, W2, b2, Wo, bo);
    k6<<<1, 64>>>(go, beo);
    k7<<<NPTS / 32, 256>>>(feats, out);
}

// round 4
// speedup vs baseline: 3.0207x; 1.0897x over previous
#include <cuda_runtime.h>
#include <cfloat>
#include <math.h>

#define BB 4
#define NN 8192
#define CC 64
#define KK 16
#define HH 64
#define NPTS (BB*NN)

// ---------------- device scratch ------------------------------------------------
__device__ float4 g_P4[NPTS];                    // (x,y,z,|p|^2)
__device__ float  g_Sx[NPTS], g_Sy[NPTS], g_Sz[NPTS], g_Sq[NPTS];  // SoA coords
__device__ float  g_PT[(size_t)NPTS*192];        // [hc+b1 (64) | hn (64) | vn+bv (64)]
__device__ int    g_NB[NPTS*KK];                 // knn indices
__device__ float  g_stats[256];
__device__ float  g_coef1[256];
__device__ float  g_ostats[128];
__device__ float  g_ocoef[128];
__device__ float  g_Opre[(size_t)NPTS*64];

// ---------------- f32x2 helpers -------------------------------------------------
__device__ __forceinline__ unsigned long long fma2(unsigned long long a,
                                                   unsigned long long b,
                                                   unsigned long long c) {
    unsigned long long d;
    asm("fma.rn.f32x2 %0,%1,%2,%3;" : "=l"(d) : "l"(a), "l"(b), "l"(c));
    return d;
}
__device__ __forceinline__ unsigned long long pk2(float v) {
    unsigned long long d;
    asm("mov.b64 %0,{%1,%1};" : "=l"(d) : "f"(v));
    return d;
}
__device__ __forceinline__ float2 unpk(unsigned long long v) {
    float2 r;
    asm("mov.b64 {%0,%1},%2;" : "=f"(r.x), "=f"(r.y) : "l"(v));
    return r;
}

// ---------------- k0: pack xyz (AoS + SoA) + zero stats -------------------------
__global__ void k0(const float* __restrict__ xyz) {
    int p = blockIdx.x * blockDim.x + threadIdx.x;
    if (p < 256) g_stats[p] = 0.f;
    if (p < 128) g_ostats[p] = 0.f;
    if (p >= NPTS) return;
    int b = p >> 13, n = p & (NN - 1);
    const float* base = xyz + (size_t)b * 3 * NN + n;
    float x = base[0], y = base[NN], z = base[2 * NN];
    float w = x * x + y * y + z * z;
    g_P4[p] = make_float4(x, y, z, w);
    g_Sx[p] = x; g_Sy[p] = y; g_Sz[p] = z; g_Sq[p] = w;
}

// ---------------- k1: KNN, 1 warp/block, f32x2 fast path ------------------------
#define TS 1024
__global__ void __launch_bounds__(32) k1() {
    __shared__ __align__(16) float sX[TS];
    __shared__ __align__(16) float sY[TS];
    __shared__ __align__(16) float sZ[TS];
    __shared__ __align__(16) float sWW[TS];
    __shared__ unsigned sVal[32 * 16];    // [lane][slot] packed dist|slot
    __shared__ int      sIdx[32 * 16];    // [lane][slot] candidate index

    int lane = threadIdx.x;
    int blk  = blockIdx.x;                // 1024 blocks
    int b    = blk >> 8;                  // 256 blocks per batch
    int n    = ((blk & 255) << 5) + lane;
    int p    = b * NN + n;

    float4 q = g_P4[p];
    float m2xf = -2.f * q.x, m2yf = -2.f * q.y, m2zf = -2.f * q.z, qw = q.w;
    unsigned long long m2x = pk2(m2xf), m2y = pk2(m2yf), m2z = pk2(m2zf);

    int vbase = lane * 16;
#pragma unroll
    for (int s = 0; s < 16; s++) {
        sVal[vbase + s] = 0x7F7FFFF0u | (unsigned)s;
        sIdx[vbase + s] = 0;
    }
    unsigned worstP = 0x7F7FFFFFu;
    float thr = __uint_as_float(0x7F7FFFF0u) - qw;   // huge

    for (int t0 = 0; t0 < NN; t0 += TS) {
        __syncwarp();
        const float* bx = g_Sx + b * NN + t0;
        const float* by = g_Sy + b * NN + t0;
        const float* bz = g_Sz + b * NN + t0;
        const float* bw = g_Sq + b * NN + t0;
#pragma unroll
        for (int i = 0; i < TS / 128; i++) {
            int o = i * 128 + lane * 4;
            *(float4*)(sX  + o) = *(const float4*)(bx + o);
            *(float4*)(sY  + o) = *(const float4*)(by + o);
            *(float4*)(sZ  + o) = *(const float4*)(bz + o);
            *(float4*)(sWW + o) = *(const float4*)(bw + o);
        }
        __syncwarp();

        for (int j = 0; j < TS; j += 8) {
            ulonglong2 X0 = *(const ulonglong2*)(sX  + j);
            ulonglong2 Y0 = *(const ulonglong2*)(sY  + j);
            ulonglong2 Z0 = *(const ulonglong2*)(sZ  + j);
            ulonglong2 W0 = *(const ulonglong2*)(sWW + j);
            ulonglong2 X1 = *(const ulonglong2*)(sX  + j + 4);
            ulonglong2 Y1 = *(const ulonglong2*)(sY  + j + 4);
            ulonglong2 Z1 = *(const ulonglong2*)(sZ  + j + 4);
            ulonglong2 W1 = *(const ulonglong2*)(sWW + j + 4);
            unsigned long long t0a = fma2(Z0.x, m2z, fma2(Y0.x, m2y, fma2(X0.x, m2x, W0.x)));
            unsigned long long t0b = fma2(Z0.y, m2z, fma2(Y0.y, m2y, fma2(X0.y, m2x, W0.y)));
            unsigned long long t1a = fma2(Z1.x, m2z, fma2(Y1.x, m2y, fma2(X1.x, m2x, W1.x)));
            unsigned long long t1b = fma2(Z1.y, m2z, fma2(Y1.y, m2y, fma2(X1.y, m2x, W1.y)));
            float2 f01 = unpk(t0a), f23 = unpk(t0b), f45 = unpk(t1a), f67 = unpk(t1b);
            float m01 = fminf(f01.x, f01.y), m23 = fminf(f23.x, f23.y);
            float m45 = fminf(f45.x, f45.y), m67 = fminf(f67.x, f67.y);
            float mm = fminf(fminf(m01, m23), fminf(m45, m67));
            if (mm < thr) {
                float tt[8] = {f01.x, f01.y, f23.x, f23.y, f45.x, f45.y, f67.x, f67.y};
#pragma unroll
                for (int uu = 0; uu < 8; uu++) {
                    if (tt[uu] < thr) {
                        float ts = fmaxf(tt[uu] + qw, 0.f);
                        unsigned slot = worstP & 0xFu;
                        sVal[vbase + slot] = (__float_as_uint(ts) & 0xFFFFFFF0u) | slot;
                        sIdx[vbase + slot] = t0 + j + uu;
                        unsigned mmax = 0u;
                        const uint4* vp = (const uint4*)(sVal + vbase);
#pragma unroll
                        for (int s4 = 0; s4 < 4; s4++) {
                            uint4 v = vp[s4];
                            mmax = max(mmax, max(max(v.x, v.y), max(v.z, v.w)));
                        }
                        worstP = mmax;
                        thr = __uint_as_float(mmax & 0xFFFFFFF0u) - qw;
                    }
                }
            }
        }
    }

#pragma unroll
    for (int s = 0; s < 16; s++) g_NB[p * KK + s] = sIdx[vbase + s];
}

// ---------------- k2: per-point transforms, 3 passes of 64 outs -----------------
// 256 threads, 64 points/block; thread = 4 outs x 4 pts
__global__ void __launch_bounds__(256) k2(const float* __restrict__ feats,
                   const float* __restrict__ W1, const float* __restrict__ b1,
                   const float* __restrict__ Wv, const float* __restrict__ bv) {
    __shared__ float sW[64][64];   // sW[c][o_local]
    __shared__ float sF[64][64];   // sF[c][n_local]
    int tid = threadIdx.x;
    int blk = blockIdx.x;
    int b   = blk >> 7;            // 128 blocks per batch
    int n0  = (blk & 127) << 6;

    for (int e = tid; e < 1024; e += 256) {
        int c = e >> 4, v4 = e & 15;
        ((float4*)sF[c])[v4] =
            ((const float4*)(feats + (size_t)b * CC * NN + (size_t)c * NN + n0))[v4];
    }

    int og = tid & 15, ng = tid >> 4;

    for (int pp = 0; pp < 3; pp++) {
        __syncthreads();
        for (int e = tid; e < 4096; e += 256) {
            int ol = e & 63, c = e >> 6;
            float w;
            if (pp == 0)      w = W1[ol * 131 + c];
            else if (pp == 1) w = W1[ol * 131 + 64 + c];
            else              w = Wv[ol * 67 + c];
            sW[c][ol] = w;
        }
        __syncthreads();

        float4 a0 = make_float4(0.f,0.f,0.f,0.f), a1 = a0, a2 = a0, a3 = a0;
        for (int c = 0; c < 64; c++) {
            float4 w4 = *(const float4*)&sW[c][og * 4];
            float4 f4 = *(const float4*)&sF[c][ng * 4];
            a0.x = fmaf(w4.x, f4.x, a0.x); a0.y = fmaf(w4.y, f4.x, a0.y);
            a0.z = fmaf(w4.z, f4.x, a0.z); a0.w = fmaf(w4.w, f4.x, a0.w);
            a1.x = fmaf(w4.x, f4.y, a1.x); a1.y = fmaf(w4.y, f4.y, a1.y);
            a1.z = fmaf(w4.z, f4.y, a1.z); a1.w = fmaf(w4.w, f4.y, a1.w);
            a2.x = fmaf(w4.x, f4.z, a2.x); a2.y = fmaf(w4.y, f4.z, a2.y);
            a2.z = fmaf(w4.z, f4.z, a2.z); a2.w = fmaf(w4.w, f4.z, a2.w);
            a3.x = fmaf(w4.x, f4.w, a3.x); a3.y = fmaf(w4.y, f4.w, a3.y);
            a3.z = fmaf(w4.z, f4.w, a3.z); a3.w = fmaf(w4.w, f4.w, a3.w);
        }

        float4 bb = make_float4(0.f, 0.f, 0.f, 0.f);
        if (pp == 0) bb = *(const float4*)(b1 + og * 4);
        if (pp == 2) bb = *(const float4*)(bv + og * 4);
        int obase = pp * 64 + og * 4;
        float4 r;
        size_t pbase = (size_t)(b * NN + n0 + ng * 4);
        r = make_float4(a0.x+bb.x, a0.y+bb.y, a0.z+bb.z, a0.w+bb.w);
        *(float4*)(g_PT + (pbase + 0) * 192 + obase) = r;
        r = make_float4(a1.x+bb.x, a1.y+bb.y, a1.z+bb.z, a1.w+bb.w);
        *(float4*)(g_PT + (pbase + 1) * 192 + obase) = r;
        r = make_float4(a2.x+bb.x, a2.y+bb.y, a2.z+bb.z, a2.w+bb.w);
        *(float4*)(g_PT + (pbase + 2) * 192 + obase) = r;
        r = make_float4(a3.x+bb.x, a3.y+bb.y, a3.z+bb.z, a3.w+bb.w);
        *(float4*)(g_PT + (pbase + 3) * 192 + obase) = r;
    }
}

// ---------------- k3: BN stats for h and v --------------------------------------
__global__ void __launch_bounds__(256) k3(const float* __restrict__ W1,
                                          const float* __restrict__ Wv) {
    __shared__ float sstat[256];
    int tid = threadIdx.x, lane = tid & 31, wid = tid >> 5;
    for (int e = tid; e < 256; e += 256) sstat[e] = 0.f;
    __syncthreads();

    int c1 = lane, c2 = lane + 32;
    float w1x0a = W1[c1 * 131 + 128], w1x1a = W1[c1 * 131 + 129], w1x2a = W1[c1 * 131 + 130];
    float w1x0b = W1[c2 * 131 + 128], w1x1b = W1[c2 * 131 + 129], w1x2b = W1[c2 * 131 + 130];
    float wvx0a = Wv[c1 * 67 + 64],  wvx1a = Wv[c1 * 67 + 65],  wvx2a = Wv[c1 * 67 + 66];
    float wvx0b = Wv[c2 * 67 + 64],  wvx1b = Wv[c2 * 67 + 65],  wvx2b = Wv[c2 * 67 + 66];

    float s0=0,s1=0,s2=0,s3=0,s4=0,s5=0,s6=0,s7=0;
    int gw = blockIdx.x * 8 + wid, nw = gridDim.x * 8;
    for (int p = gw; p < NPTS; p += nw) {
        int b = p >> 13;
        float4 q = g_P4[p];
        const int4* nb = (const int4*)(g_NB + p * KK);
        int4 iA = nb[0], iB = nb[1], iC = nb[2], iD = nb[3];
        int mi[16] = {iA.x, iA.y, iA.z, iA.w, iB.x, iB.y, iB.z, iB.w,
                      iC.x, iC.y, iC.z, iC.w, iD.x, iD.y, iD.z, iD.w};
        const float* ptp = g_PT + (size_t)p * 192;
        float hc1 = ptp[c1], hc2 = ptp[c2];
#pragma unroll
        for (int k = 0; k < KK; k++) {
            int m = mi[k];
            float4 pm = g_P4[b * NN + m];
            float rx = pm.x - q.x, ry = pm.y - q.y, rz = pm.z - q.z;
            const float* ptm = g_PT + (size_t)(b * NN + m) * 192;
            float h1 = hc1 + ptm[64 + c1] + rx * w1x0a + ry * w1x1a + rz * w1x2a;
            float h2 = hc2 + ptm[64 + c2] + rx * w1x0b + ry * w1x1b + rz * w1x2b;
            float v1 = ptm[128 + c1] + rx * wvx0a + ry * wvx1a + rz * wvx2a;
            float v2 = ptm[128 + c2] + rx * wvx0b + ry * wvx1b + rz * wvx2b;
            s0 += h1; s1 += h1 * h1; s2 += h2; s3 += h2 * h2;
            s4 += v1; s5 += v1 * v1; s6 += v2; s7 += v2 * v2;
        }
    }
    atomicAdd(&sstat[c1], s0);        atomicAdd(&sstat[64 + c1], s1);
    atomicAdd(&sstat[c2], s2);        atomicAdd(&sstat[64 + c2], s3);
    atomicAdd(&sstat[128 + c1], s4);  atomicAdd(&sstat[192 + c1], s5);
    atomicAdd(&sstat[128 + c2], s6);  atomicAdd(&sstat[192 + c2], s7);
    __syncthreads();
    for (int e = tid; e < 256; e += 256) atomicAdd(&g_stats[e], sstat[e]);
}

// ---------------- k4: stats -> BN coefficients ----------------------------------
__global__ void k4(const float* __restrict__ g1, const float* __restrict__ be1,
                   const float* __restrict__ gv, const float* __restrict__ bev) {
    int c = threadIdx.x;
    float cnt = (float)((size_t)NPTS * KK);
    float mh = g_stats[c] / cnt;
    float vh = g_stats[64 + c] / cnt - mh * mh;
    float a1 = g1[c] * rsqrtf(vh + 1e-5f);
    g_coef1[c] = a1; g_coef1[64 + c] = be1[c] - a1 * mh;
    float mv = g_stats[128 + c] / cnt;
    float vv = g_stats[192 + c] / cnt - mv * mv;
    float av = gv[c] * rsqrtf(vv + 1e-5f);
    g_coef1[128 + c] = av; g_coef1[192 + c] = bev[c] - av * mv;
}

// ---------------- k5: attention + value + weighted sum + out-conv ---------------
__global__ void __launch_bounds__(256) k5(const float* __restrict__ W1,
                   const float* __restrict__ Wv,
                   const float* __restrict__ W2, const float* __restrict__ b2,
                   const float* __restrict__ Wo, const float* __restrict__ bo) {
    __shared__ float sWo[64][65];
    __shared__ float sOut[8][64];
    __shared__ float sstat[128];
    int tid = threadIdx.x, lane = tid & 31, wid = tid >> 5;

    for (int e = tid; e < 64 * 64; e += 256) {
        int j = e >> 6, c = e & 63;
        sWo[j][c] = Wo[c * 64 + j];
    }
    for (int e = tid; e < 128; e += 256) sstat[e] = 0.f;

    int c1 = lane, c2 = lane + 32;
    float w1x0a = W1[c1 * 131 + 128], w1x1a = W1[c1 * 131 + 129], w1x2a = W1[c1 * 131 + 130];
    float w1x0b = W1[c2 * 131 + 128], w1x1b = W1[c2 * 131 + 129], w1x2b = W1[c2 * 131 + 130];
    float wvx0a = Wv[c1 * 67 + 64],  wvx1a = Wv[c1 * 67 + 65],  wvx2a = Wv[c1 * 67 + 66];
    float wvx0b = Wv[c2 * 67 + 64],  wvx1b = Wv[c2 * 67 + 65],  wvx2b = Wv[c2 * 67 + 66];
    float a1a = g_coef1[c1],      a1b = g_coef1[c2];
    float d1a = g_coef1[64 + c1], d1b = g_coef1[64 + c2];
    float ava = g_coef1[128 + c1], avb = g_coef1[128 + c2];
    float dva = g_coef1[192 + c1], dvb = g_coef1[192 + c2];
    float w2a = W2[c1], w2b = W2[c2];
    float b2v = b2[0];
    float boa = bo[c1], bob = bo[c2];
    __syncthreads();

    float so1 = 0.f, so1q = 0.f, so2 = 0.f, so2q = 0.f;
    int gw = blockIdx.x * 8 + wid, nw = gridDim.x * 8;

    for (int p = gw; p < NPTS; p += nw) {
        int b = p >> 13;
        float4 q = g_P4[p];
        const int4* nb = (const int4*)(g_NB + p * KK);
        int4 iA = nb[0], iB = nb[1], iC = nb[2], iD = nb[3];
        int mi[16] = {iA.x, iA.y, iA.z, iA.w, iB.x, iB.y, iB.z, iB.w,
                      iC.x, iC.y, iC.z, iC.w, iD.x, iD.y, iD.z, iD.w};
        const float* ptp = g_PT + (size_t)p * 192;
        float hc1 = ptp[c1], hc2 = ptp[c2];

        float logits[KK], vv1[KK], vv2[KK];
#pragma unroll
        for (int k = 0; k < KK; k++) {
            int m = mi[k];
            float4 pm = g_P4[b * NN + m];
            float rx = pm.x - q.x, ry = pm.y - q.y, rz = pm.z - q.z;
            const float* ptm = g_PT + (size_t)(b * NN + m) * 192;
            float h1 = hc1 + ptm[64 + c1] + rx * w1x0a + ry * w1x1a + rz * w1x2a;
            float h2 = hc2 + ptm[64 + c2] + rx * w1x0b + ry * w1x1b + rz * w1x2b;
            float v1 = ptm[128 + c1] + rx * wvx0a + ry * wvx1a + rz * wvx2a;
            float v2 = ptm[128 + c2] + rx * wvx0b + ry * wvx1b + rz * wvx2b;
            float hb1 = fmaxf(a1a * h1 + d1a, 0.f);
            float hb2 = fmaxf(a1b * h2 + d1b, 0.f);
            vv1[k] = fmaxf(ava * v1 + dva, 0.f);
            vv2[k] = fmaxf(avb * v2 + dvb, 0.f);
            float t = hb1 * w2a + hb2 * w2b;
#pragma unroll
            for (int off = 16; off > 0; off >>= 1) t += __shfl_xor_sync(0xffffffffu, t, off);
            logits[k] = t + b2v;
        }
        float mx = logits[0];
#pragma unroll
        for (int k = 1; k < KK; k++) mx = fmaxf(mx, logits[k]);
        float ex[KK], se = 0.f;
#pragma unroll
        for (int k = 0; k < KK; k++) { ex[k] = __expf(logits[k] - mx); se += ex[k]; }
        float inv = 1.0f / se;
        float out1 = 0.f, out2 = 0.f;
#pragma unroll
        for (int k = 0; k < KK; k++) {
            float w = ex[k] * inv;
            out1 += w * vv1[k];
            out2 += w * vv2[k];
        }
        __syncwarp();
        sOut[wid][c1] = out1; sOut[wid][c2] = out2;
        __syncwarp();
        float oo1 = boa, oo2 = bob;
#pragma unroll 8
        for (int j = 0; j < 64; j++) {
            float oj = sOut[wid][j];
            oo1 = fmaf(sWo[j][c1], oj, oo1);
            oo2 = fmaf(sWo[j][c2], oj, oo2);
        }
        g_Opre[(size_t)p * 64 + c1] = oo1;
        g_Opre[(size_t)p * 64 + c2] = oo2;
        so1 += oo1; so1q += oo1 * oo1;
        so2 += oo2; so2q += oo2 * oo2;
    }
    atomicAdd(&sstat[c1], so1); atomicAdd(&sstat[64 + c1], so1q);
    atomicAdd(&sstat[c2], so2); atomicAdd(&sstat[64 + c2], so2q);
    __syncthreads();
    for (int e = tid; e < 128; e += 256) atomicAdd(&g_ostats[e], sstat[e]);
}

// ---------------- k6 ------------------------------------------------------------
__global__ void k6(const float* __restrict__ go, const float* __restrict__ beo) {
    int c = threadIdx.x;
    float cnt = (float)NPTS;
    float m = g_ostats[c] / cnt;
    float v = g_ostats[64 + c] / cnt - m * m;
    float a = go[c] * rsqrtf(v + 1e-5f);
    g_ocoef[c] = a; g_ocoef[64 + c] = beo[c] - a * m;
}

// ---------------- k7: BN + relu + residual + transpose --------------------------
__global__ void k7(const float* __restrict__ feats, float* __restrict__ out) {
    __shared__ float tile[32][65];
    int blk = blockIdx.x;
    int b = blk >> 8;
    int n0 = (blk & 255) << 5;
    int tid = threadIdx.x;
    for (int e = tid; e < 32 * 64; e += 256) {
        int pp = e >> 6, c = e & 63;
        tile[pp][c] = g_Opre[(size_t)(b * NN + n0 + pp) * 64 + c];
    }
    __syncthreads();
    for (int e = tid; e < 64 * 32; e += 256) {
        int c = e >> 5, j = e & 31;
        float val = g_ocoef[c] * tile[j][c] + g_ocoef[64 + c];
        val = fmaxf(val, 0.f) + feats[(size_t)b * CC * NN + (size_t)c * NN + n0 + j];
        out[(size_t)b * CC * NN + (size_t)c * NN + n0 + j] = val;
    }
}

// ---------------- launch --------------------------------------------------------
extern "C" void kernel_launch(void* const* d_in, const int* in_sizes, int n_in,
                              void* d_out, int out_size) {
    const float* xyz   = (const float*)d_in[0];
    const float* feats = (const float*)d_in[1];
    const float* W1    = (const float*)d_in[2];
    const float* b1    = (const float*)d_in[3];
    const float* g1    = (const float*)d_in[4];
    const float* be1   = (const float*)d_in[5];
    const float* W2    = (const float*)d_in[6];
    const float* b2    = (const float*)d_in[7];
    const float* Wv    = (const float*)d_in[8];
    const float* bv    = (const float*)d_in[9];
    const float* gv    = (const float*)d_in[10];
    const float* bev   = (const float*)d_in[11];
    const float* Wo    = (const float*)d_in[12];
    const float* bo    = (const float*)d_in[13];
    const float* go    = (const float*)d_in[14];
    const float* beo   = (const float*)d_in[15];
    float* out = (float*)d_out;

    k0<<<NPTS / 256, 256>>>(xyz);
    k1<<<NPTS / 32, 32>>>();
    k2<<<NPTS / 64, 256>>>(feats, W1, b1, Wv, bv);
    k3<<<1184, 256>>>(W1, Wv);
    k4<<<1, 64>>>(g1, be1, gv, bev);
    k5<<<1184, 256>>>(W1, Wv, W2, b2, Wo, bo);
    k6<<<1, 64>>>(go, beo);
    k7<<<NPTS / 32, 256>>>(feats, out);
}

// round 5
// speedup vs baseline: 3.2866x; 1.0880x over previous
#include <cuda_runtime.h>
#include <cfloat>
#include <math.h>

#define BB 4
#define NN 8192
#define CC 64
#define KK 16
#define HH 64
#define NPTS (BB*NN)

// ---------------- device scratch ------------------------------------------------
__device__ float4 g_P4[NPTS];                    // (x,y,z,|p|^2)
__device__ float  g_Sx[NPTS], g_Sy[NPTS], g_Sz[NPTS], g_Sq[NPTS];  // SoA coords
__device__ float  g_PT[(size_t)NPTS*192];        // [hc+b1 (64) | hn (64) | vn+bv (64)]
__device__ int    g_NB[NPTS*KK];                 // knn indices
__device__ float  g_stats[256];
__device__ float  g_coef1[256];
__device__ float  g_ostats[128];
__device__ float  g_ocoef[128];
__device__ float  g_Opre[(size_t)NPTS*64];

// ---------------- f32x2 helpers -------------------------------------------------
typedef unsigned long long u64;
__device__ __forceinline__ u64 fma2(u64 a, u64 b, u64 c) {
    u64 d; asm("fma.rn.f32x2 %0,%1,%2,%3;" : "=l"(d) : "l"(a), "l"(b), "l"(c));
    return d;
}
__device__ __forceinline__ u64 add2(u64 a, u64 b) {
    u64 d; asm("add.rn.f32x2 %0,%1,%2;" : "=l"(d) : "l"(a), "l"(b));
    return d;
}
__device__ __forceinline__ u64 pk2(float v) {
    u64 d; asm("mov.b64 %0,{%1,%1};" : "=l"(d) : "f"(v));
    return d;
}
__device__ __forceinline__ u64 pkab(float a, float b) {
    u64 d; asm("mov.b64 %0,{%1,%2};" : "=l"(d) : "f"(a), "f"(b));
    return d;
}
__device__ __forceinline__ float2 unpk(u64 v) {
    float2 r; asm("mov.b64 {%0,%1},%2;" : "=f"(r.x), "=f"(r.y) : "l"(v));
    return r;
}

// ---------------- k0: pack xyz (AoS + SoA) + zero stats -------------------------
__global__ void k0(const float* __restrict__ xyz) {
    int p = blockIdx.x * blockDim.x + threadIdx.x;
    if (p < 256) g_stats[p] = 0.f;
    if (p < 128) g_ostats[p] = 0.f;
    if (p >= NPTS) return;
    int b = p >> 13, n = p & (NN - 1);
    const float* base = xyz + (size_t)b * 3 * NN + n;
    float x = base[0], y = base[NN], z = base[2 * NN];
    float w = x * x + y * y + z * z;
    g_P4[p] = make_float4(x, y, z, w);
    g_Sx[p] = x; g_Sy[p] = y; g_Sz[p] = z; g_Sq[p] = w;
}

// ---------------- k1: KNN, 2 warps split the candidate range --------------------
// block = 64 threads = 2 warps; both warps own the same 32 queries.
// warp w scans candidates [w*4096, (w+1)*4096); warp 0 merges at the end.
#define TSH 512
__global__ void __launch_bounds__(64) k1() {
    __shared__ __align__(16) float sX[2][TSH];
    __shared__ __align__(16) float sY[2][TSH];
    __shared__ __align__(16) float sZ[2][TSH];
    __shared__ __align__(16) float sWW[2][TSH];
    __shared__ unsigned sVal[2 * 32 * 16];   // [warp][lane][slot]
    __shared__ int      sIdx[2 * 32 * 16];

    int lane = threadIdx.x & 31;
    int wid  = threadIdx.x >> 5;
    int blk  = blockIdx.x;                // 1024 blocks
    int b    = blk >> 8;                  // 256 blocks per batch
    int n    = ((blk & 255) << 5) + lane;
    int p    = b * NN + n;

    float4 q = g_P4[p];
    float m2xf = -2.f * q.x, m2yf = -2.f * q.y, m2zf = -2.f * q.z, qw = q.w;
    u64 m2x = pk2(m2xf), m2y = pk2(m2yf), m2z = pk2(m2zf);

    int vbase = wid * 512 + lane * 16;
#pragma unroll
    for (int s = 0; s < 16; s++) {
        sVal[vbase + s] = 0x7F7FFFF0u | (unsigned)s;
        sIdx[vbase + s] = 0;
    }
    unsigned worstP = 0x7F7FFFFFu;
    float thr = __uint_as_float(0x7F7FFFF0u) - qw;   // huge, t-domain

    int cbase = wid * 4096;
    for (int t0 = 0; t0 < 4096; t0 += TSH) {
        __syncwarp();
        const float* bx = g_Sx + b * NN + cbase + t0;
        const float* by = g_Sy + b * NN + cbase + t0;
        const float* bz = g_Sz + b * NN + cbase + t0;
        const float* bw = g_Sq + b * NN + cbase + t0;
#pragma unroll
        for (int i = 0; i < TSH / 128; i++) {
            int o = i * 128 + lane * 4;
            *(float4*)(sX[wid]  + o) = *(const float4*)(bx + o);
            *(float4*)(sY[wid]  + o) = *(const float4*)(by + o);
            *(float4*)(sZ[wid]  + o) = *(const float4*)(bz + o);
            *(float4*)(sWW[wid] + o) = *(const float4*)(bw + o);
        }
        __syncwarp();

        for (int j = 0; j < TSH; j += 8) {
            ulonglong2 X0 = *(const ulonglong2*)(sX[wid]  + j);
            ulonglong2 Y0 = *(const ulonglong2*)(sY[wid]  + j);
            ulonglong2 Z0 = *(const ulonglong2*)(sZ[wid]  + j);
            ulonglong2 W0 = *(const ulonglong2*)(sWW[wid] + j);
            ulonglong2 X1 = *(const ulonglong2*)(sX[wid]  + j + 4);
            ulonglong2 Y1 = *(const ulonglong2*)(sY[wid]  + j + 4);
            ulonglong2 Z1 = *(const ulonglong2*)(sZ[wid]  + j + 4);
            ulonglong2 W1 = *(const ulonglong2*)(sWW[wid] + j + 4);
            u64 t0a = fma2(Z0.x, m2z, fma2(Y0.x, m2y, fma2(X0.x, m2x, W0.x)));
            u64 t0b = fma2(Z0.y, m2z, fma2(Y0.y, m2y, fma2(X0.y, m2x, W0.y)));
            u64 t1a = fma2(Z1.x, m2z, fma2(Y1.x, m2y, fma2(X1.x, m2x, W1.x)));
            u64 t1b = fma2(Z1.y, m2z, fma2(Y1.y, m2y, fma2(X1.y, m2x, W1.y)));
            float2 f01 = unpk(t0a), f23 = unpk(t0b), f45 = unpk(t1a), f67 = unpk(t1b);
            float m01 = fminf(f01.x, f01.y), m23 = fminf(f23.x, f23.y);
            float m45 = fminf(f45.x, f45.y), m67 = fminf(f67.x, f67.y);
            float mm = fminf(fminf(m01, m23), fminf(m45, m67));
            if (mm < thr) {
                float tt[8] = {f01.x, f01.y, f23.x, f23.y, f45.x, f45.y, f67.x, f67.y};
#pragma unroll
                for (int uu = 0; uu < 8; uu++) {
                    if (tt[uu] < thr) {
                        float ts = fmaxf(tt[uu] + qw, 0.f);
                        unsigned slot = worstP & 0xFu;
                        sVal[vbase + slot] = (__float_as_uint(ts) & 0xFFFFFFF0u) | slot;
                        sIdx[vbase + slot] = cbase + t0 + j + uu;
                        unsigned mmax = 0u;
                        const uint4* vp = (const uint4*)(sVal + vbase);
#pragma unroll
                        for (int s4 = 0; s4 < 4; s4++) {
                            uint4 v = vp[s4];
                            mmax = max(mmax, max(max(v.x, v.y), max(v.z, v.w)));
                        }
                        worstP = mmax;
                        thr = __uint_as_float(mmax & 0xFFFFFFF0u) - qw;
                    }
                }
            }
        }
    }

    __syncthreads();
    if (wid == 0) {
        int pbase = 512 + lane * 16;
        float thrts = __uint_as_float(worstP & 0xFFFFFFF0u);
#pragma unroll
        for (int s = 0; s < 16; s++) {
            unsigned pv = sVal[pbase + s];
            float pvts = __uint_as_float(pv & 0xFFFFFFF0u);
            if (pvts < thrts) {
                unsigned slot = worstP & 0xFu;
                sVal[vbase + slot] = (pv & 0xFFFFFFF0u) | slot;
                sIdx[vbase + slot] = sIdx[pbase + s];
                unsigned mmax = 0u;
                const uint4* vp = (const uint4*)(sVal + vbase);
#pragma unroll
                for (int s4 = 0; s4 < 4; s4++) {
                    uint4 v = vp[s4];
                    mmax = max(mmax, max(max(v.x, v.y), max(v.z, v.w)));
                }
                worstP = mmax;
                thrts = __uint_as_float(mmax & 0xFFFFFFF0u);
            }
        }
#pragma unroll
        for (int s = 0; s < 16; s++) g_NB[p * KK + s] = sIdx[vbase + s];
    }
}

// ---------------- k2: per-point transforms, 3 passes of 64 outs -----------------
__global__ void __launch_bounds__(256) k2(const float* __restrict__ feats,
                   const float* __restrict__ W1, const float* __restrict__ b1,
                   const float* __restrict__ Wv, const float* __restrict__ bv) {
    __shared__ float sW[64][64];
    __shared__ float sF[64][64];
    int tid = threadIdx.x;
    int blk = blockIdx.x;
    int b   = blk >> 7;
    int n0  = (blk & 127) << 6;

    for (int e = tid; e < 1024; e += 256) {
        int c = e >> 4, v4 = e & 15;
        ((float4*)sF[c])[v4] =
            ((const float4*)(feats + (size_t)b * CC * NN + (size_t)c * NN + n0))[v4];
    }

    int og = tid & 15, ng = tid >> 4;

    for (int pp = 0; pp < 3; pp++) {
        __syncthreads();
        for (int e = tid; e < 4096; e += 256) {
            int ol = e & 63, c = e >> 6;
            float w;
            if (pp == 0)      w = W1[ol * 131 + c];
            else if (pp == 1) w = W1[ol * 131 + 64 + c];
            else              w = Wv[ol * 67 + c];
            sW[c][ol] = w;
        }
        __syncthreads();

        float4 a0 = make_float4(0.f,0.f,0.f,0.f), a1 = a0, a2 = a0, a3 = a0;
        for (int c = 0; c < 64; c++) {
            float4 w4 = *(const float4*)&sW[c][og * 4];
            float4 f4 = *(const float4*)&sF[c][ng * 4];
            a0.x = fmaf(w4.x, f4.x, a0.x); a0.y = fmaf(w4.y, f4.x, a0.y);
            a0.z = fmaf(w4.z, f4.x, a0.z); a0.w = fmaf(w4.w, f4.x, a0.w);
            a1.x = fmaf(w4.x, f4.y, a1.x); a1.y = fmaf(w4.y, f4.y, a1.y);
            a1.z = fmaf(w4.z, f4.y, a1.z); a1.w = fmaf(w4.w, f4.y, a1.w);
            a2.x = fmaf(w4.x, f4.z, a2.x); a2.y = fmaf(w4.y, f4.z, a2.y);
            a2.z = fmaf(w4.z, f4.z, a2.z); a2.w = fmaf(w4.w, f4.z, a2.w);
            a3.x = fmaf(w4.x, f4.w, a3.x); a3.y = fmaf(w4.y, f4.w, a3.y);
            a3.z = fmaf(w4.z, f4.w, a3.z); a3.w = fmaf(w4.w, f4.w, a3.w);
        }

        float4 bb = make_float4(0.f, 0.f, 0.f, 0.f);
        if (pp == 0) bb = *(const float4*)(b1 + og * 4);
        if (pp == 2) bb = *(const float4*)(bv + og * 4);
        int obase = pp * 64 + og * 4;
        float4 r;
        size_t pbase = (size_t)(b * NN + n0 + ng * 4);
        r = make_float4(a0.x+bb.x, a0.y+bb.y, a0.z+bb.z, a0.w+bb.w);
        *(float4*)(g_PT + (pbase + 0) * 192 + obase) = r;
        r = make_float4(a1.x+bb.x, a1.y+bb.y, a1.z+bb.z, a1.w+bb.w);
        *(float4*)(g_PT + (pbase + 1) * 192 + obase) = r;
        r = make_float4(a2.x+bb.x, a2.y+bb.y, a2.z+bb.z, a2.w+bb.w);
        *(float4*)(g_PT + (pbase + 2) * 192 + obase) = r;
        r = make_float4(a3.x+bb.x, a3.y+bb.y, a3.z+bb.z, a3.w+bb.w);
        *(float4*)(g_PT + (pbase + 3) * 192 + obase) = r;
    }
}

// ---------------- k3: BN stats for h and v (f32x2, channel pairs) ---------------
__global__ void __launch_bounds__(256) k3(const float* __restrict__ W1,
                                          const float* __restrict__ Wv) {
    __shared__ float sstat[256];
    int tid = threadIdx.x, lane = tid & 31, wid = tid >> 5;
    for (int e = tid; e < 256; e += 256) sstat[e] = 0.f;
    __syncthreads();

    int cc = lane * 2;   // channels cc, cc+1
    u64 w1x0 = pkab(W1[cc * 131 + 128], W1[(cc + 1) * 131 + 128]);
    u64 w1x1 = pkab(W1[cc * 131 + 129], W1[(cc + 1) * 131 + 129]);
    u64 w1x2 = pkab(W1[cc * 131 + 130], W1[(cc + 1) * 131 + 130]);
    u64 wvx0 = pkab(Wv[cc * 67 + 64],  Wv[(cc + 1) * 67 + 64]);
    u64 wvx1 = pkab(Wv[cc * 67 + 65],  Wv[(cc + 1) * 67 + 65]);
    u64 wvx2 = pkab(Wv[cc * 67 + 66],  Wv[(cc + 1) * 67 + 66]);

    u64 sh = 0, shq = 0, sv = 0, svq = 0;
    int gw = blockIdx.x * 8 + wid, nw = gridDim.x * 8;
    for (int p = gw; p < NPTS; p += nw) {
        int b = p >> 13;
        float4 q = g_P4[p];
        const int4* nb = (const int4*)(g_NB + p * KK);
        int4 iA = nb[0], iB = nb[1], iC = nb[2], iD = nb[3];
        int mi[16] = {iA.x, iA.y, iA.z, iA.w, iB.x, iB.y, iB.z, iB.w,
                      iC.x, iC.y, iC.z, iC.w, iD.x, iD.y, iD.z, iD.w};
        const float* ptp = g_PT + (size_t)p * 192;
        u64 hcp = *(const u64*)(ptp + cc);
#pragma unroll
        for (int k = 0; k < KK; k++) {
            int m = mi[k];
            float4 pm = g_P4[b * NN + m];
            u64 rxp = pk2(pm.x - q.x), ryp = pk2(pm.y - q.y), rzp = pk2(pm.z - q.z);
            const float* ptm = g_PT + (size_t)(b * NN + m) * 192;
            u64 hnp = *(const u64*)(ptm + 64 + cc);
            u64 vnp = *(const u64*)(ptm + 128 + cc);
            u64 h = fma2(rzp, w1x2, fma2(ryp, w1x1, fma2(rxp, w1x0, add2(hcp, hnp))));
            u64 v = fma2(rzp, wvx2, fma2(ryp, wvx1, fma2(rxp, wvx0, vnp)));
            sh = add2(sh, h); shq = fma2(h, h, shq);
            sv = add2(sv, v); svq = fma2(v, v, svq);
        }
    }
    float2 fsh = unpk(sh), fshq = unpk(shq), fsv = unpk(sv), fsvq = unpk(svq);
    atomicAdd(&sstat[cc], fsh.x);       atomicAdd(&sstat[cc + 1], fsh.y);
    atomicAdd(&sstat[64 + cc], fshq.x); atomicAdd(&sstat[64 + cc + 1], fshq.y);
    atomicAdd(&sstat[128 + cc], fsv.x); atomicAdd(&sstat[128 + cc + 1], fsv.y);
    atomicAdd(&sstat[192 + cc], fsvq.x);atomicAdd(&sstat[192 + cc + 1], fsvq.y);
    __syncthreads();
    for (int e = tid; e < 256; e += 256) atomicAdd(&g_stats[e], sstat[e]);
}

// ---------------- k4: stats -> BN coefficients ----------------------------------
__global__ void k4(const float* __restrict__ g1, const float* __restrict__ be1,
                   const float* __restrict__ gv, const float* __restrict__ bev) {
    int c = threadIdx.x;
    float cnt = (float)((size_t)NPTS * KK);
    float mh = g_stats[c] / cnt;
    float vh = g_stats[64 + c] / cnt - mh * mh;
    float a1 = g1[c] * rsqrtf(vh + 1e-5f);
    g_coef1[c] = a1; g_coef1[64 + c] = be1[c] - a1 * mh;
    float mv = g_stats[128 + c] / cnt;
    float vv = g_stats[192 + c] / cnt - mv * mv;
    float av = gv[c] * rsqrtf(vv + 1e-5f);
    g_coef1[128 + c] = av; g_coef1[192 + c] = bev[c] - av * mv;
}

// ---------------- k5: attention + value + weighted sum + out-conv ---------------
__global__ void __launch_bounds__(256) k5(const float* __restrict__ W1,
                   const float* __restrict__ Wv,
                   const float* __restrict__ W2, const float* __restrict__ b2,
                   const float* __restrict__ Wo, const float* __restrict__ bo) {
    __shared__ float sWo[64][65];
    __shared__ float sOut[8][64];
    __shared__ float sstat[128];
    int tid = threadIdx.x, lane = tid & 31, wid = tid >> 5;

    for (int e = tid; e < 64 * 64; e += 256) {
        int j = e >> 6, c = e & 63;
        sWo[j][c] = Wo[c * 64 + j];
    }
    for (int e = tid; e < 128; e += 256) sstat[e] = 0.f;

    int cc = lane * 2;
    u64 w1x0 = pkab(W1[cc * 131 + 128], W1[(cc + 1) * 131 + 128]);
    u64 w1x1 = pkab(W1[cc * 131 + 129], W1[(cc + 1) * 131 + 129]);
    u64 w1x2 = pkab(W1[cc * 131 + 130], W1[(cc + 1) * 131 + 130]);
    u64 wvx0 = pkab(Wv[cc * 67 + 64],  Wv[(cc + 1) * 67 + 64]);
    u64 wvx1 = pkab(Wv[cc * 67 + 65],  Wv[(cc + 1) * 67 + 65]);
    u64 wvx2 = pkab(Wv[cc * 67 + 66],  Wv[(cc + 1) * 67 + 66]);
    float a1a = g_coef1[cc],      a1b = g_coef1[cc + 1];
    float d1a = g_coef1[64 + cc], d1b = g_coef1[64 + cc + 1];
    float ava = g_coef1[128 + cc], avb = g_coef1[128 + cc + 1];
    float dva = g_coef1[192 + cc], dvb = g_coef1[192 + cc + 1];
    float w2a = W2[cc], w2b = W2[cc + 1];
    float b2v = b2[0];
    float boa = bo[cc], bob = bo[cc + 1];
    __syncthreads();

    float so1 = 0.f, so1q = 0.f, so2 = 0.f, so2q = 0.f;
    int gw = blockIdx.x * 8 + wid, nw = gridDim.x * 8;

    for (int p = gw; p < NPTS; p += nw) {
        int b = p >> 13;
        float4 q = g_P4[p];
        const int4* nb = (const int4*)(g_NB + p * KK);
        int4 iA = nb[0], iB = nb[1], iC = nb[2], iD = nb[3];
        int mi[16] = {iA.x, iA.y, iA.z, iA.w, iB.x, iB.y, iB.z, iB.w,
                      iC.x, iC.y, iC.z, iC.w, iD.x, iD.y, iD.z, iD.w};
        const float* ptp = g_PT + (size_t)p * 192;
        u64 hcp = *(const u64*)(ptp + cc);

        float logits[KK], vv1[KK], vv2[KK];
#pragma unroll
        for (int k = 0; k < KK; k++) {
            int m = mi[k];
            float4 pm = g_P4[b * NN + m];
            u64 rxp = pk2(pm.x - q.x), ryp = pk2(pm.y - q.y), rzp = pk2(pm.z - q.z);
            const float* ptm = g_PT + (size_t)(b * NN + m) * 192;
            u64 hnp = *(const u64*)(ptm + 64 + cc);
            u64 vnp = *(const u64*)(ptm + 128 + cc);
            u64 h = fma2(rzp, w1x2, fma2(ryp, w1x1, fma2(rxp, w1x0, add2(hcp, hnp))));
            u64 v = fma2(rzp, wvx2, fma2(ryp, wvx1, fma2(rxp, wvx0, vnp)));
            float2 hf = unpk(h), vf = unpk(v);
            float hb1 = fmaxf(a1a * hf.x + d1a, 0.f);
            float hb2 = fmaxf(a1b * hf.y + d1b, 0.f);
            vv1[k] = fmaxf(ava * vf.x + dva, 0.f);
            vv2[k] = fmaxf(avb * vf.y + dvb, 0.f);
            float t = hb1 * w2a + hb2 * w2b;
#pragma unroll
            for (int off = 16; off > 0; off >>= 1) t += __shfl_xor_sync(0xffffffffu, t, off);
            logits[k] = t + b2v;
        }
        float mx = logits[0];
#pragma unroll
        for (int k = 1; k < KK; k++) mx = fmaxf(mx, logits[k]);
        float ex[KK], se = 0.f;
#pragma unroll
        for (int k = 0; k < KK; k++) { ex[k] = __expf(logits[k] - mx); se += ex[k]; }
        float inv = 1.0f / se;
        float out1 = 0.f, out2 = 0.f;
#pragma unroll
        for (int k = 0; k < KK; k++) {
            float w = ex[k] * inv;
            out1 += w * vv1[k];
            out2 += w * vv2[k];
        }
        __syncwarp();
        sOut[wid][cc] = out1; sOut[wid][cc + 1] = out2;
        __syncwarp();
        float oo1 = boa, oo2 = bob;
#pragma unroll 8
        for (int j = 0; j < 64; j++) {
            float oj = sOut[wid][j];
            oo1 = fmaf(sWo[j][cc], oj, oo1);
            oo2 = fmaf(sWo[j][cc + 1], oj, oo2);
        }
        g_Opre[(size_t)p * 64 + cc] = oo1;
        g_Opre[(size_t)p * 64 + cc + 1] = oo2;
        so1 += oo1; so1q += oo1 * oo1;
        so2 += oo2; so2q += oo2 * oo2;
    }
    atomicAdd(&sstat[cc], so1);     atomicAdd(&sstat[64 + cc], so1q);
    atomicAdd(&sstat[cc + 1], so2); atomicAdd(&sstat[64 + cc + 1], so2q);
    __syncthreads();
    for (int e = tid; e < 128; e += 256) atomicAdd(&g_ostats[e], sstat[e]);
}

// ---------------- k6 ------------------------------------------------------------
__global__ void k6(const float* __restrict__ go, const float* __restrict__ beo) {
    int c = threadIdx.x;
    float cnt = (float)NPTS;
    float m = g_ostats[c] / cnt;
    float v = g_ostats[64 + c] / cnt - m * m;
    float a = go[c] * rsqrtf(v + 1e-5f);
    g_ocoef[c] = a; g_ocoef[64 + c] = beo[c] - a * m;
}

// ---------------- k7: BN + relu + residual + transpose --------------------------
__global__ void k7(const float* __restrict__ feats, float* __restrict__ out) {
    __shared__ float tile[32][65];
    int blk = blockIdx.x;
    int b = blk >> 8;
    int n0 = (blk & 255) << 5;
    int tid = threadIdx.x;
    for (int e = tid; e < 32 * 64; e += 256) {
        int pp = e >> 6, c = e & 63;
        tile[pp][c] = g_Opre[(size_t)(b * NN + n0 + pp) * 64 + c];
    }
    __syncthreads();
    for (int e = tid; e < 64 * 32; e += 256) {
        int c = e >> 5, j = e & 31;
        float val = g_ocoef[c] * tile[j][c] + g_ocoef[64 + c];
        val = fmaxf(val, 0.f) + feats[(size_t)b * CC * NN + (size_t)c * NN + n0 + j];
        out[(size_t)b * CC * NN + (size_t)c * NN + n0 + j] = val;
    }
}

// ---------------- launch --------------------------------------------------------
extern "C" void kernel_launch(void* const* d_in, const int* in_sizes, int n_in,
                              void* d_out, int out_size) {
    const float* xyz   = (const float*)d_in[0];
    const float* feats = (const float*)d_in[1];
    const float* W1    = (const float*)d_in[2];
    const float* b1    = (const float*)d_in[3];
    const float* g1    = (const float*)d_in[4];
    const float* be1   = (const float*)d_in[5];
    const float* W2    = (const float*)d_in[6];
    const float* b2    = (const float*)d_in[7];
    const float* Wv    = (const float*)d_in[8];
    const float* bv    = (const float*)d_in[9];
    const float* gv    = (const float*)d_in[10];
    const float* bev   = (const float*)d_in[11];
    const float* Wo    = (const float*)d_in[12];
    const float* bo    = (const float*)d_in[13];
    const float* go    = (const float*)d_in[14];
    const float* beo   = (const float*)d_in[15];
    float* out = (float*)d_out;

    k0<<<NPTS / 256, 256>>>(xyz);
    k1<<<NPTS / 32, 64>>>();
    k2<<<NPTS / 64, 256>>>(feats, W1, b1, Wv, bv);
    k3<<<1184, 256>>>(W1, Wv);
    k4<<<1, 64>>>(g1, be1, gv, bev);
    k5<<<1184, 256>>>(W1, Wv, W2, b2, Wo, bo);
    k6<<<1, 64>>>(go, beo);
    k7<<<NPTS / 32, 256>>>(feats, out);
}

// round 6
// speedup vs baseline: 3.2902x; 1.0011x over previous
#include <cuda_runtime.h>
#include <cfloat>
#include <math.h>

#define BB 4
#define NN 8192
#define CC 64
#define KK 16
#define HH 64
#define NPTS (BB*NN)

// ---------------- device scratch ------------------------------------------------
__device__ float4 g_P4[NPTS];                    // (x,y,z,|p|^2)
__device__ float  g_Sx[NPTS], g_Sy[NPTS], g_Sz[NPTS], g_Sq[NPTS];  // SoA coords
__device__ float  g_PT[(size_t)NPTS*192];        // [hc+b1 (64) | hn (64) | vn+bv (64)]
__device__ int    g_NB[NPTS*KK];                 // knn indices
__device__ float  g_stats[256];
__device__ float  g_coef1[256];
__device__ float  g_ostats[128];
__device__ float  g_ocoef[128];
__device__ float  g_Opre[(size_t)NPTS*64];

// ---------------- f32x2 helpers -------------------------------------------------
typedef unsigned long long u64;
__device__ __forceinline__ u64 fma2(u64 a, u64 b, u64 c) {
    u64 d; asm("fma.rn.f32x2 %0,%1,%2,%3;" : "=l"(d) : "l"(a), "l"(b), "l"(c));
    return d;
}
__device__ __forceinline__ u64 add2(u64 a, u64 b) {
    u64 d; asm("add.rn.f32x2 %0,%1,%2;" : "=l"(d) : "l"(a), "l"(b));
    return d;
}
__device__ __forceinline__ u64 pk2(float v) {
    u64 d; asm("mov.b64 %0,{%1,%1};" : "=l"(d) : "f"(v));
    return d;
}
__device__ __forceinline__ u64 pkab(float a, float b) {
    u64 d; asm("mov.b64 %0,{%1,%2};" : "=l"(d) : "f"(a), "f"(b));
    return d;
}
__device__ __forceinline__ float2 unpk(u64 v) {
    float2 r; asm("mov.b64 {%0,%1},%2;" : "=f"(r.x), "=f"(r.y) : "l"(v));
    return r;
}

// ---------------- k0: pack xyz (AoS + SoA) + zero stats -------------------------
__global__ void k0(const float* __restrict__ xyz) {
    int p = blockIdx.x * blockDim.x + threadIdx.x;
    if (p < 256) g_stats[p] = 0.f;
    if (p < 128) g_ostats[p] = 0.f;
    if (p >= NPTS) return;
    int b = p >> 13, n = p & (NN - 1);
    const float* base = xyz + (size_t)b * 3 * NN + n;
    float x = base[0], y = base[NN], z = base[2 * NN];
    float w = x * x + y * y + z * z;
    g_P4[p] = make_float4(x, y, z, w);
    g_Sx[p] = x; g_Sy[p] = y; g_Sz[p] = z; g_Sq[p] = w;
}

// ---------------- k1: KNN, 2 warps split the candidate range --------------------
// block = 64 threads = 2 warps; both warps own the same 32 queries.
// warp w scans candidates [w*4096, (w+1)*4096); warp 0 merges at the end.
#define TSH 512
__global__ void __launch_bounds__(64) k1() {
    __shared__ __align__(16) float sX[2][TSH];
    __shared__ __align__(16) float sY[2][TSH];
    __shared__ __align__(16) float sZ[2][TSH];
    __shared__ __align__(16) float sWW[2][TSH];
    __shared__ unsigned sVal[2 * 32 * 16];   // [warp][lane][slot]
    __shared__ int      sIdx[2 * 32 * 16];

    int lane = threadIdx.x & 31;
    int wid  = threadIdx.x >> 5;
    int blk  = blockIdx.x;                // 1024 blocks
    int b    = blk >> 8;                  // 256 blocks per batch
    int n    = ((blk & 255) << 5) + lane;
    int p    = b * NN + n;

    float4 q = g_P4[p];
    float m2xf = -2.f * q.x, m2yf = -2.f * q.y, m2zf = -2.f * q.z, qw = q.w;
    u64 m2x = pk2(m2xf), m2y = pk2(m2yf), m2z = pk2(m2zf);

    int vbase = wid * 512 + lane * 16;
#pragma unroll
    for (int s = 0; s < 16; s++) {
        sVal[vbase + s] = 0x7F7FFFF0u | (unsigned)s;
        sIdx[vbase + s] = 0;
    }
    unsigned worstP = 0x7F7FFFFFu;
    float thr = __uint_as_float(0x7F7FFFF0u) - qw;   // huge, t-domain

    int cbase = wid * 4096;
    for (int t0 = 0; t0 < 4096; t0 += TSH) {
        __syncwarp();
        const float* bx = g_Sx + b * NN + cbase + t0;
        const float* by = g_Sy + b * NN + cbase + t0;
        const float* bz = g_Sz + b * NN + cbase + t0;
        const float* bw = g_Sq + b * NN + cbase + t0;
#pragma unroll
        for (int i = 0; i < TSH / 128; i++) {
            int o = i * 128 + lane * 4;
            *(float4*)(sX[wid]  + o) = *(const float4*)(bx + o);
            *(float4*)(sY[wid]  + o) = *(const float4*)(by + o);
            *(float4*)(sZ[wid]  + o) = *(const float4*)(bz + o);
            *(float4*)(sWW[wid] + o) = *(const float4*)(bw + o);
        }
        __syncwarp();

        for (int j = 0; j < TSH; j += 8) {
            ulonglong2 X0 = *(const ulonglong2*)(sX[wid]  + j);
            ulonglong2 Y0 = *(const ulonglong2*)(sY[wid]  + j);
            ulonglong2 Z0 = *(const ulonglong2*)(sZ[wid]  + j);
            ulonglong2 W0 = *(const ulonglong2*)(sWW[wid] + j);
            ulonglong2 X1 = *(const ulonglong2*)(sX[wid]  + j + 4);
            ulonglong2 Y1 = *(const ulonglong2*)(sY[wid]  + j + 4);
            ulonglong2 Z1 = *(const ulonglong2*)(sZ[wid]  + j + 4);
            ulonglong2 W1 = *(const ulonglong2*)(sWW[wid] + j + 4);
            u64 t0a = fma2(Z0.x, m2z, fma2(Y0.x, m2y, fma2(X0.x, m2x, W0.x)));
            u64 t0b = fma2(Z0.y, m2z, fma2(Y0.y, m2y, fma2(X0.y, m2x, W0.y)));
            u64 t1a = fma2(Z1.x, m2z, fma2(Y1.x, m2y, fma2(X1.x, m2x, W1.x)));
            u64 t1b = fma2(Z1.y, m2z, fma2(Y1.y, m2y, fma2(X1.y, m2x, W1.y)));
            float2 f01 = unpk(t0a), f23 = unpk(t0b), f45 = unpk(t1a), f67 = unpk(t1b);
            float m01 = fminf(f01.x, f01.y), m23 = fminf(f23.x, f23.y);
            float m45 = fminf(f45.x, f45.y), m67 = fminf(f67.x, f67.y);
            float mm = fminf(fminf(m01, m23), fminf(m45, m67));
            if (mm < thr) {
                float tt[8] = {f01.x, f01.y, f23.x, f23.y, f45.x, f45.y, f67.x, f67.y};
#pragma unroll
                for (int uu = 0; uu < 8; uu++) {
                    if (tt[uu] < thr) {
                        float ts = fmaxf(tt[uu] + qw, 0.f);
                        unsigned slot = worstP & 0xFu;
                        sVal[vbase + slot] = (__float_as_uint(ts) & 0xFFFFFFF0u) | slot;
                        sIdx[vbase + slot] = cbase + t0 + j + uu;
                        unsigned mmax = 0u;
                        const uint4* vp = (const uint4*)(sVal + vbase);
#pragma unroll
                        for (int s4 = 0; s4 < 4; s4++) {
                            uint4 v = vp[s4];
                            mmax = max(mmax, max(max(v.x, v.y), max(v.z, v.w)));
                        }
                        worstP = mmax;
                        thr = __uint_as_float(mmax & 0xFFFFFFF0u) - qw;
                    }
                }
            }
        }
    }

    __syncthreads();
    if (wid == 0) {
        int pbase = 512 + lane * 16;
        float thrts = __uint_as_float(worstP & 0xFFFFFFF0u);
#pragma unroll
        for (int s = 0; s < 16; s++) {
            unsigned pv = sVal[pbase + s];
            float pvts = __uint_as_float(pv & 0xFFFFFFF0u);
            if (pvts < thrts) {
                unsigned slot = worstP & 0xFu;
                sVal[vbase + slot] = (pv & 0xFFFFFFF0u) | slot;
                sIdx[vbase + slot] = sIdx[pbase + s];
                unsigned mmax = 0u;
                const uint4* vp = (const uint4*)(sVal + vbase);
#pragma unroll
                for (int s4 = 0; s4 < 4; s4++) {
                    uint4 v = vp[s4];
                    mmax = max(mmax, max(max(v.x, v.y), max(v.z, v.w)));
                }
                worstP = mmax;
                thrts = __uint_as_float(mmax & 0xFFFFFFF0u);
            }
        }
#pragma unroll
        for (int s = 0; s < 16; s++) g_NB[p * KK + s] = sIdx[vbase + s];
    }
}

// ---------------- k2: per-point transforms, 3 passes of 64 outs -----------------
__global__ void __launch_bounds__(256) k2(const float* __restrict__ feats,
                   const float* __restrict__ W1, const float* __restrict__ b1,
                   const float* __restrict__ Wv, const float* __restrict__ bv) {
    __shared__ float sW[64][64];
    __shared__ float sF[64][64];
    int tid = threadIdx.x;
    int blk = blockIdx.x;
    int b   = blk >> 7;
    int n0  = (blk & 127) << 6;

    for (int e = tid; e < 1024; e += 256) {
        int c = e >> 4, v4 = e & 15;
        ((float4*)sF[c])[v4] =
            ((const float4*)(feats + (size_t)b * CC * NN + (size_t)c * NN + n0))[v4];
    }

    int og = tid & 15, ng = tid >> 4;

    for (int pp = 0; pp < 3; pp++) {
        __syncthreads();
        for (int e = tid; e < 4096; e += 256) {
            int ol = e & 63, c = e >> 6;
            float w;
            if (pp == 0)      w = W1[ol * 131 + c];
            else if (pp == 1) w = W1[ol * 131 + 64 + c];
            else              w = Wv[ol * 67 + c];
            sW[c][ol] = w;
        }
        __syncthreads();

        float4 a0 = make_float4(0.f,0.f,0.f,0.f), a1 = a0, a2 = a0, a3 = a0;
        for (int c = 0; c < 64; c++) {
            float4 w4 = *(const float4*)&sW[c][og * 4];
            float4 f4 = *(const float4*)&sF[c][ng * 4];
            a0.x = fmaf(w4.x, f4.x, a0.x); a0.y = fmaf(w4.y, f4.x, a0.y);
            a0.z = fmaf(w4.z, f4.x, a0.z); a0.w = fmaf(w4.w, f4.x, a0.w);
            a1.x = fmaf(w4.x, f4.y, a1.x); a1.y = fmaf(w4.y, f4.y, a1.y);
            a1.z = fmaf(w4.z, f4.y, a1.z); a1.w = fmaf(w4.w, f4.y, a1.w);
            a2.x = fmaf(w4.x, f4.z, a2.x); a2.y = fmaf(w4.y, f4.z, a2.y);
            a2.z = fmaf(w4.z, f4.z, a2.z); a2.w = fmaf(w4.w, f4.z, a2.w);
            a3.x = fmaf(w4.x, f4.w, a3.x); a3.y = fmaf(w4.y, f4.w, a3.y);
            a3.z = fmaf(w4.z, f4.w, a3.z); a3.w = fmaf(w4.w, f4.w, a3.w);
        }

        float4 bb = make_float4(0.f, 0.f, 0.f, 0.f);
        if (pp == 0) bb = *(const float4*)(b1 + og * 4);
        if (pp == 2) bb = *(const float4*)(bv + og * 4);
        int obase = pp * 64 + og * 4;
        float4 r;
        size_t pbase = (size_t)(b * NN + n0 + ng * 4);
        r = make_float4(a0.x+bb.x, a0.y+bb.y, a0.z+bb.z, a0.w+bb.w);
        *(float4*)(g_PT + (pbase + 0) * 192 + obase) = r;
        r = make_float4(a1.x+bb.x, a1.y+bb.y, a1.z+bb.z, a1.w+bb.w);
        *(float4*)(g_PT + (pbase + 1) * 192 + obase) = r;
        r = make_float4(a2.x+bb.x, a2.y+bb.y, a2.z+bb.z, a2.w+bb.w);
        *(float4*)(g_PT + (pbase + 2) * 192 + obase) = r;
        r = make_float4(a3.x+bb.x, a3.y+bb.y, a3.z+bb.z, a3.w+bb.w);
        *(float4*)(g_PT + (pbase + 3) * 192 + obase) = r;
    }
}

// ---------------- k3: BN stats for h and v (f32x2, channel pairs) ---------------
__global__ void __launch_bounds__(256) k3(const float* __restrict__ W1,
                                          const float* __restrict__ Wv) {
    __shared__ float sstat[256];
    int tid = threadIdx.x, lane = tid & 31, wid = tid >> 5;
    for (int e = tid; e < 256; e += 256) sstat[e] = 0.f;
    __syncthreads();

    int cc = lane * 2;   // channels cc, cc+1
    u64 w1x0 = pkab(W1[cc * 131 + 128], W1[(cc + 1) * 131 + 128]);
    u64 w1x1 = pkab(W1[cc * 131 + 129], W1[(cc + 1) * 131 + 129]);
    u64 w1x2 = pkab(W1[cc * 131 + 130], W1[(cc + 1) * 131 + 130]);
    u64 wvx0 = pkab(Wv[cc * 67 + 64],  Wv[(cc + 1) * 67 + 64]);
    u64 wvx1 = pkab(Wv[cc * 67 + 65],  Wv[(cc + 1) * 67 + 65]);
    u64 wvx2 = pkab(Wv[cc * 67 + 66],  Wv[(cc + 1) * 67 + 66]);

    u64 sh = 0, shq = 0, sv = 0, svq = 0;
    int gw = blockIdx.x * 8 + wid, nw = gridDim.x * 8;
    for (int p = gw; p < NPTS; p += nw) {
        int b = p >> 13;
        float4 q = g_P4[p];
        const int4* nb = (const int4*)(g_NB + p * KK);
        int4 iA = nb[0], iB = nb[1], iC = nb[2], iD = nb[3];
        int mi[16] = {iA.x, iA.y, iA.z, iA.w, iB.x, iB.y, iB.z, iB.w,
                      iC.x, iC.y, iC.z, iC.w, iD.x, iD.y, iD.z, iD.w};
        const float* ptp = g_PT + (size_t)p * 192;
        u64 hcp = *(const u64*)(ptp + cc);
#pragma unroll
        for (int k = 0; k < KK; k++) {
            int m = mi[k];
            float4 pm = g_P4[b * NN + m];
            u64 rxp = pk2(pm.x - q.x), ryp = pk2(pm.y - q.y), rzp = pk2(pm.z - q.z);
            const float* ptm = g_PT + (size_t)(b * NN + m) * 192;
            u64 hnp = *(const u64*)(ptm + 64 + cc);
            u64 vnp = *(const u64*)(ptm + 128 + cc);
            u64 h = fma2(rzp, w1x2, fma2(ryp, w1x1, fma2(rxp, w1x0, add2(hcp, hnp))));
            u64 v = fma2(rzp, wvx2, fma2(ryp, wvx1, fma2(rxp, wvx0, vnp)));
            sh = add2(sh, h); shq = fma2(h, h, shq);
            sv = add2(sv, v); svq = fma2(v, v, svq);
        }
    }
    float2 fsh = unpk(sh), fshq = unpk(shq), fsv = unpk(sv), fsvq = unpk(svq);
    atomicAdd(&sstat[cc], fsh.x);       atomicAdd(&sstat[cc + 1], fsh.y);
    atomicAdd(&sstat[64 + cc], fshq.x); atomicAdd(&sstat[64 + cc + 1], fshq.y);
    atomicAdd(&sstat[128 + cc], fsv.x); atomicAdd(&sstat[128 + cc + 1], fsv.y);
    atomicAdd(&sstat[192 + cc], fsvq.x);atomicAdd(&sstat[192 + cc + 1], fsvq.y);
    __syncthreads();
    for (int e = tid; e < 256; e += 256) atomicAdd(&g_stats[e], sstat[e]);
}

// ---------------- k4: stats -> BN coefficients ----------------------------------
__global__ void k4(const float* __restrict__ g1, const float* __restrict__ be1,
                   const float* __restrict__ gv, const float* __restrict__ bev) {
    int c = threadIdx.x;
    float cnt = (float)((size_t)NPTS * KK);
    float mh = g_stats[c] / cnt;
    float vh = g_stats[64 + c] / cnt - mh * mh;
    float a1 = g1[c] * rsqrtf(vh + 1e-5f);
    g_coef1[c] = a1; g_coef1[64 + c] = be1[c] - a1 * mh;
    float mv = g_stats[128 + c] / cnt;
    float vv = g_stats[192 + c] / cnt - mv * mv;
    float av = gv[c] * rsqrtf(vv + 1e-5f);
    g_coef1[128 + c] = av; g_coef1[192 + c] = bev[c] - av * mv;
}

// ---------------- k5: attention + value + weighted sum + out-conv ---------------
__global__ void __launch_bounds__(256) k5(const float* __restrict__ W1,
                   const float* __restrict__ Wv,
                   const float* __restrict__ W2, const float* __restrict__ b2,
                   const float* __restrict__ Wo, const float* __restrict__ bo) {
    __shared__ float sWo[64][65];
    __shared__ float sOut[8][64];
    __shared__ float sstat[128];
    int tid = threadIdx.x, lane = tid & 31, wid = tid >> 5;

    for (int e = tid; e < 64 * 64; e += 256) {
        int j = e >> 6, c = e & 63;
        sWo[j][c] = Wo[c * 64 + j];
    }
    for (int e = tid; e < 128; e += 256) sstat[e] = 0.f;

    int cc = lane * 2;
    u64 w1x0 = pkab(W1[cc * 131 + 128], W1[(cc + 1) * 131 + 128]);
    u64 w1x1 = pkab(W1[cc * 131 + 129], W1[(cc + 1) * 131 + 129]);
    u64 w1x2 = pkab(W1[cc * 131 + 130], W1[(cc + 1) * 131 + 130]);
    u64 wvx0 = pkab(Wv[cc * 67 + 64],  Wv[(cc + 1) * 67 + 64]);
    u64 wvx1 = pkab(Wv[cc * 67 + 65],  Wv[(cc + 1) * 67 + 65]);
    u64 wvx2 = pkab(Wv[cc * 67 + 66],  Wv[(cc + 1) * 67 + 66]);
    float a1a = g_coef1[cc],      a1b = g_coef1[cc + 1];
    float d1a = g_coef1[64 + cc], d1b = g_coef1[64 + cc + 1];
    float ava = g_coef1[128 + cc], avb = g_coef1[128 + cc + 1];
    float dva = g_coef1[192 + cc], dvb = g_coef1[192 + cc + 1];
    float w2a = W2[cc], w2b = W2[cc + 1];
    float b2v = b2[0];
    float boa = bo[cc], bob = bo[cc + 1];
    __syncthreads();

    float so1 = 0.f, so1q = 0.f, so2 = 0.f, so2q = 0.f;
    int gw = blockIdx.x * 8 + wid, nw = gridDim.x * 8;

    for (int p = gw; p < NPTS; p += nw) {
        int b = p >> 13;
        float4 q = g_P4[p];
        const int4* nb = (const int4*)(g_NB + p * KK);
        int4 iA = nb[0], iB = nb[1], iC = nb[2], iD = nb[3];
        int mi[16] = {iA.x, iA.y, iA.z, iA.w, iB.x, iB.y, iB.z, iB.w,
                      iC.x, iC.y, iC.z, iC.w, iD.x, iD.y, iD.z, iD.w};
        const float* ptp = g_PT + (size_t)p * 192;
        u64 hcp = *(const u64*)(ptp + cc);

        float logits[KK], vv1[KK], vv2[KK];
#pragma unroll
        for (int k = 0; k < KK; k++) {
            int m = mi[k];
            float4 pm = g_P4[b * NN + m];
            u64 rxp = pk2(pm.x - q.x), ryp = pk2(pm.y - q.y), rzp = pk2(pm.z - q.z);
            const float* ptm = g_PT + (size_t)(b * NN + m) * 192;
            u64 hnp = *(const u64*)(ptm + 64 + cc);
            u64 vnp = *(const u64*)(ptm + 128 + cc);
            u64 h = fma2(rzp, w1x2, fma2(ryp, w1x1, fma2(rxp, w1x0, add2(hcp, hnp))));
            u64 v = fma2(rzp, wvx2, fma2(ryp, wvx1, fma2(rxp, wvx0, vnp)));
            float2 hf = unpk(h), vf = unpk(v);
            float hb1 = fmaxf(a1a * hf.x + d1a, 0.f);
            float hb2 = fmaxf(a1b * hf.y + d1b, 0.f);
            vv1[k] = fmaxf(ava * vf.x + dva, 0.f);
            vv2[k] = fmaxf(avb * vf.y + dvb, 0.f);
            float t = hb1 * w2a + hb2 * w2b;
#pragma unroll
            for (int off = 16; off > 0; off >>= 1) t += __shfl_xor_sync(0xffffffffu, t, off);
            logits[k] = t + b2v;
        }
        float mx = logits[0];
#pragma unroll
        for (int k = 1; k < KK; k++) mx = fmaxf(mx, logits[k]);
        float ex[KK], se = 0.f;
#pragma unroll
        for (int k = 0; k < KK; k++) { ex[k] = __expf(logits[k] - mx); se += ex[k]; }
        float inv = 1.0f / se;
        float out1 = 0.f, out2 = 0.f;
#pragma unroll
        for (int k = 0; k < KK; k++) {
            float w = ex[k] * inv;
            out1 += w * vv1[k];
            out2 += w * vv2[k];
        }
        __syncwarp();
        sOut[wid][cc] = out1; sOut[wid][cc + 1] = out2;
        __syncwarp();
        float oo1 = boa, oo2 = bob;
#pragma unroll 8
        for (int j = 0; j < 64; j++) {
            float oj = sOut[wid][j];
            oo1 = fmaf(sWo[j][cc], oj, oo1);
            oo2 = fmaf(sWo[j][cc + 1], oj, oo2);
        }
        g_Opre[(size_t)p * 64 + cc] = oo1;
        g_Opre[(size_t)p * 64 + cc + 1] = oo2;
        so1 += oo1; so1q += oo1 * oo1;
        so2 += oo2; so2q += oo2 * oo2;
    }
    atomicAdd(&sstat[cc], so1);     atomicAdd(&sstat[64 + cc], so1q);
    atomicAdd(&sstat[cc + 1], so2); atomicAdd(&sstat[64 + cc + 1], so2q);
    __syncthreads();
    for (int e = tid; e < 128; e += 256) atomicAdd(&g_ostats[e], sstat[e]);
}

// ---------------- k6 ------------------------------------------------------------
__global__ void k6(const float* __restrict__ go, const float* __restrict__ beo) {
    int c = threadIdx.x;
    float cnt = (float)NPTS;
    float m = g_ostats[c] / cnt;
    float v = g_ostats[64 + c] / cnt - m * m;
    float a = go[c] * rsqrtf(v + 1e-5f);
    g_ocoef[c] = a; g_ocoef[64 + c] = beo[c] - a * m;
}

// ---------------- k7: BN + relu + residual + transpose --------------------------
__global__ void k7(const float* __restrict__ feats, float* __restrict__ out) {
    __shared__ float tile[32][65];
    int blk = blockIdx.x;
    int b = blk >> 8;
    int n0 = (blk & 255) << 5;
    int tid = threadIdx.x;
    for (int e = tid; e < 32 * 64; e += 256) {
        int pp = e >> 6, c = e & 63;
        tile[pp][c] = g_Opre[(size_t)(b * NN + n0 + pp) * 64 + c];
    }
    __syncthreads();
    for (int e = tid; e < 64 * 32; e += 256) {
        int c = e >> 5, j = e & 31;
        float val = g_ocoef[c] * tile[j][c] + g_ocoef[64 + c];
        val = fmaxf(val, 0.f) + feats[(size_t)b * CC * NN + (size_t)c * NN + n0 + j];
        out[(size_t)b * CC * NN + (size_t)c * NN + n0 + j] = val;
    }
}

// ---------------- launch --------------------------------------------------------
extern "C" void kernel_launch(void* const* d_in, const int* in_sizes, int n_in,
                              void* d_out, int out_size) {
    const float* xyz   = (const float*)d_in[0];
    const float* feats = (const float*)d_in[1];
    const float* W1    = (const float*)d_in[2];
    const float* b1    = (const float*)d_in[3];
    const float* g1    = (const float*)d_in[4];
    const float* be1   = (const float*)d_in[5];
    const float* W2    = (const float*)d_in[6];
    const float* b2    = (const float*)d_in[7];
    const float* Wv    = (const float*)d_in[8];
    const float* bv    = (const float*)d_in[9];
    const float* gv    = (const float*)d_in[10];
    const float* bev   = (const float*)d_in[11];
    const float* Wo    = (const float*)d_in[12];
    const float* bo    = (const float*)d_in[13];
    const float* go    = (const float*)d_in[14];
    const float* beo   = (const float*)d_in[15];
    float* out = (float*)d_out;

    k0<<<NPTS / 256, 256>>>(xyz);
    k1<<<NPTS / 32, 64>>>();
    k2<<<NPTS / 64, 256>>>(feats, W1, b1, Wv, bv);
    k3<<<1184, 256>>>(W1, Wv);
    k4<<<1, 64>>>(g1, be1, gv, bev);
    k5<<<1184, 256>>>(W1, Wv, W2, b2, Wo, bo);
    k6<<<1, 64>>>(go, beo);
    k7<<<NPTS / 32, 256>>>(feats, out);
}

// round 7
// speedup vs baseline: 3.4506x; 1.0487x over previous
#include <cuda_runtime.h>
#include <cfloat>
#include <math.h>

#define BB 4
#define NN 8192
#define CC 64
#define KK 16
#define HH 64
#define NPTS (BB*NN)

// ---------------- device scratch ------------------------------------------------
__device__ float4 g_P4[NPTS];                    // (x,y,z,|p|^2)
__device__ float  g_Sx[NPTS], g_Sy[NPTS], g_Sz[NPTS], g_Sq[NPTS];  // SoA coords
__device__ float  g_PT[(size_t)NPTS*192];        // [hc+b1 (64) | hn (64) | vn+bv (64)]
__device__ int    g_NB[NPTS*KK];                 // knn indices
__device__ float  g_stats[256];
__device__ float  g_coef1[256];
__device__ float  g_ostats[128];
__device__ float  g_ocoef[128];
__device__ float  g_Opre[(size_t)NPTS*64];

// ---------------- f32x2 helpers -------------------------------------------------
typedef unsigned long long u64;
__device__ __forceinline__ u64 fma2(u64 a, u64 b, u64 c) {
    u64 d; asm("fma.rn.f32x2 %0,%1,%2,%3;" : "=l"(d) : "l"(a), "l"(b), "l"(c));
    return d;
}
__device__ __forceinline__ u64 add2(u64 a, u64 b) {
    u64 d; asm("add.rn.f32x2 %0,%1,%2;" : "=l"(d) : "l"(a), "l"(b));
    return d;
}
__device__ __forceinline__ u64 pk2(float v) {
    u64 d; asm("mov.b64 %0,{%1,%1};" : "=l"(d) : "f"(v));
    return d;
}
__device__ __forceinline__ u64 pkab(float a, float b) {
    u64 d; asm("mov.b64 %0,{%1,%2};" : "=l"(d) : "f"(a), "f"(b));
    return d;
}
__device__ __forceinline__ float2 unpk(u64 v) {
    float2 r; asm("mov.b64 {%0,%1},%2;" : "=f"(r.x), "=f"(r.y) : "l"(v));
    return r;
}

// ---------------- k0: pack xyz (AoS + SoA) + zero stats -------------------------
__global__ void k0(const float* __restrict__ xyz) {
    int p = blockIdx.x * blockDim.x + threadIdx.x;
    if (p < 256) g_stats[p] = 0.f;
    if (p < 128) g_ostats[p] = 0.f;
    if (p >= NPTS) return;
    int b = p >> 13, n = p & (NN - 1);
    const float* base = xyz + (size_t)b * 3 * NN + n;
    float x = base[0], y = base[NN], z = base[2 * NN];
    float w = x * x + y * y + z * z;
    g_P4[p] = make_float4(x, y, z, w);
    g_Sx[p] = x; g_Sy[p] = y; g_Sz[p] = z; g_Sq[p] = w;
}

// ---------------- k1: KNN, 2 warps split range, deferred buffered inserts -------
#define TSH 512
#define BS  17      // 2*17 == 2 (mod 32)  -> conflict-free float2 smem accesses
#define VST 20      // top16 list stride (ints); 20*4B=80B -> conflict-free LDS.128
__global__ void __launch_bounds__(64) k1() {
    __shared__ __align__(16) float sX[2][TSH];
    __shared__ __align__(16) float sY[2][TSH];
    __shared__ __align__(16) float sZ[2][TSH];
    __shared__ __align__(16) float sWW[2][TSH];
    __shared__ __align__(16) unsigned sVal[2 * 32 * VST];
    __shared__ int      sIdx[2 * 32 * VST];
    __shared__ __align__(8) float2 sBuf[2 * 32 * BS];

    int lane = threadIdx.x & 31;
    int wid  = threadIdx.x >> 5;
    int blk  = blockIdx.x;                // 1024 blocks
    int b    = blk >> 8;                  // 256 blocks per batch
    int n    = ((blk & 255) << 5) + lane;
    int p    = b * NN + n;

    float4 q = g_P4[p];
    float qw = q.w;
    u64 m2x = pk2(-2.f * q.x), m2y = pk2(-2.f * q.y), m2z = pk2(-2.f * q.z);

    int vb = (wid * 32 + lane) * VST;
    int bbuf = (wid * 32 + lane) * BS;
#pragma unroll
    for (int s = 0; s < 16; s++) {
        sVal[vb + s] = 0x7F7FFFF0u | (unsigned)s;
        sIdx[vb + s] = 0;
    }
    unsigned worstP = 0x7F7FFFFFu;
    float thr = __uint_as_float(0x7F7FFFF0u) - qw;   // t-domain threshold
    int cnt = 0;

    int cbase = wid * 4096;
    for (int t0 = 0; t0 < 4096; t0 += TSH) {
        __syncwarp();
        const float* bx = g_Sx + b * NN + cbase + t0;
        const float* by = g_Sy + b * NN + cbase + t0;
        const float* bz = g_Sz + b * NN + cbase + t0;
        const float* bw = g_Sq + b * NN + cbase + t0;
#pragma unroll
        for (int i = 0; i < TSH / 128; i++) {
            int o = i * 128 + lane * 4;
            *(float4*)(sX[wid]  + o) = *(const float4*)(bx + o);
            *(float4*)(sY[wid]  + o) = *(const float4*)(by + o);
            *(float4*)(sZ[wid]  + o) = *(const float4*)(bz + o);
            *(float4*)(sWW[wid] + o) = *(const float4*)(bw + o);
        }
        __syncwarp();

        for (int j = 0; j < TSH; j += 8) {
            ulonglong2 X0 = *(const ulonglong2*)(sX[wid]  + j);
            ulonglong2 Y0 = *(const ulonglong2*)(sY[wid]  + j);
            ulonglong2 Z0 = *(const ulonglong2*)(sZ[wid]  + j);
            ulonglong2 W0 = *(const ulonglong2*)(sWW[wid] + j);
            ulonglong2 X1 = *(const ulonglong2*)(sX[wid]  + j + 4);
            ulonglong2 Y1 = *(const ulonglong2*)(sY[wid]  + j + 4);
            ulonglong2 Z1 = *(const ulonglong2*)(sZ[wid]  + j + 4);
            ulonglong2 W1 = *(const ulonglong2*)(sWW[wid] + j + 4);
            u64 t0a = fma2(Z0.x, m2z, fma2(Y0.x, m2y, fma2(X0.x, m2x, W0.x)));
            u64 t0b = fma2(Z0.y, m2z, fma2(Y0.y, m2y, fma2(X0.y, m2x, W0.y)));
            u64 t1a = fma2(Z1.x, m2z, fma2(Y1.x, m2y, fma2(X1.x, m2x, W1.x)));
            u64 t1b = fma2(Z1.y, m2z, fma2(Y1.y, m2y, fma2(X1.y, m2x, W1.y)));
            float2 f01 = unpk(t0a), f23 = unpk(t0b), f45 = unpk(t1a), f67 = unpk(t1b);
            float m01 = fminf(f01.x, f01.y), m23 = fminf(f23.x, f23.y);
            float m45 = fminf(f45.x, f45.y), m67 = fminf(f67.x, f67.y);
            float mm = fminf(fminf(m01, m23), fminf(m45, m67));
            if (mm < thr) {
                float tt[8] = {f01.x, f01.y, f23.x, f23.y, f45.x, f45.y, f67.x, f67.y};
                int ib = cbase + t0 + j;
#pragma unroll
                for (int uu = 0; uu < 8; uu++) {
                    // unconditional store is safe: cnt only advances on pass
                    sBuf[bbuf + cnt] = make_float2(tt[uu], __int_as_float(ib + uu));
                    cnt += (tt[uu] < thr) ? 1 : 0;
                }
            }
            if (__any_sync(0xffffffffu, cnt >= BS - 7)) {
#pragma unroll 1
                for (int e = 0; e < cnt; e++) {
                    float2 pr = sBuf[bbuf + e];
                    if (pr.x < thr) {
                        float ts = fmaxf(pr.x + qw, 0.f);
                        unsigned slot = worstP & 0xFu;
                        sVal[vb + slot] = (__float_as_uint(ts) & 0xFFFFFFF0u) | slot;
                        sIdx[vb + slot] = __float_as_int(pr.y);
                        unsigned mmax = 0u;
                        const uint4* vp = (const uint4*)(sVal + vb);
#pragma unroll
                        for (int s4 = 0; s4 < 4; s4++) {
                            uint4 v = vp[s4];
                            mmax = max(mmax, max(max(v.x, v.y), max(v.z, v.w)));
                        }
                        worstP = mmax;
                        thr = __uint_as_float(mmax & 0xFFFFFFF0u) - qw;
                    }
                }
                cnt = 0;
            }
        }
    }

    // final flush of buffered candidates
#pragma unroll 1
    for (int e = 0; e < cnt; e++) {
        float2 pr = sBuf[bbuf + e];
        if (pr.x < thr) {
            float ts = fmaxf(pr.x + qw, 0.f);
            unsigned slot = worstP & 0xFu;
            sVal[vb + slot] = (__float_as_uint(ts) & 0xFFFFFFF0u) | slot;
            sIdx[vb + slot] = __float_as_int(pr.y);
            unsigned mmax = 0u;
            const uint4* vp = (const uint4*)(sVal + vb);
#pragma unroll
            for (int s4 = 0; s4 < 4; s4++) {
                uint4 v = vp[s4];
                mmax = max(mmax, max(max(v.x, v.y), max(v.z, v.w)));
            }
            worstP = mmax;
            thr = __uint_as_float(mmax & 0xFFFFFFF0u) - qw;
        }
    }

    __syncthreads();
    if (wid == 0) {
        int pb = (32 + lane) * VST;
        float thrts = __uint_as_float(worstP & 0xFFFFFFF0u);
#pragma unroll
        for (int s = 0; s < 16; s++) {
            unsigned pv = sVal[pb + s];
            float pvts = __uint_as_float(pv & 0xFFFFFFF0u);
            if (pvts < thrts) {
                unsigned slot = worstP & 0xFu;
                sVal[vb + slot] = (pv & 0xFFFFFFF0u) | slot;
                sIdx[vb + slot] = sIdx[pb + s];
                unsigned mmax = 0u;
                const uint4* vp = (const uint4*)(sVal + vb);
#pragma unroll
                for (int s4 = 0; s4 < 4; s4++) {
                    uint4 v = vp[s4];
                    mmax = max(mmax, max(max(v.x, v.y), max(v.z, v.w)));
                }
                worstP = mmax;
                thrts = __uint_as_float(mmax & 0xFFFFFFF0u);
            }
        }
#pragma unroll
        for (int s = 0; s < 16; s++) g_NB[p * KK + s] = sIdx[vb + s];
    }
}

// ---------------- k2: per-point transforms, 3 passes of 64 outs -----------------
__global__ void __launch_bounds__(256) k2(const float* __restrict__ feats,
                   const float* __restrict__ W1, const float* __restrict__ b1,
                   const float* __restrict__ Wv, const float* __restrict__ bv) {
    __shared__ float sW[64][64];
    __shared__ float sF[64][64];
    int tid = threadIdx.x;
    int blk = blockIdx.x;
    int b   = blk >> 7;
    int n0  = (blk & 127) << 6;

    for (int e = tid; e < 1024; e += 256) {
        int c = e >> 4, v4 = e & 15;
        ((float4*)sF[c])[v4] =
            ((const float4*)(feats + (size_t)b * CC * NN + (size_t)c * NN + n0))[v4];
    }

    int og = tid & 15, ng = tid >> 4;

    for (int pp = 0; pp < 3; pp++) {
        __syncthreads();
        for (int e = tid; e < 4096; e += 256) {
            int ol = e & 63, c = e >> 6;
            float w;
            if (pp == 0)      w = W1[ol * 131 + c];
            else if (pp == 1) w = W1[ol * 131 + 64 + c];
            else              w = Wv[ol * 67 + c];
            sW[c][ol] = w;
        }
        __syncthreads();

        float4 a0 = make_float4(0.f,0.f,0.f,0.f), a1 = a0, a2 = a0, a3 = a0;
        for (int c = 0; c < 64; c++) {
            float4 w4 = *(const float4*)&sW[c][og * 4];
            float4 f4 = *(const float4*)&sF[c][ng * 4];
            a0.x = fmaf(w4.x, f4.x, a0.x); a0.y = fmaf(w4.y, f4.x, a0.y);
            a0.z = fmaf(w4.z, f4.x, a0.z); a0.w = fmaf(w4.w, f4.x, a0.w);
            a1.x = fmaf(w4.x, f4.y, a1.x); a1.y = fmaf(w4.y, f4.y, a1.y);
            a1.z = fmaf(w4.z, f4.y, a1.z); a1.w = fmaf(w4.w, f4.y, a1.w);
            a2.x = fmaf(w4.x, f4.z, a2.x); a2.y = fmaf(w4.y, f4.z, a2.y);
            a2.z = fmaf(w4.z, f4.z, a2.z); a2.w = fmaf(w4.w, f4.z, a2.w);
            a3.x = fmaf(w4.x, f4.w, a3.x); a3.y = fmaf(w4.y, f4.w, a3.y);
            a3.z = fmaf(w4.z, f4.w, a3.z); a3.w = fmaf(w4.w, f4.w, a3.w);
        }

        float4 bb = make_float4(0.f, 0.f, 0.f, 0.f);
        if (pp == 0) bb = *(const float4*)(b1 + og * 4);
        if (pp == 2) bb = *(const float4*)(bv + og * 4);
        int obase = pp * 64 + og * 4;
        float4 r;
        size_t pbase = (size_t)(b * NN + n0 + ng * 4);
        r = make_float4(a0.x+bb.x, a0.y+bb.y, a0.z+bb.z, a0.w+bb.w);
        *(float4*)(g_PT + (pbase + 0) * 192 + obase) = r;
        r = make_float4(a1.x+bb.x, a1.y+bb.y, a1.z+bb.z, a1.w+bb.w);
        *(float4*)(g_PT + (pbase + 1) * 192 + obase) = r;
        r = make_float4(a2.x+bb.x, a2.y+bb.y, a2.z+bb.z, a2.w+bb.w);
        *(float4*)(g_PT + (pbase + 2) * 192 + obase) = r;
        r = make_float4(a3.x+bb.x, a3.y+bb.y, a3.z+bb.z, a3.w+bb.w);
        *(float4*)(g_PT + (pbase + 3) * 192 + obase) = r;
    }
}

// ---------------- k3: BN stats for h and v (f32x2, channel pairs) ---------------
__global__ void __launch_bounds__(256) k3(const float* __restrict__ W1,
                                          const float* __restrict__ Wv) {
    __shared__ float sstat[256];
    int tid = threadIdx.x, lane = tid & 31, wid = tid >> 5;
    for (int e = tid; e < 256; e += 256) sstat[e] = 0.f;
    __syncthreads();

    int cc = lane * 2;   // channels cc, cc+1
    u64 w1x0 = pkab(W1[cc * 131 + 128], W1[(cc + 1) * 131 + 128]);
    u64 w1x1 = pkab(W1[cc * 131 + 129], W1[(cc + 1) * 131 + 129]);
    u64 w1x2 = pkab(W1[cc * 131 + 130], W1[(cc + 1) * 131 + 130]);
    u64 wvx0 = pkab(Wv[cc * 67 + 64],  Wv[(cc + 1) * 67 + 64]);
    u64 wvx1 = pkab(Wv[cc * 67 + 65],  Wv[(cc + 1) * 67 + 65]);
    u64 wvx2 = pkab(Wv[cc * 67 + 66],  Wv[(cc + 1) * 67 + 66]);

    u64 sh = 0, shq = 0, sv = 0, svq = 0;
    int gw = blockIdx.x * 8 + wid, nw = gridDim.x * 8;
    for (int p = gw; p < NPTS; p += nw) {
        int b = p >> 13;
        float4 q = g_P4[p];
        const int4* nb = (const int4*)(g_NB + p * KK);
        int4 iA = nb[0], iB = nb[1], iC = nb[2], iD = nb[3];
        int mi[16] = {iA.x, iA.y, iA.z, iA.w, iB.x, iB.y, iB.z, iB.w,
                      iC.x, iC.y, iC.z, iC.w, iD.x, iD.y, iD.z, iD.w};
        const float* ptp = g_PT + (size_t)p * 192;
        u64 hcp = *(const u64*)(ptp + cc);
#pragma unroll
        for (int k = 0; k < KK; k++) {
            int m = mi[k];
            float4 pm = g_P4[b * NN + m];
            u64 rxp = pk2(pm.x - q.x), ryp = pk2(pm.y - q.y), rzp = pk2(pm.z - q.z);
            const float* ptm = g_PT + (size_t)(b * NN + m) * 192;
            u64 hnp = *(const u64*)(ptm + 64 + cc);
            u64 vnp = *(const u64*)(ptm + 128 + cc);
            u64 h = fma2(rzp, w1x2, fma2(ryp, w1x1, fma2(rxp, w1x0, add2(hcp, hnp))));
            u64 v = fma2(rzp, wvx2, fma2(ryp, wvx1, fma2(rxp, wvx0, vnp)));
            sh = add2(sh, h); shq = fma2(h, h, shq);
            sv = add2(sv, v); svq = fma2(v, v, svq);
        }
    }
    float2 fsh = unpk(sh), fshq = unpk(shq), fsv = unpk(sv), fsvq = unpk(svq);
    atomicAdd(&sstat[cc], fsh.x);       atomicAdd(&sstat[cc + 1], fsh.y);
    atomicAdd(&sstat[64 + cc], fshq.x); atomicAdd(&sstat[64 + cc + 1], fshq.y);
    atomicAdd(&sstat[128 + cc], fsv.x); atomicAdd(&sstat[128 + cc + 1], fsv.y);
    atomicAdd(&sstat[192 + cc], fsvq.x);atomicAdd(&sstat[192 + cc + 1], fsvq.y);
    __syncthreads();
    for (int e = tid; e < 256; e += 256) atomicAdd(&g_stats[e], sstat[e]);
}

// ---------------- k4: stats -> BN coefficients ----------------------------------
__global__ void k4(const float* __restrict__ g1, const float* __restrict__ be1,
                   const float* __restrict__ gv, const float* __restrict__ bev) {
    int c = threadIdx.x;
    float cnt = (float)((size_t)NPTS * KK);
    float mh = g_stats[c] / cnt;
    float vh = g_stats[64 + c] / cnt - mh * mh;
    float a1 = g1[c] * rsqrtf(vh + 1e-5f);
    g_coef1[c] = a1; g_coef1[64 + c] = be1[c] - a1 * mh;
    float mv = g_stats[128 + c] / cnt;
    float vv = g_stats[192 + c] / cnt - mv * mv;
    float av = gv[c] * rsqrtf(vv + 1e-5f);
    g_coef1[128 + c] = av; g_coef1[192 + c] = bev[c] - av * mv;
}

// ---------------- k5: attention + value + weighted sum + out-conv ---------------
__global__ void __launch_bounds__(256) k5(const float* __restrict__ W1,
                   const float* __restrict__ Wv,
                   const float* __restrict__ W2, const float* __restrict__ b2,
                   const float* __restrict__ Wo, const float* __restrict__ bo) {
    __shared__ float sWo[64][65];
    __shared__ float sOut[8][64];
    __shared__ float sstat[128];
    int tid = threadIdx.x, lane = tid & 31, wid = tid >> 5;

    for (int e = tid; e < 64 * 64; e += 256) {
        int j = e >> 6, c = e & 63;
        sWo[j][c] = Wo[c * 64 + j];
    }
    for (int e = tid; e < 128; e += 256) sstat[e] = 0.f;

    int cc = lane * 2;
    u64 w1x0 = pkab(W1[cc * 131 + 128], W1[(cc + 1) * 131 + 128]);
    u64 w1x1 = pkab(W1[cc * 131 + 129], W1[(cc + 1) * 131 + 129]);
    u64 w1x2 = pkab(W1[cc * 131 + 130], W1[(cc + 1) * 131 + 130]);
    u64 wvx0 = pkab(Wv[cc * 67 + 64],  Wv[(cc + 1) * 67 + 64]);
    u64 wvx1 = pkab(Wv[cc * 67 + 65],  Wv[(cc + 1) * 67 + 65]);
    u64 wvx2 = pkab(Wv[cc * 67 + 66],  Wv[(cc + 1) * 67 + 66]);
    float a1a = g_coef1[cc],      a1b = g_coef1[cc + 1];
    float d1a = g_coef1[64 + cc], d1b = g_coef1[64 + cc + 1];
    float ava = g_coef1[128 + cc], avb = g_coef1[128 + cc + 1];
    float dva = g_coef1[192 + cc], dvb = g_coef1[192 + cc + 1];
    float w2a = W2[cc], w2b = W2[cc + 1];
    float b2v = b2[0];
    float boa = bo[cc], bob = bo[cc + 1];
    __syncthreads();

    float so1 = 0.f, so1q = 0.f, so2 = 0.f, so2q = 0.f;
    int gw = blockIdx.x * 8 + wid, nw = gridDim.x * 8;

    for (int p = gw; p < NPTS; p += nw) {
        int b = p >> 13;
        float4 q = g_P4[p];
        const int4* nb = (const int4*)(g_NB + p * KK);
        int4 iA = nb[0], iB = nb[1], iC = nb[2], iD = nb[3];
        int mi[16] = {iA.x, iA.y, iA.z, iA.w, iB.x, iB.y, iB.z, iB.w,
                      iC.x, iC.y, iC.z, iC.w, iD.x, iD.y, iD.z, iD.w};
        const float* ptp = g_PT + (size_t)p * 192;
        u64 hcp = *(const u64*)(ptp + cc);

        float logits[KK], vv1[KK], vv2[KK];
#pragma unroll
        for (int k = 0; k < KK; k++) {
            int m = mi[k];
            float4 pm = g_P4[b * NN + m];
            u64 rxp = pk2(pm.x - q.x), ryp = pk2(pm.y - q.y), rzp = pk2(pm.z - q.z);
            const float* ptm = g_PT + (size_t)(b * NN + m) * 192;
            u64 hnp = *(const u64*)(ptm + 64 + cc);
            u64 vnp = *(const u64*)(ptm + 128 + cc);
            u64 h = fma2(rzp, w1x2, fma2(ryp, w1x1, fma2(rxp, w1x0, add2(hcp, hnp))));
            u64 v = fma2(rzp, wvx2, fma2(ryp, wvx1, fma2(rxp, wvx0, vnp)));
            float2 hf = unpk(h), vf = unpk(v);
            float hb1 = fmaxf(a1a * hf.x + d1a, 0.f);
            float hb2 = fmaxf(a1b * hf.y + d1b, 0.f);
            vv1[k] = fmaxf(ava * vf.x + dva, 0.f);
            vv2[k] = fmaxf(avb * vf.y + dvb, 0.f);
            float t = hb1 * w2a + hb2 * w2b;
#pragma unroll
            for (int off = 16; off > 0; off >>= 1) t += __shfl_xor_sync(0xffffffffu, t, off);
            logits[k] = t + b2v;
        }
        float mx = logits[0];
#pragma unroll
        for (int k = 1; k < KK; k++) mx = fmaxf(mx, logits[k]);
        float ex[KK], se = 0.f;
#pragma unroll
        for (int k = 0; k < KK; k++) { ex[k] = __expf(logits[k] - mx); se += ex[k]; }
        float inv = 1.0f / se;
        float out1 = 0.f, out2 = 0.f;
#pragma unroll
        for (int k = 0; k < KK; k++) {
            float w = ex[k] * inv;
            out1 += w * vv1[k];
            out2 += w * vv2[k];
        }
        __syncwarp();
        sOut[wid][cc] = out1; sOut[wid][cc + 1] = out2;
        __syncwarp();
        float oo1 = boa, oo2 = bob;
#pragma unroll 8
        for (int j = 0; j < 64; j++) {
            float oj = sOut[wid][j];
            oo1 = fmaf(sWo[j][cc], oj, oo1);
            oo2 = fmaf(sWo[j][cc + 1], oj, oo2);
        }
        g_Opre[(size_t)p * 64 + cc] = oo1;
        g_Opre[(size_t)p * 64 + cc + 1] = oo2;
        so1 += oo1; so1q += oo1 * oo1;
        so2 += oo2; so2q += oo2 * oo2;
    }
    atomicAdd(&sstat[cc], so1);     atomicAdd(&sstat[64 + cc], so1q);
    atomicAdd(&sstat[cc + 1], so2); atomicAdd(&sstat[64 + cc + 1], so2q);
    __syncthreads();
    for (int e = tid; e < 128; e += 256) atomicAdd(&g_ostats[e], sstat[e]);
}

// ---------------- k6 ------------------------------------------------------------
__global__ void k6(const float* __restrict__ go, const float* __restrict__ beo) {
    int c = threadIdx.x;
    float cnt = (float)NPTS;
    float m = g_ostats[c] / cnt;
    float v = g_ostats[64 + c] / cnt - m * m;
    float a = go[c] * rsqrtf(v + 1e-5f);
    g_ocoef[c] = a; g_ocoef[64 + c] = beo[c] - a * m;
}

// ---------------- k7: BN + relu + residual + transpose --------------------------
__global__ void k7(const float* __restrict__ feats, float* __restrict__ out) {
    __shared__ float tile[32][65];
    int blk = blockIdx.x;
    int b = blk >> 8;
    int n0 = (blk & 255) << 5;
    int tid = threadIdx.x;
    for (int e = tid; e < 32 * 64; e += 256) {
        int pp = e >> 6, c = e & 63;
        tile[pp][c] = g_Opre[(size_t)(b * NN + n0 + pp) * 64 + c];
    }
    __syncthreads();
    for (int e = tid; e < 64 * 32; e += 256) {
        int c = e >> 5, j = e & 31;
        float val = g_ocoef[c] * tile[j][c] + g_ocoef[64 + c];
        val = fmaxf(val, 0.f) + feats[(size_t)b * CC * NN + (size_t)c * NN + n0 + j];
        out[(size_t)b * CC * NN + (size_t)c * NN + n0 + j] = val;
    }
}

// ---------------- launch --------------------------------------------------------
extern "C" void kernel_launch(void* const* d_in, const int* in_sizes, int n_in,
                              void* d_out, int out_size) {
    const float* xyz   = (const float*)d_in[0];
    const float* feats = (const float*)d_in[1];
    const float* W1    = (const float*)d_in[2];
    const float* b1    = (const float*)d_in[3];
    const float* g1    = (const float*)d_in[4];
    const float* be1   = (const float*)d_in[5];
    const float* W2    = (const float*)d_in[6];
    const float* b2    = (const float*)d_in[7];
    const float* Wv    = (const float*)d_in[8];
    const float* bv    = (const float*)d_in[9];
    const float* gv    = (const float*)d_in[10];
    const float* bev   = (const float*)d_in[11];
    const float* Wo    = (const float*)d_in[12];
    const float* bo    = (const float*)d_in[13];
    const float* go    = (const float*)d_in[14];
    const float* beo   = (const float*)d_in[15];
    float* out = (float*)d_out;

    k0<<<NPTS / 256, 256>>>(xyz);
    k1<<<NPTS / 32, 64>>>();
    k2<<<NPTS / 64, 256>>>(feats, W1, b1, Wv, bv);
    k3<<<1184, 256>>>(W1, Wv);
    k4<<<1, 64>>>(g1, be1, gv, bev);
    k5<<<1184, 256>>>(W1, Wv, W2, b2, Wo, bo);
    k6<<<1, 64>>>(go, beo);
    k7<<<NPTS / 32, 256>>>(feats, out);
}

// round 8
// speedup vs baseline: 3.6283x; 1.0515x over previous
#include <cuda_runtime.h>
#include <cfloat>
#include <math.h>

#define BB 4
#define NN 8192
#define CC 64
#define KK 16
#define HH 64
#define NPTS (BB*NN)

// ---------------- device scratch ------------------------------------------------
__device__ float4 g_P4[NPTS];                    // (x,y,z,|p|^2)
__device__ float  g_Sx[NPTS], g_Sy[NPTS], g_Sz[NPTS], g_Sq[NPTS];  // SoA coords
__device__ float  g_PT[(size_t)NPTS*192];        // [hc+b1 (64) | hn (64) | vn+bv (64)]
__device__ int    g_NB[NPTS*KK];                 // knn indices
__device__ float  g_stats[256];
__device__ float  g_coef1[256];
__device__ float  g_ostats[128];
__device__ float  g_ocoef[128];
__device__ float  g_Opre[(size_t)NPTS*64];

// ---------------- f32x2 helpers -------------------------------------------------
typedef unsigned long long u64;
__device__ __forceinline__ u64 fma2(u64 a, u64 b, u64 c) {
    u64 d; asm("fma.rn.f32x2 %0,%1,%2,%3;" : "=l"(d) : "l"(a), "l"(b), "l"(c));
    return d;
}
__device__ __forceinline__ u64 add2(u64 a, u64 b) {
    u64 d; asm("add.rn.f32x2 %0,%1,%2;" : "=l"(d) : "l"(a), "l"(b));
    return d;
}
__device__ __forceinline__ u64 pk2(float v) {
    u64 d; asm("mov.b64 %0,{%1,%1};" : "=l"(d) : "f"(v));
    return d;
}
__device__ __forceinline__ u64 pkab(float a, float b) {
    u64 d; asm("mov.b64 %0,{%1,%2};" : "=l"(d) : "f"(a), "f"(b));
    return d;
}
__device__ __forceinline__ float2 unpk(u64 v) {
    float2 r; asm("mov.b64 {%0,%1},%2;" : "=f"(r.x), "=f"(r.y) : "l"(v));
    return r;
}

// ---------------- k0: pack xyz (AoS + SoA) + zero stats -------------------------
__global__ void k0(const float* __restrict__ xyz) {
    int p = blockIdx.x * blockDim.x + threadIdx.x;
    if (p < 256) g_stats[p] = 0.f;
    if (p < 128) g_ostats[p] = 0.f;
    if (p >= NPTS) return;
    int b = p >> 13, n = p & (NN - 1);
    const float* base = xyz + (size_t)b * 3 * NN + n;
    float x = base[0], y = base[NN], z = base[2 * NN];
    float w = x * x + y * y + z * z;
    g_P4[p] = make_float4(x, y, z, w);
    g_Sx[p] = x; g_Sy[p] = y; g_Sz[p] = z; g_Sq[p] = w;
}

// ---------------- k1: KNN, 4 warps split candidate range ------------------------
// block = 128 threads = 4 warps owning the same 32 queries.
// warp w scans candidates [w*2048, (w+1)*2048); warp 0 merges 3 partner lists.
#define NWARP 4
#define RANGE 2048
#define TSH 256
#define BS  11      // 2*11 == 22 (mod 32)  -> conflict-free float2 smem accesses
#define VST 20      // top16 list stride (ints); 80B -> 16B-aligned, conflict-free LDS.128
__global__ void __launch_bounds__(128) k1() {
    __shared__ __align__(16) float sX[NWARP][TSH];
    __shared__ __align__(16) float sY[NWARP][TSH];
    __shared__ __align__(16) float sZ[NWARP][TSH];
    __shared__ __align__(16) float sWW[NWARP][TSH];
    __shared__ __align__(16) unsigned sVal[NWARP * 32 * VST];
    __shared__ int      sIdx[NWARP * 32 * VST];
    __shared__ __align__(8) float2 sBuf[NWARP * 32 * BS];

    int lane = threadIdx.x & 31;
    int wid  = threadIdx.x >> 5;
    int blk  = blockIdx.x;                // 1024 blocks
    int b    = blk >> 8;                  // 256 blocks per batch
    int n    = ((blk & 255) << 5) + lane;
    int p    = b * NN + n;

    float4 q = g_P4[p];
    float qw = q.w;
    u64 m2x = pk2(-2.f * q.x), m2y = pk2(-2.f * q.y), m2z = pk2(-2.f * q.z);

    int vb = (wid * 32 + lane) * VST;
    int bbuf = (wid * 32 + lane) * BS;
#pragma unroll
    for (int s = 0; s < 16; s++) {
        sVal[vb + s] = 0x7F7FFFF0u | (unsigned)s;
        sIdx[vb + s] = 0;
    }
    unsigned worstP = 0x7F7FFFFFu;
    float thr = __uint_as_float(0x7F7FFFF0u) - qw;   // t-domain threshold
    int cnt = 0;

    int cbase = wid * RANGE;
    for (int t0 = 0; t0 < RANGE; t0 += TSH) {
        __syncwarp();
        const float* bx = g_Sx + b * NN + cbase + t0;
        const float* by = g_Sy + b * NN + cbase + t0;
        const float* bz = g_Sz + b * NN + cbase + t0;
        const float* bw = g_Sq + b * NN + cbase + t0;
#pragma unroll
        for (int i = 0; i < TSH / 128; i++) {
            int o = i * 128 + lane * 4;
            *(float4*)(sX[wid]  + o) = *(const float4*)(bx + o);
            *(float4*)(sY[wid]  + o) = *(const float4*)(by + o);
            *(float4*)(sZ[wid]  + o) = *(const float4*)(bz + o);
            *(float4*)(sWW[wid] + o) = *(const float4*)(bw + o);
        }
        __syncwarp();

        for (int j = 0; j < TSH; j += 8) {
            ulonglong2 X0 = *(const ulonglong2*)(sX[wid]  + j);
            ulonglong2 Y0 = *(const ulonglong2*)(sY[wid]  + j);
            ulonglong2 Z0 = *(const ulonglong2*)(sZ[wid]  + j);
            ulonglong2 W0 = *(const ulonglong2*)(sWW[wid] + j);
            ulonglong2 X1 = *(const ulonglong2*)(sX[wid]  + j + 4);
            ulonglong2 Y1 = *(const ulonglong2*)(sY[wid]  + j + 4);
            ulonglong2 Z1 = *(const ulonglong2*)(sZ[wid]  + j + 4);
            ulonglong2 W1 = *(const ulonglong2*)(sWW[wid] + j + 4);
            u64 t0a = fma2(Z0.x, m2z, fma2(Y0.x, m2y, fma2(X0.x, m2x, W0.x)));
            u64 t0b = fma2(Z0.y, m2z, fma2(Y0.y, m2y, fma2(X0.y, m2x, W0.y)));
            u64 t1a = fma2(Z1.x, m2z, fma2(Y1.x, m2y, fma2(X1.x, m2x, W1.x)));
            u64 t1b = fma2(Z1.y, m2z, fma2(Y1.y, m2y, fma2(X1.y, m2x, W1.y)));
            float2 f01 = unpk(t0a), f23 = unpk(t0b), f45 = unpk(t1a), f67 = unpk(t1b);
            float m01 = fminf(f01.x, f01.y), m23 = fminf(f23.x, f23.y);
            float m45 = fminf(f45.x, f45.y), m67 = fminf(f67.x, f67.y);
            float mm = fminf(fminf(m01, m23), fminf(m45, m67));
            if (mm < thr) {
                float tt[8] = {f01.x, f01.y, f23.x, f23.y, f45.x, f45.y, f67.x, f67.y};
                int ib = cbase + t0 + j;
#pragma unroll
                for (int uu = 0; uu < 8; uu++) {
                    // unconditional store is safe: cnt only advances on pass
                    sBuf[bbuf + cnt] = make_float2(tt[uu], __int_as_float(ib + uu));
                    cnt += (tt[uu] < thr) ? 1 : 0;
                }
            }
            if (__any_sync(0xffffffffu, cnt >= BS - 7)) {
#pragma unroll 1
                for (int e = 0; e < cnt; e++) {
                    float2 pr = sBuf[bbuf + e];
                    if (pr.x < thr) {
                        float ts = fmaxf(pr.x + qw, 0.f);
                        unsigned slot = worstP & 0xFu;
                        sVal[vb + slot] = (__float_as_uint(ts) & 0xFFFFFFF0u) | slot;
                        sIdx[vb + slot] = __float_as_int(pr.y);
                        unsigned mmax = 0u;
                        const uint4* vp = (const uint4*)(sVal + vb);
#pragma unroll
                        for (int s4 = 0; s4 < 4; s4++) {
                            uint4 v = vp[s4];
                            mmax = max(mmax, max(max(v.x, v.y), max(v.z, v.w)));
                        }
                        worstP = mmax;
                        thr = __uint_as_float(mmax & 0xFFFFFFF0u) - qw;
                    }
                }
                cnt = 0;
            }
        }
    }

    // final flush of buffered candidates
#pragma unroll 1
    for (int e = 0; e < cnt; e++) {
        float2 pr = sBuf[bbuf + e];
        if (pr.x < thr) {
            float ts = fmaxf(pr.x + qw, 0.f);
            unsigned slot = worstP & 0xFu;
            sVal[vb + slot] = (__float_as_uint(ts) & 0xFFFFFFF0u) | slot;
            sIdx[vb + slot] = __float_as_int(pr.y);
            unsigned mmax = 0u;
            const uint4* vp = (const uint4*)(sVal + vb);
#pragma unroll
            for (int s4 = 0; s4 < 4; s4++) {
                uint4 v = vp[s4];
                mmax = max(mmax, max(max(v.x, v.y), max(v.z, v.w)));
            }
            worstP = mmax;
            thr = __uint_as_float(mmax & 0xFFFFFFF0u) - qw;
        }
    }

    __syncthreads();
    if (wid == 0) {
        float thrts = __uint_as_float(worstP & 0xFFFFFFF0u);
#pragma unroll 1
        for (int w = 1; w < NWARP; w++) {
            int pb = (w * 32 + lane) * VST;
#pragma unroll
            for (int s = 0; s < 16; s++) {
                unsigned pv = sVal[pb + s];
                float pvts = __uint_as_float(pv & 0xFFFFFFF0u);
                if (pvts < thrts) {
                    unsigned slot = worstP & 0xFu;
                    sVal[vb + slot] = (pv & 0xFFFFFFF0u) | slot;
                    sIdx[vb + slot] = sIdx[pb + s];
                    unsigned mmax = 0u;
                    const uint4* vp = (const uint4*)(sVal + vb);
#pragma unroll
                    for (int s4 = 0; s4 < 4; s4++) {
                        uint4 v = vp[s4];
                        mmax = max(mmax, max(max(v.x, v.y), max(v.z, v.w)));
                    }
                    worstP = mmax;
                    thrts = __uint_as_float(mmax & 0xFFFFFFF0u);
                }
            }
        }
#pragma unroll
        for (int s = 0; s < 16; s++) g_NB[p * KK + s] = sIdx[vb + s];
    }
}

// ---------------- k2: per-point transforms, 3 passes of 64 outs -----------------
__global__ void __launch_bounds__(256) k2(const float* __restrict__ feats,
                   const float* __restrict__ W1, const float* __restrict__ b1,
                   const float* __restrict__ Wv, const float* __restrict__ bv) {
    __shared__ float sW[64][64];
    __shared__ float sF[64][64];
    int tid = threadIdx.x;
    int blk = blockIdx.x;
    int b   = blk >> 7;
    int n0  = (blk & 127) << 6;

    for (int e = tid; e < 1024; e += 256) {
        int c = e >> 4, v4 = e & 15;
        ((float4*)sF[c])[v4] =
            ((const float4*)(feats + (size_t)b * CC * NN + (size_t)c * NN + n0))[v4];
    }

    int og = tid & 15, ng = tid >> 4;

    for (int pp = 0; pp < 3; pp++) {
        __syncthreads();
        for (int e = tid; e < 4096; e += 256) {
            int ol = e & 63, c = e >> 6;
            float w;
            if (pp == 0)      w = W1[ol * 131 + c];
            else if (pp == 1) w = W1[ol * 131 + 64 + c];
            else              w = Wv[ol * 67 + c];
            sW[c][ol] = w;
        }
        __syncthreads();

        float4 a0 = make_float4(0.f,0.f,0.f,0.f), a1 = a0, a2 = a0, a3 = a0;
        for (int c = 0; c < 64; c++) {
            float4 w4 = *(const float4*)&sW[c][og * 4];
            float4 f4 = *(const float4*)&sF[c][ng * 4];
            a0.x = fmaf(w4.x, f4.x, a0.x); a0.y = fmaf(w4.y, f4.x, a0.y);
            a0.z = fmaf(w4.z, f4.x, a0.z); a0.w = fmaf(w4.w, f4.x, a0.w);
            a1.x = fmaf(w4.x, f4.y, a1.x); a1.y = fmaf(w4.y, f4.y, a1.y);
            a1.z = fmaf(w4.z, f4.y, a1.z); a1.w = fmaf(w4.w, f4.y, a1.w);
            a2.x = fmaf(w4.x, f4.z, a2.x); a2.y = fmaf(w4.y, f4.z, a2.y);
            a2.z = fmaf(w4.z, f4.z, a2.z); a2.w = fmaf(w4.w, f4.z, a2.w);
            a3.x = fmaf(w4.x, f4.w, a3.x); a3.y = fmaf(w4.y, f4.w, a3.y);
            a3.z = fmaf(w4.z, f4.w, a3.z); a3.w = fmaf(w4.w, f4.w, a3.w);
        }

        float4 bb = make_float4(0.f, 0.f, 0.f, 0.f);
        if (pp == 0) bb = *(const float4*)(b1 + og * 4);
        if (pp == 2) bb = *(const float4*)(bv + og * 4);
        int obase = pp * 64 + og * 4;
        float4 r;
        size_t pbase = (size_t)(b * NN + n0 + ng * 4);
        r = make_float4(a0.x+bb.x, a0.y+bb.y, a0.z+bb.z, a0.w+bb.w);
        *(float4*)(g_PT + (pbase + 0) * 192 + obase) = r;
        r = make_float4(a1.x+bb.x, a1.y+bb.y, a1.z+bb.z, a1.w+bb.w);
        *(float4*)(g_PT + (pbase + 1) * 192 + obase) = r;
        r = make_float4(a2.x+bb.x, a2.y+bb.y, a2.z+bb.z, a2.w+bb.w);
        *(float4*)(g_PT + (pbase + 2) * 192 + obase) = r;
        r = make_float4(a3.x+bb.x, a3.y+bb.y, a3.z+bb.z, a3.w+bb.w);
        *(float4*)(g_PT + (pbase + 3) * 192 + obase) = r;
    }
}

// ---------------- k3: BN stats for h and v (f32x2, channel pairs) ---------------
__global__ void __launch_bounds__(256) k3(const float* __restrict__ W1,
                                          const float* __restrict__ Wv) {
    __shared__ float sstat[256];
    int tid = threadIdx.x, lane = tid & 31, wid = tid >> 5;
    for (int e = tid; e < 256; e += 256) sstat[e] = 0.f;
    __syncthreads();

    int cc = lane * 2;   // channels cc, cc+1
    u64 w1x0 = pkab(W1[cc * 131 + 128], W1[(cc + 1) * 131 + 128]);
    u64 w1x1 = pkab(W1[cc * 131 + 129], W1[(cc + 1) * 131 + 129]);
    u64 w1x2 = pkab(W1[cc * 131 + 130], W1[(cc + 1) * 131 + 130]);
    u64 wvx0 = pkab(Wv[cc * 67 + 64],  Wv[(cc + 1) * 67 + 64]);
    u64 wvx1 = pkab(Wv[cc * 67 + 65],  Wv[(cc + 1) * 67 + 65]);
    u64 wvx2 = pkab(Wv[cc * 67 + 66],  Wv[(cc + 1) * 67 + 66]);

    u64 sh = 0, shq = 0, sv = 0, svq = 0;
    int gw = blockIdx.x * 8 + wid, nw = gridDim.x * 8;
    for (int p = gw; p < NPTS; p += nw) {
        int b = p >> 13;
        float4 q = g_P4[p];
        const int4* nb = (const int4*)(g_NB + p * KK);
        int4 iA = nb[0], iB = nb[1], iC = nb[2], iD = nb[3];
        int mi[16] = {iA.x, iA.y, iA.z, iA.w, iB.x, iB.y, iB.z, iB.w,
                      iC.x, iC.y, iC.z, iC.w, iD.x, iD.y, iD.z, iD.w};
        const float* ptp = g_PT + (size_t)p * 192;
        u64 hcp = *(const u64*)(ptp + cc);
#pragma unroll
        for (int k = 0; k < KK; k++) {
            int m = mi[k];
            float4 pm = g_P4[b * NN + m];
            u64 rxp = pk2(pm.x - q.x), ryp = pk2(pm.y - q.y), rzp = pk2(pm.z - q.z);
            const float* ptm = g_PT + (size_t)(b * NN + m) * 192;
            u64 hnp = *(const u64*)(ptm + 64 + cc);
            u64 vnp = *(const u64*)(ptm + 128 + cc);
            u64 h = fma2(rzp, w1x2, fma2(ryp, w1x1, fma2(rxp, w1x0, add2(hcp, hnp))));
            u64 v = fma2(rzp, wvx2, fma2(ryp, wvx1, fma2(rxp, wvx0, vnp)));
            sh = add2(sh, h); shq = fma2(h, h, shq);
            sv = add2(sv, v); svq = fma2(v, v, svq);
        }
    }
    float2 fsh = unpk(sh), fshq = unpk(shq), fsv = unpk(sv), fsvq = unpk(svq);
    atomicAdd(&sstat[cc], fsh.x);       atomicAdd(&sstat[cc + 1], fsh.y);
    atomicAdd(&sstat[64 + cc], fshq.x); atomicAdd(&sstat[64 + cc + 1], fshq.y);
    atomicAdd(&sstat[128 + cc], fsv.x); atomicAdd(&sstat[128 + cc + 1], fsv.y);
    atomicAdd(&sstat[192 + cc], fsvq.x);atomicAdd(&sstat[192 + cc + 1], fsvq.y);
    __syncthreads();
    for (int e = tid; e < 256; e += 256) atomicAdd(&g_stats[e], sstat[e]);
}

// ---------------- k4: stats -> BN coefficients ----------------------------------
__global__ void k4(const float* __restrict__ g1, const float* __restrict__ be1,
                   const float* __restrict__ gv, const float* __restrict__ bev) {
    int c = threadIdx.x;
    float cnt = (float)((size_t)NPTS * KK);
    float mh = g_stats[c] / cnt;
    float vh = g_stats[64 + c] / cnt - mh * mh;
    float a1 = g1[c] * rsqrtf(vh + 1e-5f);
    g_coef1[c] = a1; g_coef1[64 + c] = be1[c] - a1 * mh;
    float mv = g_stats[128 + c] / cnt;
    float vv = g_stats[192 + c] / cnt - mv * mv;
    float av = gv[c] * rsqrtf(vv + 1e-5f);
    g_coef1[128 + c] = av; g_coef1[192 + c] = bev[c] - av * mv;
}

// ---------------- k5: attention + value + weighted sum + out-conv ---------------
__global__ void __launch_bounds__(256) k5(const float* __restrict__ W1,
                   const float* __restrict__ Wv,
                   const float* __restrict__ W2, const float* __restrict__ b2,
                   const float* __restrict__ Wo, const float* __restrict__ bo) {
    __shared__ float sWo[64][65];
    __shared__ float sOut[8][64];
    __shared__ float sstat[128];
    int tid = threadIdx.x, lane = tid & 31, wid = tid >> 5;

    for (int e = tid; e < 64 * 64; e += 256) {
        int j = e >> 6, c = e & 63;
        sWo[j][c] = Wo[c * 64 + j];
    }
    for (int e = tid; e < 128; e += 256) sstat[e] = 0.f;

    int cc = lane * 2;
    u64 w1x0 = pkab(W1[cc * 131 + 128], W1[(cc + 1) * 131 + 128]);
    u64 w1x1 = pkab(W1[cc * 131 + 129], W1[(cc + 1) * 131 + 129]);
    u64 w1x2 = pkab(W1[cc * 131 + 130], W1[(cc + 1) * 131 + 130]);
    u64 wvx0 = pkab(Wv[cc * 67 + 64],  Wv[(cc + 1) * 67 + 64]);
    u64 wvx1 = pkab(Wv[cc * 67 + 65],  Wv[(cc + 1) * 67 + 65]);
    u64 wvx2 = pkab(Wv[cc * 67 + 66],  Wv[(cc + 1) * 67 + 66]);
    float a1a = g_coef1[cc],      a1b = g_coef1[cc + 1];
    float d1a = g_coef1[64 + cc], d1b = g_coef1[64 + cc + 1];
    float ava = g_coef1[128 + cc], avb = g_coef1[128 + cc + 1];
    float dva = g_coef1[192 + cc], dvb = g_coef1[192 + cc + 1];
    float w2a = W2[cc], w2b = W2[cc + 1];
    float b2v = b2[0];
    float boa = bo[cc], bob = bo[cc + 1];
    __syncthreads();

    float so1 = 0.f, so1q = 0.f, so2 = 0.f, so2q = 0.f;
    int gw = blockIdx.x * 8 + wid, nw = gridDim.x * 8;

    for (int p = gw; p < NPTS; p += nw) {
        int b = p >> 13;
        float4 q = g_P4[p];
        const int4* nb = (const int4*)(g_NB + p * KK);
        int4 iA = nb[0], iB = nb[1], iC = nb[2], iD = nb[3];
        int mi[16] = {iA.x, iA.y, iA.z, iA.w, iB.x, iB.y, iB.z, iB.w,
                      iC.x, iC.y, iC.z, iC.w, iD.x, iD.y, iD.z, iD.w};
        const float* ptp = g_PT + (size_t)p * 192;
        u64 hcp = *(const u64*)(ptp + cc);

        float logits[KK], vv1[KK], vv2[KK];
#pragma unroll
        for (int k = 0; k < KK; k++) {
            int m = mi[k];
            float4 pm = g_P4[b * NN + m];
            u64 rxp = pk2(pm.x - q.x), ryp = pk2(pm.y - q.y), rzp = pk2(pm.z - q.z);
            const float* ptm = g_PT + (size_t)(b * NN + m) * 192;
            u64 hnp = *(const u64*)(ptm + 64 + cc);
            u64 vnp = *(const u64*)(ptm + 128 + cc);
            u64 h = fma2(rzp, w1x2, fma2(ryp, w1x1, fma2(rxp, w1x0, add2(hcp, hnp))));
            u64 v = fma2(rzp, wvx2, fma2(ryp, wvx1, fma2(rxp, wvx0, vnp)));
            float2 hf = unpk(h), vf = unpk(v);
            float hb1 = fmaxf(a1a * hf.x + d1a, 0.f);
            float hb2 = fmaxf(a1b * hf.y + d1b, 0.f);
            vv1[k] = fmaxf(ava * vf.x + dva, 0.f);
            vv2[k] = fmaxf(avb * vf.y + dvb, 0.f);
            float t = hb1 * w2a + hb2 * w2b;
#pragma unroll
            for (int off = 16; off > 0; off >>= 1) t += __shfl_xor_sync(0xffffffffu, t, off);
            logits[k] = t + b2v;
        }
        float mx = logits[0];
#pragma unroll
        for (int k = 1; k < KK; k++) mx = fmaxf(mx, logits[k]);
        float ex[KK], se = 0.f;
#pragma unroll
        for (int k = 0; k < KK; k++) { ex[k] = __expf(logits[k] - mx); se += ex[k]; }
        float inv = 1.0f / se;
        float out1 = 0.f, out2 = 0.f;
#pragma unroll
        for (int k = 0; k < KK; k++) {
            float w = ex[k] * inv;
            out1 += w * vv1[k];
            out2 += w * vv2[k];
        }
        __syncwarp();
        sOut[wid][cc] = out1; sOut[wid][cc + 1] = out2;
        __syncwarp();
        float oo1 = boa, oo2 = bob;
#pragma unroll 8
        for (int j = 0; j < 64; j++) {
            float oj = sOut[wid][j];
            oo1 = fmaf(sWo[j][cc], oj, oo1);
            oo2 = fmaf(sWo[j][cc + 1], oj, oo2);
        }
        g_Opre[(size_t)p * 64 + cc] = oo1;
        g_Opre[(size_t)p * 64 + cc + 1] = oo2;
        so1 += oo1; so1q += oo1 * oo1;
        so2 += oo2; so2q += oo2 * oo2;
    }
    atomicAdd(&sstat[cc], so1);     atomicAdd(&sstat[64 + cc], so1q);
    atomicAdd(&sstat[cc + 1], so2); atomicAdd(&sstat[64 + cc + 1], so2q);
    __syncthreads();
    for (int e = tid; e < 128; e += 256) atomicAdd(&g_ostats[e], sstat[e]);
}

// ---------------- k6 ------------------------------------------------------------
__global__ void k6(const float* __restrict__ go, const float* __restrict__ beo) {
    int c = threadIdx.x;
    float cnt = (float)NPTS;
    float m = g_ostats[c] / cnt;
    float v = g_ostats[64 + c] / cnt - m * m;
    float a = go[c] * rsqrtf(v + 1e-5f);
    g_ocoef[c] = a; g_ocoef[64 + c] = beo[c] - a * m;
}

// ---------------- k7: BN + relu + residual + transpose --------------------------
__global__ void k7(const float* __restrict__ feats, float* __restrict__ out) {
    __shared__ float tile[32][65];
    int blk = blockIdx.x;
    int b = blk >> 8;
    int n0 = (blk & 255) << 5;
    int tid = threadIdx.x;
    for (int e = tid; e < 32 * 64; e += 256) {
        int pp = e >> 6, c = e & 63;
        tile[pp][c] = g_Opre[(size_t)(b * NN + n0 + pp) * 64 + c];
    }
    __syncthreads();
    for (int e = tid; e < 64 * 32; e += 256) {
        int c = e >> 5, j = e & 31;
        float val = g_ocoef[c] * tile[j][c] + g_ocoef[64 + c];
        val = fmaxf(val, 0.f) + feats[(size_t)b * CC * NN + (size_t)c * NN + n0 + j];
        out[(size_t)b * CC * NN + (size_t)c * NN + n0 + j] = val;
    }
}

// ---------------- launch --------------------------------------------------------
extern "C" void kernel_launch(void* const* d_in, const int* in_sizes, int n_in,
                              void* d_out, int out_size) {
    const float* xyz   = (const float*)d_in[0];
    const float* feats = (const float*)d_in[1];
    const float* W1    = (const float*)d_in[2];
    const float* b1    = (const float*)d_in[3];
    const float* g1    = (const float*)d_in[4];
    const float* be1   = (const float*)d_in[5];
    const float* W2    = (const float*)d_in[6];
    const float* b2    = (const float*)d_in[7];
    const float* Wv    = (const float*)d_in[8];
    const float* bv    = (const float*)d_in[9];
    const float* gv    = (const float*)d_in[10];
    const float* bev   = (const float*)d_in[11];
    const float* Wo    = (const float*)d_in[12];
    const float* bo    = (const float*)d_in[13];
    const float* go    = (const float*)d_in[14];
    const float* beo   = (const float*)d_in[15];
    float* out = (float*)d_out;

    k0<<<NPTS / 256, 256>>>(xyz);
    k1<<<NPTS / 32, 128>>>();
    k2<<<NPTS / 64, 256>>>(feats, W1, b1, Wv, bv);
    k3<<<1184, 256>>>(W1, Wv);
    k4<<<1, 64>>>(g1, be1, gv, bev);
    k5<<<1184, 256>>>(W1, Wv, W2, b2, Wo, bo);
    k6<<<1, 64>>>(go, beo);
    k7<<<NPTS / 32, 256>>>(feats, out);
}

// round 9
// speedup vs baseline: 3.7379x; 1.0302x over previous
#include <cuda_runtime.h>
#include <cfloat>
#include <math.h>

#define BB 4
#define NN 8192
#define CC 64
#define KK 16
#define HH 64
#define NPTS (BB*NN)

// ---------------- device scratch ------------------------------------------------
__device__ float4 g_P4[NPTS];                    // (x,y,z,|p|^2)
__device__ float  g_Sx[NPTS], g_Sy[NPTS], g_Sz[NPTS], g_Sq[NPTS];  // SoA coords
__device__ float  g_PT[(size_t)NPTS*192];        // [hc+b1 (64) | hn (64) | vn+bv (64)]
__device__ int    g_NB[NPTS*KK];                 // knn indices
__device__ float  g_stats[256];
__device__ float  g_ostats[128];
__device__ float  g_Opre[(size_t)NPTS*64];

// ---------------- f32x2 helpers -------------------------------------------------
typedef unsigned long long u64;
__device__ __forceinline__ u64 fma2(u64 a, u64 b, u64 c) {
    u64 d; asm("fma.rn.f32x2 %0,%1,%2,%3;" : "=l"(d) : "l"(a), "l"(b), "l"(c));
    return d;
}
__device__ __forceinline__ u64 add2(u64 a, u64 b) {
    u64 d; asm("add.rn.f32x2 %0,%1,%2;" : "=l"(d) : "l"(a), "l"(b));
    return d;
}
__device__ __forceinline__ u64 pk2(float v) {
    u64 d; asm("mov.b64 %0,{%1,%1};" : "=l"(d) : "f"(v));
    return d;
}
__device__ __forceinline__ u64 pkab(float a, float b) {
    u64 d; asm("mov.b64 %0,{%1,%2};" : "=l"(d) : "f"(a), "f"(b));
    return d;
}
__device__ __forceinline__ float2 unpk(u64 v) {
    float2 r; asm("mov.b64 {%0,%1},%2;" : "=f"(r.x), "=f"(r.y) : "l"(v));
    return r;
}

// ---------------- k0: pack xyz (AoS + SoA) + zero stats -------------------------
__global__ void k0(const float* __restrict__ xyz) {
    int p = blockIdx.x * blockDim.x + threadIdx.x;
    if (p < 256) g_stats[p] = 0.f;
    if (p < 128) g_ostats[p] = 0.f;
    if (p >= NPTS) return;
    int b = p >> 13, n = p & (NN - 1);
    const float* base = xyz + (size_t)b * 3 * NN + n;
    float x = base[0], y = base[NN], z = base[2 * NN];
    float w = x * x + y * y + z * z;
    g_P4[p] = make_float4(x, y, z, w);
    g_Sx[p] = x; g_Sy[p] = y; g_Sz[p] = z; g_Sq[p] = w;
}

// ---------------- k1: KNN, 4 warps split candidate range ------------------------
#define NWARP 4
#define RANGE 2048
#define TSH 128
#define BS  13      // odd -> no worse than natural 2-phase 64b smem access
#define VST 20      // top16 list stride (ints); 80B -> 16B-aligned LDS.128
__global__ void __launch_bounds__(128) k1() {
    __shared__ __align__(16) float sX[NWARP][TSH];
    __shared__ __align__(16) float sY[NWARP][TSH];
    __shared__ __align__(16) float sZ[NWARP][TSH];
    __shared__ __align__(16) float sWW[NWARP][TSH];
    __shared__ __align__(16) unsigned sVal[NWARP * 32 * VST];
    __shared__ int      sIdx[NWARP * 32 * VST];
    __shared__ __align__(8) float2 sBuf[NWARP * 32 * BS];

    int lane = threadIdx.x & 31;
    int wid  = threadIdx.x >> 5;
    int blk  = blockIdx.x;                // 1024 blocks
    int b    = blk >> 8;                  // 256 blocks per batch
    int n    = ((blk & 255) << 5) + lane;
    int p    = b * NN + n;

    float4 q = g_P4[p];
    float qw = q.w;
    u64 m2x = pk2(-2.f * q.x), m2y = pk2(-2.f * q.y), m2z = pk2(-2.f * q.z);

    int vb = (wid * 32 + lane) * VST;
    int bbuf = (wid * 32 + lane) * BS;
#pragma unroll
    for (int s = 0; s < 16; s++) {
        sVal[vb + s] = 0x7F7FFFF0u | (unsigned)s;
        sIdx[vb + s] = 0;
    }
    unsigned worstP = 0x7F7FFFFFu;
    float thr = __uint_as_float(0x7F7FFFF0u) - qw;   // t-domain threshold
    int cnt = 0;

    int cbase = wid * RANGE;
    for (int t0 = 0; t0 < RANGE; t0 += TSH) {
        __syncwarp();
        const float* bx = g_Sx + b * NN + cbase + t0;
        const float* by = g_Sy + b * NN + cbase + t0;
        const float* bz = g_Sz + b * NN + cbase + t0;
        const float* bw = g_Sq + b * NN + cbase + t0;
        {
            int o = lane * 4;
            *(float4*)(sX[wid]  + o) = *(const float4*)(bx + o);
            *(float4*)(sY[wid]  + o) = *(const float4*)(by + o);
            *(float4*)(sZ[wid]  + o) = *(const float4*)(bz + o);
            *(float4*)(sWW[wid] + o) = *(const float4*)(bw + o);
        }
        __syncwarp();

        for (int j = 0; j < TSH; j += 8) {
            ulonglong2 X0 = *(const ulonglong2*)(sX[wid]  + j);
            ulonglong2 Y0 = *(const ulonglong2*)(sY[wid]  + j);
            ulonglong2 Z0 = *(const ulonglong2*)(sZ[wid]  + j);
            ulonglong2 W0 = *(const ulonglong2*)(sWW[wid] + j);
            ulonglong2 X1 = *(const ulonglong2*)(sX[wid]  + j + 4);
            ulonglong2 Y1 = *(const ulonglong2*)(sY[wid]  + j + 4);
            ulonglong2 Z1 = *(const ulonglong2*)(sZ[wid]  + j + 4);
            ulonglong2 W1 = *(const ulonglong2*)(sWW[wid] + j + 4);
            u64 t0a = fma2(Z0.x, m2z, fma2(Y0.x, m2y, fma2(X0.x, m2x, W0.x)));
            u64 t0b = fma2(Z0.y, m2z, fma2(Y0.y, m2y, fma2(X0.y, m2x, W0.y)));
            u64 t1a = fma2(Z1.x, m2z, fma2(Y1.x, m2y, fma2(X1.x, m2x, W1.x)));
            u64 t1b = fma2(Z1.y, m2z, fma2(Y1.y, m2y, fma2(X1.y, m2x, W1.y)));
            float2 f01 = unpk(t0a), f23 = unpk(t0b), f45 = unpk(t1a), f67 = unpk(t1b);
            float m01 = fminf(f01.x, f01.y), m23 = fminf(f23.x, f23.y);
            float m45 = fminf(f45.x, f45.y), m67 = fminf(f67.x, f67.y);
            float mm = fminf(fminf(m01, m23), fminf(m45, m67));
            if (mm < thr) {
                float tt[8] = {f01.x, f01.y, f23.x, f23.y, f45.x, f45.y, f67.x, f67.y};
                int ib = cbase + t0 + j;
#pragma unroll
                for (int uu = 0; uu < 8; uu++) {
                    // unconditional store is safe: cnt only advances on pass
                    sBuf[bbuf + cnt] = make_float2(tt[uu], __int_as_float(ib + uu));
                    cnt += (tt[uu] < thr) ? 1 : 0;
                }
            }
            if (__any_sync(0xffffffffu, cnt >= BS - 7)) {
#pragma unroll 1
                for (int e = 0; e < cnt; e++) {
                    float2 pr = sBuf[bbuf + e];
                    if (pr.x < thr) {
                        float ts = fmaxf(pr.x + qw, 0.f);
                        unsigned slot = worstP & 0xFu;
                        sVal[vb + slot] = (__float_as_uint(ts) & 0xFFFFFFF0u) | slot;
                        sIdx[vb + slot] = __float_as_int(pr.y);
                        unsigned mmax = 0u;
                        const uint4* vp = (const uint4*)(sVal + vb);
#pragma unroll
                        for (int s4 = 0; s4 < 4; s4++) {
                            uint4 v = vp[s4];
                            mmax = max(mmax, max(max(v.x, v.y), max(v.z, v.w)));
                        }
                        worstP = mmax;
                        thr = __uint_as_float(mmax & 0xFFFFFFF0u) - qw;
                    }
                }
                cnt = 0;
            }
        }
    }

    // final flush of buffered candidates
#pragma unroll 1
    for (int e = 0; e < cnt; e++) {
        float2 pr = sBuf[bbuf + e];
        if (pr.x < thr) {
            float ts = fmaxf(pr.x + qw, 0.f);
            unsigned slot = worstP & 0xFu;
            sVal[vb + slot] = (__float_as_uint(ts) & 0xFFFFFFF0u) | slot;
            sIdx[vb + slot] = __float_as_int(pr.y);
            unsigned mmax = 0u;
            const uint4* vp = (const uint4*)(sVal + vb);
#pragma unroll
            for (int s4 = 0; s4 < 4; s4++) {
                uint4 v = vp[s4];
                mmax = max(mmax, max(max(v.x, v.y), max(v.z, v.w)));
            }
            worstP = mmax;
            thr = __uint_as_float(mmax & 0xFFFFFFF0u) - qw;
        }
    }

    // tree merge: round 1: w0<-w2, w1<-w3 ; round 2: w0<-w1
    float thrts = __uint_as_float(worstP & 0xFFFFFFF0u);
    __syncthreads();
    if (wid < 2) {
        int pb = ((wid + 2) * 32 + lane) * VST;
#pragma unroll
        for (int s = 0; s < 16; s++) {
            unsigned pv = sVal[pb + s];
            float pvts = __uint_as_float(pv & 0xFFFFFFF0u);
            if (pvts < thrts) {
                unsigned slot = worstP & 0xFu;
                sVal[vb + slot] = (pv & 0xFFFFFFF0u) | slot;
                sIdx[vb + slot] = sIdx[pb + s];
                unsigned mmax = 0u;
                const uint4* vp = (const uint4*)(sVal + vb);
#pragma unroll
                for (int s4 = 0; s4 < 4; s4++) {
                    uint4 v = vp[s4];
                    mmax = max(mmax, max(max(v.x, v.y), max(v.z, v.w)));
                }
                worstP = mmax;
                thrts = __uint_as_float(mmax & 0xFFFFFFF0u);
            }
        }
    }
    __syncthreads();
    if (wid == 0) {
        int pb = (32 + lane) * VST;
#pragma unroll
        for (int s = 0; s < 16; s++) {
            unsigned pv = sVal[pb + s];
            float pvts = __uint_as_float(pv & 0xFFFFFFF0u);
            if (pvts < thrts) {
                unsigned slot = worstP & 0xFu;
                sVal[vb + slot] = (pv & 0xFFFFFFF0u) | slot;
                sIdx[vb + slot] = sIdx[pb + s];
                unsigned mmax = 0u;
                const uint4* vp = (const uint4*)(sVal + vb);
#pragma unroll
                for (int s4 = 0; s4 < 4; s4++) {
                    uint4 v = vp[s4];
                    mmax = max(mmax, max(max(v.x, v.y), max(v.z, v.w)));
                }
                worstP = mmax;
                thrts = __uint_as_float(mmax & 0xFFFFFFF0u);
            }
        }
#pragma unroll
        for (int s = 0; s < 16; s++) g_NB[p * KK + s] = sIdx[vb + s];
    }
}

// ---------------- k2: per-point transforms, 3 passes of 64 outs -----------------
__global__ void __launch_bounds__(256) k2(const float* __restrict__ feats,
                   const float* __restrict__ W1, const float* __restrict__ b1,
                   const float* __restrict__ Wv, const float* __restrict__ bv) {
    __shared__ float sW[64][64];
    __shared__ float sF[64][64];
    int tid = threadIdx.x;
    int blk = blockIdx.x;
    int b   = blk >> 7;
    int n0  = (blk & 127) << 6;

    for (int e = tid; e < 1024; e += 256) {
        int c = e >> 4, v4 = e & 15;
        ((float4*)sF[c])[v4] =
            ((const float4*)(feats + (size_t)b * CC * NN + (size_t)c * NN + n0))[v4];
    }

    int og = tid & 15, ng = tid >> 4;

    for (int pp = 0; pp < 3; pp++) {
        __syncthreads();
        for (int e = tid; e < 4096; e += 256) {
            int ol = e & 63, c = e >> 6;
            float w;
            if (pp == 0)      w = W1[ol * 131 + c];
            else if (pp == 1) w = W1[ol * 131 + 64 + c];
            else              w = Wv[ol * 67 + c];
            sW[c][ol] = w;
        }
        __syncthreads();

        float4 a0 = make_float4(0.f,0.f,0.f,0.f), a1 = a0, a2 = a0, a3 = a0;
        for (int c = 0; c < 64; c++) {
            float4 w4 = *(const float4*)&sW[c][og * 4];
            float4 f4 = *(const float4*)&sF[c][ng * 4];
            a0.x = fmaf(w4.x, f4.x, a0.x); a0.y = fmaf(w4.y, f4.x, a0.y);
            a0.z = fmaf(w4.z, f4.x, a0.z); a0.w = fmaf(w4.w, f4.x, a0.w);
            a1.x = fmaf(w4.x, f4.y, a1.x); a1.y = fmaf(w4.y, f4.y, a1.y);
            a1.z = fmaf(w4.z, f4.y, a1.z); a1.w = fmaf(w4.w, f4.y, a1.w);
            a2.x = fmaf(w4.x, f4.z, a2.x); a2.y = fmaf(w4.y, f4.z, a2.y);
            a2.z = fmaf(w4.z, f4.z, a2.z); a2.w = fmaf(w4.w, f4.z, a2.w);
            a3.x = fmaf(w4.x, f4.w, a3.x); a3.y = fmaf(w4.y, f4.w, a3.y);
            a3.z = fmaf(w4.z, f4.w, a3.z); a3.w = fmaf(w4.w, f4.w, a3.w);
        }

        float4 bb = make_float4(0.f, 0.f, 0.f, 0.f);
        if (pp == 0) bb = *(const float4*)(b1 + og * 4);
        if (pp == 2) bb = *(const float4*)(bv + og * 4);
        int obase = pp * 64 + og * 4;
        float4 r;
        size_t pbase = (size_t)(b * NN + n0 + ng * 4);
        r = make_float4(a0.x+bb.x, a0.y+bb.y, a0.z+bb.z, a0.w+bb.w);
        *(float4*)(g_PT + (pbase + 0) * 192 + obase) = r;
        r = make_float4(a1.x+bb.x, a1.y+bb.y, a1.z+bb.z, a1.w+bb.w);
        *(float4*)(g_PT + (pbase + 1) * 192 + obase) = r;
        r = make_float4(a2.x+bb.x, a2.y+bb.y, a2.z+bb.z, a2.w+bb.w);
        *(float4*)(g_PT + (pbase + 2) * 192 + obase) = r;
        r = make_float4(a3.x+bb.x, a3.y+bb.y, a3.z+bb.z, a3.w+bb.w);
        *(float4*)(g_PT + (pbase + 3) * 192 + obase) = r;
    }
}

// ---------------- k3: BN stats for h and v (f32x2, channel pairs) ---------------
__global__ void __launch_bounds__(256) k3(const float* __restrict__ W1,
                                          const float* __restrict__ Wv) {
    __shared__ float sstat[256];
    int tid = threadIdx.x, lane = tid & 31, wid = tid >> 5;
    for (int e = tid; e < 256; e += 256) sstat[e] = 0.f;
    __syncthreads();

    int cc = lane * 2;   // channels cc, cc+1
    u64 w1x0 = pkab(W1[cc * 131 + 128], W1[(cc + 1) * 131 + 128]);
    u64 w1x1 = pkab(W1[cc * 131 + 129], W1[(cc + 1) * 131 + 129]);
    u64 w1x2 = pkab(W1[cc * 131 + 130], W1[(cc + 1) * 131 + 130]);
    u64 wvx0 = pkab(Wv[cc * 67 + 64],  Wv[(cc + 1) * 67 + 64]);
    u64 wvx1 = pkab(Wv[cc * 67 + 65],  Wv[(cc + 1) * 67 + 65]);
    u64 wvx2 = pkab(Wv[cc * 67 + 66],  Wv[(cc + 1) * 67 + 66]);

    u64 sh = 0, shq = 0, sv = 0, svq = 0;
    int gw = blockIdx.x * 8 + wid, nw = gridDim.x * 8;
    for (int p = gw; p < NPTS; p += nw) {
        int b = p >> 13;
        float4 q = g_P4[p];
        const int4* nb = (const int4*)(g_NB + p * KK);
        int4 iA = nb[0], iB = nb[1], iC = nb[2], iD = nb[3];
        int mi[16] = {iA.x, iA.y, iA.z, iA.w, iB.x, iB.y, iB.z, iB.w,
                      iC.x, iC.y, iC.z, iC.w, iD.x, iD.y, iD.z, iD.w};
        const float* ptp = g_PT + (size_t)p * 192;
        u64 hcp = *(const u64*)(ptp + cc);
#pragma unroll
        for (int k = 0; k < KK; k++) {
            int m = mi[k];
            float4 pm = g_P4[b * NN + m];
            u64 rxp = pk2(pm.x - q.x), ryp = pk2(pm.y - q.y), rzp = pk2(pm.z - q.z);
            const float* ptm = g_PT + (size_t)(b * NN + m) * 192;
            u64 hnp = *(const u64*)(ptm + 64 + cc);
            u64 vnp = *(const u64*)(ptm + 128 + cc);
            u64 h = fma2(rzp, w1x2, fma2(ryp, w1x1, fma2(rxp, w1x0, add2(hcp, hnp))));
            u64 v = fma2(rzp, wvx2, fma2(ryp, wvx1, fma2(rxp, wvx0, vnp)));
            sh = add2(sh, h); shq = fma2(h, h, shq);
            sv = add2(sv, v); svq = fma2(v, v, svq);
        }
    }
    float2 fsh = unpk(sh), fshq = unpk(shq), fsv = unpk(sv), fsvq = unpk(svq);
    atomicAdd(&sstat[cc], fsh.x);       atomicAdd(&sstat[cc + 1], fsh.y);
    atomicAdd(&sstat[64 + cc], fshq.x); atomicAdd(&sstat[64 + cc + 1], fshq.y);
    atomicAdd(&sstat[128 + cc], fsv.x); atomicAdd(&sstat[128 + cc + 1], fsv.y);
    atomicAdd(&sstat[192 + cc], fsvq.x);atomicAdd(&sstat[192 + cc + 1], fsvq.y);
    __syncthreads();
    for (int e = tid; e < 256; e += 256) atomicAdd(&g_stats[e], sstat[e]);
}

// ---------------- k5: attention + value + out-conv (BN coefs computed inline) ---
__global__ void __launch_bounds__(256) k5(const float* __restrict__ W1,
                   const float* __restrict__ Wv,
                   const float* __restrict__ W2, const float* __restrict__ b2,
                   const float* __restrict__ Wo, const float* __restrict__ bo,
                   const float* __restrict__ g1, const float* __restrict__ be1,
                   const float* __restrict__ gv, const float* __restrict__ bev) {
    __shared__ float sWo[64][65];
    __shared__ float sOut[8][64];
    __shared__ float sstat[128];
    int tid = threadIdx.x, lane = tid & 31, wid = tid >> 5;

    for (int e = tid; e < 64 * 64; e += 256) {
        int j = e >> 6, c = e & 63;
        sWo[j][c] = Wo[c * 64 + j];
    }
    for (int e = tid; e < 128; e += 256) sstat[e] = 0.f;

    int cc = lane * 2;
    u64 w1x0 = pkab(W1[cc * 131 + 128], W1[(cc + 1) * 131 + 128]);
    u64 w1x1 = pkab(W1[cc * 131 + 129], W1[(cc + 1) * 131 + 129]);
    u64 w1x2 = pkab(W1[cc * 131 + 130], W1[(cc + 1) * 131 + 130]);
    u64 wvx0 = pkab(Wv[cc * 67 + 64],  Wv[(cc + 1) * 67 + 64]);
    u64 wvx1 = pkab(Wv[cc * 67 + 65],  Wv[(cc + 1) * 67 + 65]);
    u64 wvx2 = pkab(Wv[cc * 67 + 66],  Wv[(cc + 1) * 67 + 66]);

    // BN coefficients computed from finalized g_stats (k4 folded in)
    float cntk = (float)((size_t)NPTS * KK);
    float mh1 = g_stats[cc] / cntk,     mh2 = g_stats[cc + 1] / cntk;
    float vh1 = g_stats[64 + cc] / cntk - mh1 * mh1;
    float vh2 = g_stats[64 + cc + 1] / cntk - mh2 * mh2;
    float a1a = g1[cc] * rsqrtf(vh1 + 1e-5f), a1b = g1[cc + 1] * rsqrtf(vh2 + 1e-5f);
    float d1a = be1[cc] - a1a * mh1,          d1b = be1[cc + 1] - a1b * mh2;
    float mv1 = g_stats[128 + cc] / cntk,     mv2 = g_stats[128 + cc + 1] / cntk;
    float vv1s = g_stats[192 + cc] / cntk - mv1 * mv1;
    float vv2s = g_stats[192 + cc + 1] / cntk - mv2 * mv2;
    float ava = gv[cc] * rsqrtf(vv1s + 1e-5f), avb = gv[cc + 1] * rsqrtf(vv2s + 1e-5f);
    float dva = bev[cc] - ava * mv1,           dvb = bev[cc + 1] - avb * mv2;

    float w2a = W2[cc], w2b = W2[cc + 1];
    float b2v = b2[0];
    float boa = bo[cc], bob = bo[cc + 1];
    __syncthreads();

    float so1 = 0.f, so1q = 0.f, so2 = 0.f, so2q = 0.f;
    int gw = blockIdx.x * 8 + wid, nw = gridDim.x * 8;

    for (int p = gw; p < NPTS; p += nw) {
        int b = p >> 13;
        float4 q = g_P4[p];
        const int4* nb = (const int4*)(g_NB + p * KK);
        int4 iA = nb[0], iB = nb[1], iC = nb[2], iD = nb[3];
        int mi[16] = {iA.x, iA.y, iA.z, iA.w, iB.x, iB.y, iB.z, iB.w,
                      iC.x, iC.y, iC.z, iC.w, iD.x, iD.y, iD.z, iD.w};
        const float* ptp = g_PT + (size_t)p * 192;
        u64 hcp = *(const u64*)(ptp + cc);

        float logits[KK], vv1[KK], vv2[KK];
#pragma unroll
        for (int k = 0; k < KK; k++) {
            int m = mi[k];
            float4 pm = g_P4[b * NN + m];
            u64 rxp = pk2(pm.x - q.x), ryp = pk2(pm.y - q.y), rzp = pk2(pm.z - q.z);
            const float* ptm = g_PT + (size_t)(b * NN + m) * 192;
            u64 hnp = *(const u64*)(ptm + 64 + cc);
            u64 vnp = *(const u64*)(ptm + 128 + cc);
            u64 h = fma2(rzp, w1x2, fma2(ryp, w1x1, fma2(rxp, w1x0, add2(hcp, hnp))));
            u64 v = fma2(rzp, wvx2, fma2(ryp, wvx1, fma2(rxp, wvx0, vnp)));
            float2 hf = unpk(h), vf = unpk(v);
            float hb1 = fmaxf(a1a * hf.x + d1a, 0.f);
            float hb2 = fmaxf(a1b * hf.y + d1b, 0.f);
            vv1[k] = fmaxf(ava * vf.x + dva, 0.f);
            vv2[k] = fmaxf(avb * vf.y + dvb, 0.f);
            float t = hb1 * w2a + hb2 * w2b;
#pragma unroll
            for (int off = 16; off > 0; off >>= 1) t += __shfl_xor_sync(0xffffffffu, t, off);
            logits[k] = t + b2v;
        }
        float mx = logits[0];
#pragma unroll
        for (int k = 1; k < KK; k++) mx = fmaxf(mx, logits[k]);
        float ex[KK], se = 0.f;
#pragma unroll
        for (int k = 0; k < KK; k++) { ex[k] = __expf(logits[k] - mx); se += ex[k]; }
        float inv = 1.0f / se;
        float out1 = 0.f, out2 = 0.f;
#pragma unroll
        for (int k = 0; k < KK; k++) {
            float w = ex[k] * inv;
            out1 += w * vv1[k];
            out2 += w * vv2[k];
        }
        __syncwarp();
        sOut[wid][cc] = out1; sOut[wid][cc + 1] = out2;
        __syncwarp();
        float oo1 = boa, oo2 = bob;
#pragma unroll 8
        for (int j = 0; j < 64; j++) {
            float oj = sOut[wid][j];
            oo1 = fmaf(sWo[j][cc], oj, oo1);
            oo2 = fmaf(sWo[j][cc + 1], oj, oo2);
        }
        g_Opre[(size_t)p * 64 + cc] = oo1;
        g_Opre[(size_t)p * 64 + cc + 1] = oo2;
        so1 += oo1; so1q += oo1 * oo1;
        so2 += oo2; so2q += oo2 * oo2;
    }
    atomicAdd(&sstat[cc], so1);     atomicAdd(&sstat[64 + cc], so1q);
    atomicAdd(&sstat[cc + 1], so2); atomicAdd(&sstat[64 + cc + 1], so2q);
    __syncthreads();
    for (int e = tid; e < 128; e += 256) atomicAdd(&g_ostats[e], sstat[e]);
}

// ---------------- k7: BN + relu + residual + transpose (k6 folded in) -----------
__global__ void k7(const float* __restrict__ feats, float* __restrict__ out,
                   const float* __restrict__ go, const float* __restrict__ beo) {
    __shared__ float tile[32][65];
    __shared__ float sco[128];
    int blk = blockIdx.x;
    int b = blk >> 8;
    int n0 = (blk & 255) << 5;
    int tid = threadIdx.x;
    if (tid < 64) {
        float cntp = (float)NPTS;
        float m = g_ostats[tid] / cntp;
        float v = g_ostats[64 + tid] / cntp - m * m;
        float a = go[tid] * rsqrtf(v + 1e-5f);
        sco[tid] = a; sco[64 + tid] = beo[tid] - a * m;
    }
    for (int e = tid; e < 32 * 64; e += 256) {
        int pp = e >> 6, c = e & 63;
        tile[pp][c] = g_Opre[(size_t)(b * NN + n0 + pp) * 64 + c];
    }
    __syncthreads();
    for (int e = tid; e < 64 * 32; e += 256) {
        int c = e >> 5, j = e & 31;
        float val = sco[c] * tile[j][c] + sco[64 + c];
        val = fmaxf(val, 0.f) + feats[(size_t)b * CC * NN + (size_t)c * NN + n0 + j];
        out[(size_t)b * CC * NN + (size_t)c * NN + n0 + j] = val;
    }
}

// ---------------- launch --------------------------------------------------------
extern "C" void kernel_launch(void* const* d_in, const int* in_sizes, int n_in,
                              void* d_out, int out_size) {
    const float* xyz   = (const float*)d_in[0];
    const float* feats = (const float*)d_in[1];
    const float* W1    = (const float*)d_in[2];
    const float* b1    = (const float*)d_in[3];
    const float* g1    = (const float*)d_in[4];
    const float* be1   = (const float*)d_in[5];
    const float* W2    = (const float*)d_in[6];
    const float* b2    = (const float*)d_in[7];
    const float* Wv    = (const float*)d_in[8];
    const float* bv    = (const float*)d_in[9];
    const float* gv    = (const float*)d_in[10];
    const float* bev   = (const float*)d_in[11];
    const float* Wo    = (const float*)d_in[12];
    const float* bo    = (const float*)d_in[13];
    const float* go    = (const float*)d_in[14];
    const float* beo   = (const float*)d_in[15];
    float* out = (float*)d_out;

    // lazily-created side stream + events (no device memory involved)
    static cudaStream_t s2 = nullptr;
    static cudaEvent_t evFork = nullptr, evJoin = nullptr;
    if (s2 == nullptr) {
        cudaStreamCreateWithFlags(&s2, cudaStreamNonBlocking);
        cudaEventCreateWithFlags(&evFork, cudaEventDisableTiming);
        cudaEventCreateWithFlags(&evJoin, cudaEventDisableTiming);
    }

    // fork: k2 (depends only on feats) runs concurrently with k0+k1
    cudaEventRecord(evFork, 0);
    cudaStreamWaitEvent(s2, evFork, 0);
    k2<<<NPTS / 64, 256, 0, s2>>>(feats, W1, b1, Wv, bv);
    cudaEventRecord(evJoin, s2);

    k0<<<NPTS / 256, 256>>>(xyz);
    k1<<<NPTS / 32, 128>>>();

    // join: k3 needs both k1 (g_NB) and k2 (g_PT)
    cudaStreamWaitEvent(0, evJoin, 0);
    k3<<<1184, 256>>>(W1, Wv);
    k5<<<1184, 256>>>(W1, Wv, W2, b2, Wo, bo, g1, be1, gv, bev);
    k7<<<NPTS / 32, 256>>>(feats, out, go, beo);
}

// round 13
// speedup vs baseline: 3.7525x; 1.0039x over previous
#include <cuda_runtime.h>
#include <cfloat>
#include <math.h>

#define BB 4
#define NN 8192
#define CC 64
#define KK 16
#define HH 64
#define NPTS (BB*NN)

// ---------------- device scratch ------------------------------------------------
__device__ float4 g_P4[NPTS];                    // (x,y,z,|p|^2)
__device__ float  g_Sx[NPTS], g_Sy[NPTS], g_Sz[NPTS], g_Sq[NPTS];  // SoA coords
__device__ float  g_PT[(size_t)NPTS*192];        // [hc+b1 (64) | hn (64) | vn+bv (64)]
__device__ int    g_NB[NPTS*KK];                 // knn indices
__device__ float  g_stats[256];
__device__ float  g_ostats[128];
__device__ float  g_Opre[(size_t)NPTS*64];

// ---------------- f32x2 helpers -------------------------------------------------
typedef unsigned long long u64;
__device__ __forceinline__ u64 fma2(u64 a, u64 b, u64 c) {
    u64 d; asm("fma.rn.f32x2 %0,%1,%2,%3;" : "=l"(d) : "l"(a), "l"(b), "l"(c));
    return d;
}
__device__ __forceinline__ u64 add2(u64 a, u64 b) {
    u64 d; asm("add.rn.f32x2 %0,%1,%2;" : "=l"(d) : "l"(a), "l"(b));
    return d;
}
__device__ __forceinline__ u64 pk2(float v) {
    u64 d; asm("mov.b64 %0,{%1,%1};" : "=l"(d) : "f"(v));
    return d;
}
__device__ __forceinline__ u64 pkab(float a, float b) {
    u64 d; asm("mov.b64 %0,{%1,%2};" : "=l"(d) : "f"(a), "f"(b));
    return d;
}
__device__ __forceinline__ float2 unpk(u64 v) {
    float2 r; asm("mov.b64 {%0,%1},%2;" : "=f"(r.x), "=f"(r.y) : "l"(v));
    return r;
}

// ---------------- k0: pack xyz (AoS + SoA) + zero stats -------------------------
__global__ void k0(const float* __restrict__ xyz) {
    int p = blockIdx.x * blockDim.x + threadIdx.x;
    if (p < 256) g_stats[p] = 0.f;
    if (p < 128) g_ostats[p] = 0.f;
    if (p >= NPTS) return;
    int b = p >> 13, n = p & (NN - 1);
    const float* base = xyz + (size_t)b * 3 * NN + n;
    float x = base[0], y = base[NN], z = base[2 * NN];
    float w = x * x + y * y + z * z;
    g_P4[p] = make_float4(x, y, z, w);
    g_Sx[p] = x; g_Sy[p] = y; g_Sz[p] = z; g_Sq[p] = w;
}

// ---------------- k1: KNN, 4 warps split candidate range ------------------------
#define NWARP 4
#define RANGE 2048
#define TSH 128
#define BS  13      // odd -> no worse than natural 2-phase 64b smem access
#define VST 20      // top16 list stride (ints); 80B -> 16B-aligned LDS.128
__global__ void __launch_bounds__(128) k1() {
    __shared__ __align__(16) float sX[NWARP][TSH];
    __shared__ __align__(16) float sY[NWARP][TSH];
    __shared__ __align__(16) float sZ[NWARP][TSH];
    __shared__ __align__(16) float sWW[NWARP][TSH];
    __shared__ __align__(16) unsigned sVal[NWARP * 32 * VST];
    __shared__ int      sIdx[NWARP * 32 * VST];
    __shared__ __align__(8) float2 sBuf[NWARP * 32 * BS];

    int lane = threadIdx.x & 31;
    int wid  = threadIdx.x >> 5;
    int blk  = blockIdx.x;                // 1024 blocks
    int b    = blk >> 8;                  // 256 blocks per batch
    int n    = ((blk & 255) << 5) + lane;
    int p    = b * NN + n;

    float4 q = g_P4[p];
    float qw = q.w;
    u64 m2x = pk2(-2.f * q.x), m2y = pk2(-2.f * q.y), m2z = pk2(-2.f * q.z);

    int vb = (wid * 32 + lane) * VST;
    int bbuf = (wid * 32 + lane) * BS;
#pragma unroll
    for (int s = 0; s < 16; s++) {
        sVal[vb + s] = 0x7F7FFFF0u | (unsigned)s;
        sIdx[vb + s] = 0;
    }
    unsigned worstP = 0x7F7FFFFFu;
    float thr = __uint_as_float(0x7F7FFFF0u) - qw;   // t-domain threshold
    int cnt = 0;

    int cbase = wid * RANGE;
    for (int t0 = 0; t0 < RANGE; t0 += TSH) {
        __syncwarp();
        const float* bx = g_Sx + b * NN + cbase + t0;
        const float* by = g_Sy + b * NN + cbase + t0;
        const float* bz = g_Sz + b * NN + cbase + t0;
        const float* bw = g_Sq + b * NN + cbase + t0;
        {
            int o = lane * 4;
            *(float4*)(sX[wid]  + o) = *(const float4*)(bx + o);
            *(float4*)(sY[wid]  + o) = *(const float4*)(by + o);
            *(float4*)(sZ[wid]  + o) = *(const float4*)(bz + o);
            *(float4*)(sWW[wid] + o) = *(const float4*)(bw + o);
        }
        __syncwarp();

        for (int j = 0; j < TSH; j += 8) {
            ulonglong2 X0 = *(const ulonglong2*)(sX[wid]  + j);
            ulonglong2 Y0 = *(const ulonglong2*)(sY[wid]  + j);
            ulonglong2 Z0 = *(const ulonglong2*)(sZ[wid]  + j);
            ulonglong2 W0 = *(const ulonglong2*)(sWW[wid] + j);
            ulonglong2 X1 = *(const ulonglong2*)(sX[wid]  + j + 4);
            ulonglong2 Y1 = *(const ulonglong2*)(sY[wid]  + j + 4);
            ulonglong2 Z1 = *(const ulonglong2*)(sZ[wid]  + j + 4);
            ulonglong2 W1 = *(const ulonglong2*)(sWW[wid] + j + 4);
            u64 t0a = fma2(Z0.x, m2z, fma2(Y0.x, m2y, fma2(X0.x, m2x, W0.x)));
            u64 t0b = fma2(Z0.y, m2z, fma2(Y0.y, m2y, fma2(X0.y, m2x, W0.y)));
            u64 t1a = fma2(Z1.x, m2z, fma2(Y1.x, m2y, fma2(X1.x, m2x, W1.x)));
            u64 t1b = fma2(Z1.y, m2z, fma2(Y1.y, m2y, fma2(X1.y, m2x, W1.y)));
            float2 f01 = unpk(t0a), f23 = unpk(t0b), f45 = unpk(t1a), f67 = unpk(t1b);
            float m01 = fminf(f01.x, f01.y), m23 = fminf(f23.x, f23.y);
            float m45 = fminf(f45.x, f45.y), m67 = fminf(f67.x, f67.y);
            float mm = fminf(fminf(m01, m23), fminf(m45, m67));
            if (mm < thr) {
                float tt[8] = {f01.x, f01.y, f23.x, f23.y, f45.x, f45.y, f67.x, f67.y};
                int ib = cbase + t0 + j;
#pragma unroll
                for (int uu = 0; uu < 8; uu++) {
                    // unconditional store is safe: cnt only advances on pass
                    sBuf[bbuf + cnt] = make_float2(tt[uu], __int_as_float(ib + uu));
                    cnt += (tt[uu] < thr) ? 1 : 0;
                }
            }
            if (__any_sync(0xffffffffu, cnt >= BS - 7)) {
#pragma unroll 1
                for (int e = 0; e < cnt; e++) {
                    float2 pr = sBuf[bbuf + e];
                    if (pr.x < thr) {
                        float ts = fmaxf(pr.x + qw, 0.f);
                        unsigned slot = worstP & 0xFu;
                        sVal[vb + slot] = (__float_as_uint(ts) & 0xFFFFFFF0u) | slot;
                        sIdx[vb + slot] = __float_as_int(pr.y);
                        unsigned mmax = 0u;
                        const uint4* vp = (const uint4*)(sVal + vb);
#pragma unroll
                        for (int s4 = 0; s4 < 4; s4++) {
                            uint4 v = vp[s4];
                            mmax = max(mmax, max(max(v.x, v.y), max(v.z, v.w)));
                        }
                        worstP = mmax;
                        thr = __uint_as_float(mmax & 0xFFFFFFF0u) - qw;
                    }
                }
                cnt = 0;
            }
        }
    }

    // final flush of buffered candidates
#pragma unroll 1
    for (int e = 0; e < cnt; e++) {
        float2 pr = sBuf[bbuf + e];
        if (pr.x < thr) {
            float ts = fmaxf(pr.x + qw, 0.f);
            unsigned slot = worstP & 0xFu;
            sVal[vb + slot] = (__float_as_uint(ts) & 0xFFFFFFF0u) | slot;
            sIdx[vb + slot] = __float_as_int(pr.y);
            unsigned mmax = 0u;
            const uint4* vp = (const uint4*)(sVal + vb);
#pragma unroll
            for (int s4 = 0; s4 < 4; s4++) {
                uint4 v = vp[s4];
                mmax = max(mmax, max(max(v.x, v.y), max(v.z, v.w)));
            }
            worstP = mmax;
            thr = __uint_as_float(mmax & 0xFFFFFFF0u) - qw;
        }
    }

    // tree merge: round 1: w0<-w2, w1<-w3 ; round 2: w0<-w1
    float thrts = __uint_as_float(worstP & 0xFFFFFFF0u);
    __syncthreads();
    if (wid < 2) {
        int pb = ((wid + 2) * 32 + lane) * VST;
#pragma unroll
        for (int s = 0; s < 16; s++) {
            unsigned pv = sVal[pb + s];
            float pvts = __uint_as_float(pv & 0xFFFFFFF0u);
            if (pvts < thrts) {
                unsigned slot = worstP & 0xFu;
                sVal[vb + slot] = (pv & 0xFFFFFFF0u) | slot;
                sIdx[vb + slot] = sIdx[pb + s];
                unsigned mmax = 0u;
                const uint4* vp = (const uint4*)(sVal + vb);
#pragma unroll
                for (int s4 = 0; s4 < 4; s4++) {
                    uint4 v = vp[s4];
                    mmax = max(mmax, max(max(v.x, v.y), max(v.z, v.w)));
                }
                worstP = mmax;
                thrts = __uint_as_float(mmax & 0xFFFFFFF0u);
            }
        }
    }
    __syncthreads();
    if (wid == 0) {
        int pb = (32 + lane) * VST;
#pragma unroll
        for (int s = 0; s < 16; s++) {
            unsigned pv = sVal[pb + s];
            float pvts = __uint_as_float(pv & 0xFFFFFFF0u);
            if (pvts < thrts) {
                unsigned slot = worstP & 0xFu;
                sVal[vb + slot] = (pv & 0xFFFFFFF0u) | slot;
                sIdx[vb + slot] = sIdx[pb + s];
                unsigned mmax = 0u;
                const uint4* vp = (const uint4*)(sVal + vb);
#pragma unroll
                for (int s4 = 0; s4 < 4; s4++) {
                    uint4 v = vp[s4];
                    mmax = max(mmax, max(max(v.x, v.y), max(v.z, v.w)));
                }
                worstP = mmax;
                thrts = __uint_as_float(mmax & 0xFFFFFFF0u);
            }
        }
#pragma unroll
        for (int s = 0; s < 16; s++) g_NB[p * KK + s] = sIdx[vb + s];
    }
}

// ---------------- k2: per-point transforms, 3 passes of 64 outs -----------------
__global__ void __launch_bounds__(256) k2(const float* __restrict__ feats,
                   const float* __restrict__ W1, const float* __restrict__ b1,
                   const float* __restrict__ Wv, const float* __restrict__ bv) {
    __shared__ float sW[64][64];
    __shared__ float sF[64][64];
    int tid = threadIdx.x;
    int blk = blockIdx.x;
    int b   = blk >> 7;
    int n0  = (blk & 127) << 6;

    for (int e = tid; e < 1024; e += 256) {
        int c = e >> 4, v4 = e & 15;
        ((float4*)sF[c])[v4] =
            ((const float4*)(feats + (size_t)b * CC * NN + (size_t)c * NN + n0))[v4];
    }

    int og = tid & 15, ng = tid >> 4;

    for (int pp = 0; pp < 3; pp++) {
        __syncthreads();
        for (int e = tid; e < 4096; e += 256) {
            int ol = e & 63, c = e >> 6;
            float w;
            if (pp == 0)      w = W1[ol * 131 + c];
            else if (pp == 1) w = W1[ol * 131 + 64 + c];
            else              w = Wv[ol * 67 + c];
            sW[c][ol] = w;
        }
        __syncthreads();

        float4 a0 = make_float4(0.f,0.f,0.f,0.f), a1 = a0, a2 = a0, a3 = a0;
        for (int c = 0; c < 64; c++) {
            float4 w4 = *(const float4*)&sW[c][og * 4];
            float4 f4 = *(const float4*)&sF[c][ng * 4];
            a0.x = fmaf(w4.x, f4.x, a0.x); a0.y = fmaf(w4.y, f4.x, a0.y);
            a0.z = fmaf(w4.z, f4.x, a0.z); a0.w = fmaf(w4.w, f4.x, a0.w);
            a1.x = fmaf(w4.x, f4.y, a1.x); a1.y = fmaf(w4.y, f4.y, a1.y);
            a1.z = fmaf(w4.z, f4.y, a1.z); a1.w = fmaf(w4.w, f4.y, a1.w);
            a2.x = fmaf(w4.x, f4.z, a2.x); a2.y = fmaf(w4.y, f4.z, a2.y);
            a2.z = fmaf(w4.z, f4.z, a2.z); a2.w = fmaf(w4.w, f4.z, a2.w);
            a3.x = fmaf(w4.x, f4.w, a3.x); a3.y = fmaf(w4.y, f4.w, a3.y);
            a3.z = fmaf(w4.z, f4.w, a3.z); a3.w = fmaf(w4.w, f4.w, a3.w);
        }

        float4 bb = make_float4(0.f, 0.f, 0.f, 0.f);
        if (pp == 0) bb = *(const float4*)(b1 + og * 4);
        if (pp == 2) bb = *(const float4*)(bv + og * 4);
        int obase = pp * 64 + og * 4;
        float4 r;
        size_t pbase = (size_t)(b * NN + n0 + ng * 4);
        r = make_float4(a0.x+bb.x, a0.y+bb.y, a0.z+bb.z, a0.w+bb.w);
        *(float4*)(g_PT + (pbase + 0) * 192 + obase) = r;
        r = make_float4(a1.x+bb.x, a1.y+bb.y, a1.z+bb.z, a1.w+bb.w);
        *(float4*)(g_PT + (pbase + 1) * 192 + obase) = r;
        r = make_float4(a2.x+bb.x, a2.y+bb.y, a2.z+bb.z, a2.w+bb.w);
        *(float4*)(g_PT + (pbase + 2) * 192 + obase) = r;
        r = make_float4(a3.x+bb.x, a3.y+bb.y, a3.z+bb.z, a3.w+bb.w);
        *(float4*)(g_PT + (pbase + 3) * 192 + obase) = r;
    }
}

// ---------------- k3: BN stats for h and v (f32x2, channel pairs) ---------------
__global__ void __launch_bounds__(256) k3(const float* __restrict__ W1,
                                          const float* __restrict__ Wv) {
    __shared__ float sstat[256];
    int tid = threadIdx.x, lane = tid & 31, wid = tid >> 5;
    for (int e = tid; e < 256; e += 256) sstat[e] = 0.f;
    __syncthreads();

    int cc = lane * 2;   // channels cc, cc+1
    u64 w1x0 = pkab(W1[cc * 131 + 128], W1[(cc + 1) * 131 + 128]);
    u64 w1x1 = pkab(W1[cc * 131 + 129], W1[(cc + 1) * 131 + 129]);
    u64 w1x2 = pkab(W1[cc * 131 + 130], W1[(cc + 1) * 131 + 130]);
    u64 wvx0 = pkab(Wv[cc * 67 + 64],  Wv[(cc + 1) * 67 + 64]);
    u64 wvx1 = pkab(Wv[cc * 67 + 65],  Wv[(cc + 1) * 67 + 65]);
    u64 wvx2 = pkab(Wv[cc * 67 + 66],  Wv[(cc + 1) * 67 + 66]);

    u64 sh = 0, shq = 0, sv = 0, svq = 0;
    int gw = blockIdx.x * 8 + wid, nw = gridDim.x * 8;
    for (int p = gw; p < NPTS; p += nw) {
        int b = p >> 13;
        float4 q = g_P4[p];
        const int4* nb = (const int4*)(g_NB + p * KK);
        int4 iA = nb[0], iB = nb[1], iC = nb[2], iD = nb[3];
        int mi[16] = {iA.x, iA.y, iA.z, iA.w, iB.x, iB.y, iB.z, iB.w,
                      iC.x, iC.y, iC.z, iC.w, iD.x, iD.y, iD.z, iD.w};
        const float* ptp = g_PT + (size_t)p * 192;
        u64 hcp = *(const u64*)(ptp + cc);
#pragma unroll
        for (int k = 0; k < KK; k++) {
            int m = mi[k];
            float4 pm = g_P4[b * NN + m];
            u64 rxp = pk2(pm.x - q.x), ryp = pk2(pm.y - q.y), rzp = pk2(pm.z - q.z);
            const float* ptm = g_PT + (size_t)(b * NN + m) * 192;
            u64 hnp = *(const u64*)(ptm + 64 + cc);
            u64 vnp = *(const u64*)(ptm + 128 + cc);
            u64 h = fma2(rzp, w1x2, fma2(ryp, w1x1, fma2(rxp, w1x0, add2(hcp, hnp))));
            u64 v = fma2(rzp, wvx2, fma2(ryp, wvx1, fma2(rxp, wvx0, vnp)));
            sh = add2(sh, h); shq = fma2(h, h, shq);
            sv = add2(sv, v); svq = fma2(v, v, svq);
        }
    }
    float2 fsh = unpk(sh), fshq = unpk(shq), fsv = unpk(sv), fsvq = unpk(svq);
    atomicAdd(&sstat[cc], fsh.x);       atomicAdd(&sstat[cc + 1], fsh.y);
    atomicAdd(&sstat[64 + cc], fshq.x); atomicAdd(&sstat[64 + cc + 1], fshq.y);
    atomicAdd(&sstat[128 + cc], fsv.x); atomicAdd(&sstat[128 + cc + 1], fsv.y);
    atomicAdd(&sstat[192 + cc], fsvq.x);atomicAdd(&sstat[192 + cc + 1], fsvq.y);
    __syncthreads();
    for (int e = tid; e < 256; e += 256) atomicAdd(&g_stats[e], sstat[e]);
}

// ---------------- k5: attention + value + out-conv (BN coefs computed inline) ---
__global__ void __launch_bounds__(256) k5(const float* __restrict__ W1,
                   const float* __restrict__ Wv,
                   const float* __restrict__ W2, const float* __restrict__ b2,
                   const float* __restrict__ Wo, const float* __restrict__ bo,
                   const float* __restrict__ g1, const float* __restrict__ be1,
                   const float* __restrict__ gv, const float* __restrict__ bev) {
    __shared__ float sWo[64][65];
    __shared__ float sOut[8][64];
    __shared__ float sstat[128];
    int tid = threadIdx.x, lane = tid & 31, wid = tid >> 5;

    for (int e = tid; e < 64 * 64; e += 256) {
        int j = e >> 6, c = e & 63;
        sWo[j][c] = Wo[c * 64 + j];
    }
    for (int e = tid; e < 128; e += 256) sstat[e] = 0.f;

    int cc = lane * 2;
    u64 w1x0 = pkab(W1[cc * 131 + 128], W1[(cc + 1) * 131 + 128]);
    u64 w1x1 = pkab(W1[cc * 131 + 129], W1[(cc + 1) * 131 + 129]);
    u64 w1x2 = pkab(W1[cc * 131 + 130], W1[(cc + 1) * 131 + 130]);
    u64 wvx0 = pkab(Wv[cc * 67 + 64],  Wv[(cc + 1) * 67 + 64]);
    u64 wvx1 = pkab(Wv[cc * 67 + 65],  Wv[(cc + 1) * 67 + 65]);
    u64 wvx2 = pkab(Wv[cc * 67 + 66],  Wv[(cc + 1) * 67 + 66]);

    // BN coefficients computed from finalized g_stats (k4 folded in)
    float cntk = (float)((size_t)NPTS * KK);
    float mh1 = g_stats[cc] / cntk,     mh2 = g_stats[cc + 1] / cntk;
    float vh1 = g_stats[64 + cc] / cntk - mh1 * mh1;
    float vh2 = g_stats[64 + cc + 1] / cntk - mh2 * mh2;
    float a1a = g1[cc] * rsqrtf(vh1 + 1e-5f), a1b = g1[cc + 1] * rsqrtf(vh2 + 1e-5f);
    float d1a = be1[cc] - a1a * mh1,          d1b = be1[cc + 1] - a1b * mh2;
    float mv1 = g_stats[128 + cc] / cntk,     mv2 = g_stats[128 + cc + 1] / cntk;
    float vv1s = g_stats[192 + cc] / cntk - mv1 * mv1;
    float vv2s = g_stats[192 + cc + 1] / cntk - mv2 * mv2;
    float ava = gv[cc] * rsqrtf(vv1s + 1e-5f), avb = gv[cc + 1] * rsqrtf(vv2s + 1e-5f);
    float dva = bev[cc] - ava * mv1,           dvb = bev[cc + 1] - avb * mv2;

    float w2a = W2[cc], w2b = W2[cc + 1];
    float b2v = b2[0];
    float boa = bo[cc], bob = bo[cc + 1];
    __syncthreads();

    float so1 = 0.f, so1q = 0.f, so2 = 0.f, so2q = 0.f;
    int gw = blockIdx.x * 8 + wid, nw = gridDim.x * 8;

    for (int p = gw; p < NPTS; p += nw) {
        int b = p >> 13;
        float4 q = g_P4[p];
        const int4* nb = (const int4*)(g_NB + p * KK);
        int4 iA = nb[0], iB = nb[1], iC = nb[2], iD = nb[3];
        int mi[16] = {iA.x, iA.y, iA.z, iA.w, iB.x, iB.y, iB.z, iB.w,
                      iC.x, iC.y, iC.z, iC.w, iD.x, iD.y, iD.z, iD.w};
        const float* ptp = g_PT + (size_t)p * 192;
        u64 hcp = *(const u64*)(ptp + cc);

        float logits[KK], vv1[KK], vv2[KK];
#pragma unroll
        for (int k = 0; k < KK; k++) {
            int m = mi[k];
            float4 pm = g_P4[b * NN + m];
            u64 rxp = pk2(pm.x - q.x), ryp = pk2(pm.y - q.y), rzp = pk2(pm.z - q.z);
            const float* ptm = g_PT + (size_t)(b * NN + m) * 192;
            u64 hnp = *(const u64*)(ptm + 64 + cc);
            u64 vnp = *(const u64*)(ptm + 128 + cc);
            u64 h = fma2(rzp, w1x2, fma2(ryp, w1x1, fma2(rxp, w1x0, add2(hcp, hnp))));
            u64 v = fma2(rzp, wvx2, fma2(ryp, wvx1, fma2(rxp, wvx0, vnp)));
            float2 hf = unpk(h), vf = unpk(v);
            float hb1 = fmaxf(a1a * hf.x + d1a, 0.f);
            float hb2 = fmaxf(a1b * hf.y + d1b, 0.f);
            vv1[k] = fmaxf(ava * vf.x + dva, 0.f);
            vv2[k] = fmaxf(avb * vf.y + dvb, 0.f);
            float t = hb1 * w2a + hb2 * w2b;
#pragma unroll
            for (int off = 16; off > 0; off >>= 1) t += __shfl_xor_sync(0xffffffffu, t, off);
            logits[k] = t + b2v;
        }
        float mx = logits[0];
#pragma unroll
        for (int k = 1; k < KK; k++) mx = fmaxf(mx, logits[k]);
        float ex[KK], se = 0.f;
#pragma unroll
        for (int k = 0; k < KK; k++) { ex[k] = __expf(logits[k] - mx); se += ex[k]; }
        float inv = 1.0f / se;
        float out1 = 0.f, out2 = 0.f;
#pragma unroll
        for (int k = 0; k < KK; k++) {
            float w = ex[k] * inv;
            out1 += w * vv1[k];
            out2 += w * vv2[k];
        }
        __syncwarp();
        sOut[wid][cc] = out1; sOut[wid][cc + 1] = out2;
        __syncwarp();
        float oo1 = boa, oo2 = bob;
#pragma unroll 8
        for (int j = 0; j < 64; j++) {
            float oj = sOut[wid][j];
            oo1 = fmaf(sWo[j][cc], oj, oo1);
            oo2 = fmaf(sWo[j][cc + 1], oj, oo2);
        }
        g_Opre[(size_t)p * 64 + cc] = oo1;
        g_Opre[(size_t)p * 64 + cc + 1] = oo2;
        so1 += oo1; so1q += oo1 * oo1;
        so2 += oo2; so2q += oo2 * oo2;
    }
    atomicAdd(&sstat[cc], so1);     atomicAdd(&sstat[64 + cc], so1q);
    atomicAdd(&sstat[cc + 1], so2); atomicAdd(&sstat[64 + cc + 1], so2q);
    __syncthreads();
    for (int e = tid; e < 128; e += 256) atomicAdd(&g_ostats[e], sstat[e]);
}

// ---------------- k7: BN + relu + residual + transpose (k6 folded in) -----------
__global__ void k7(const float* __restrict__ feats, float* __restrict__ out,
                   const float* __restrict__ go, const float* __restrict__ beo) {
    __shared__ float tile[32][65];
    __shared__ float sco[128];
    int blk = blockIdx.x;
    int b = blk >> 8;
    int n0 = (blk & 255) << 5;
    int tid = threadIdx.x;
    if (tid < 64) {
        float cntp = (float)NPTS;
        float m = g_ostats[tid] / cntp;
        float v = g_ostats[64 + tid] / cntp - m * m;
        float a = go[tid] * rsqrtf(v + 1e-5f);
        sco[tid] = a; sco[64 + tid] = beo[tid] - a * m;
    }
    for (int e = tid; e < 32 * 64; e += 256) {
        int pp = e >> 6, c = e & 63;
        tile[pp][c] = g_Opre[(size_t)(b * NN + n0 + pp) * 64 + c];
    }
    __syncthreads();
    for (int e = tid; e < 64 * 32; e += 256) {
        int c = e >> 5, j = e & 31;
        float val = sco[c] * tile[j][c] + sco[64 + c];
        val = fmaxf(val, 0.f) + feats[(size_t)b * CC * NN + (size_t)c * NN + n0 + j];
        out[(size_t)b * CC * NN + (size_t)c * NN + n0 + j] = val;
    }
}

// ---------------- launch --------------------------------------------------------
extern "C" void kernel_launch(void* const* d_in, const int* in_sizes, int n_in,
                              void* d_out, int out_size) {
    const float* xyz   = (const float*)d_in[0];
    const float* feats = (const float*)d_in[1];
    const float* W1    = (const float*)d_in[2];
    const float* b1    = (const float*)d_in[3];
    const float* g1    = (const float*)d_in[4];
    const float* be1   = (const float*)d_in[5];
    const float* W2    = (const float*)d_in[6];
    const float* b2    = (const float*)d_in[7];
    const float* Wv    = (const float*)d_in[8];
    const float* bv    = (const float*)d_in[9];
    const float* gv    = (const float*)d_in[10];
    const float* bev   = (const float*)d_in[11];
    const float* Wo    = (const float*)d_in[12];
    const float* bo    = (const float*)d_in[13];
    const float* go    = (const float*)d_in[14];
    const float* beo   = (const float*)d_in[15];
    float* out = (float*)d_out;

    // lazily-created side stream + events (no device memory involved)
    static cudaStream_t s2 = nullptr;
    static cudaEvent_t evFork = nullptr, evJoin = nullptr;
    if (s2 == nullptr) {
        cudaStreamCreateWithFlags(&s2, cudaStreamNonBlocking);
        cudaEventCreateWithFlags(&evFork, cudaEventDisableTiming);
        cudaEventCreateWithFlags(&evJoin, cudaEventDisableTiming);
    }

    // fork: k2 (depends only on feats) runs concurrently with k0+k1
    cudaEventRecord(evFork, 0);
    cudaStreamWaitEvent(s2, evFork, 0);
    k2<<<NPTS / 64, 256, 0, s2>>>(feats, W1, b1, Wv, bv);
    cudaEventRecord(evJoin, s2);

    k0<<<NPTS / 256, 256>>>(xyz);
    k1<<<NPTS / 32, 128>>>();

    // join: k3 needs both k1 (g_NB) and k2 (g_PT)
    cudaStreamWaitEvent(0, evJoin, 0);
    k3<<<1184, 256>>>(W1, Wv);
    k5<<<1184, 256>>>(W1, Wv, W2, b2, Wo, bo, g1, be1, gv, bev);
    k7<<<NPTS / 32, 256>>>(feats, out, go, beo);
}